// round 7
// baseline (speedup 1.0000x reference)
#include <cuda_runtime.h>
#include <cuda_bf16.h>
#include <math.h>

#define Bb 64
#define Hh 256
#define Ll 1024
#define Nn 64
#define BHL (Bb*Hh*Ll)

// ---------------- scratch (device globals; no allocs allowed) ----------------
__device__ float g_x1[BHL];        // post-AdaLN x (residual source)
__device__ float g_z[BHL];         // z (pre-norm out); reused as packed gate g after conv
__device__ unsigned g_yg[BHL];     // gelu(conv out + D*z), packed (bf16 hi | bf16 lo<<16)
__device__ float g_ss[Bb*2048];    // scale(0:1024) / shift(1024:2048) per batch
__device__ float g_semb[Bb*1024];  // silu(sin/cos emb)
__device__ float g_ktime[Hh*2048]; // time-domain bidirectional kernel
__device__ float g_khr[Hh*2048];   // full complex spectrum of k (re)
__device__ float g_khi[Hh*2048];   // (im)
__device__ float g_part[8*Bb*2048];// ada split-K partials
__device__ float2 g_tw[1024];      // FFT twiddles exp(-i*pi*k/1024)
__device__ __nv_bfloat16 g_whi[3*Hh*Hh]; // pre-split weights (out_w, lin1_w, lin2_w)
__device__ __nv_bfloat16 g_wlo[3*Hh*Hh];

// ---------------- helpers ----------------
__device__ __forceinline__ float geluf(float x) {
    return 0.5f * x * (1.0f + erff(x * 0.70710678118654752440f));
}
__device__ __forceinline__ float gatef(float x) {
    float t  = __expf(-fmaxf(x, -30.0f));
    float t2 = t * t;
    return ((1.0f - t2) / (1.0f + t2)) * (1.0f / (1.0f + t));
}
__device__ __forceinline__ unsigned pckbf(__nv_bfloat16 a, __nv_bfloat16 b) {
    __nv_bfloat162 t; t.x = a; t.y = b;
    return *reinterpret_cast<unsigned*>(&t);
}
// pack fp32 -> (bf16 hi | bf16 lo<<16)
__device__ __forceinline__ unsigned packhl(float v) {
    __nv_bfloat16 h = __float2bfloat16(v);
    __nv_bfloat16 l = __float2bfloat16(v - __bfloat162float(h));
    unsigned short hb = *reinterpret_cast<unsigned short*>(&h);
    unsigned short lb = *reinterpret_cast<unsigned short*>(&l);
    return (unsigned)hb | ((unsigned)lb << 16);
}

// ---------------- weight pre-split ----------------
__global__ void k_wprep(const float* __restrict__ w0,
                        const float* __restrict__ w1,
                        const float* __restrict__ w2) {
    int i = blockIdx.x * 256 + threadIdx.x;      // 0 .. 3*65536-1
    int m = i >> 16, r = i & 65535;
    float v = (m == 0) ? w0[r] : (m == 1) ? w1[r] : w2[r];
    __nv_bfloat16 h = __float2bfloat16(v);
    g_whi[i] = h;
    g_wlo[i] = __float2bfloat16(v - __bfloat162float(h));
}

// ---------------- twiddle table ----------------
__global__ void k_twfill() {
    int i = blockIdx.x * 256 + threadIdx.x;
    float ang = -3.14159265358979323846f * (float)i * (1.0f / 1024.0f);
    float sn, cs; sincosf(ang, &sn, &cs);
    g_tw[i] = make_float2(cs, sn);
}

// ---------------- sinusoidal embedding + silu ----------------
__global__ void __launch_bounds__(256) k_semb(const int* __restrict__ t) {
    int b = blockIdx.x;
    float tf = (float)t[b];
    const float cfr = (float)(-9.210340371976184 / 511.0);
    #pragma unroll
    for (int r = 0; r < 4; r++) {
        int i = threadIdx.x + (r << 8);
        float v;
        if (i < 512) v = sinf(tf * expf((float)i * cfr));
        else         v = cosf(tf * expf((float)(i - 512) * cfr));
        float sg = 1.0f / (1.0f + expf(-v));
        g_semb[b * 1024 + i] = v * sg;
    }
}

// ---------------- emb @ ada_w.T  (split-K partials) ----------------
__global__ void __launch_bounds__(256) k_ada_gemm(const float* __restrict__ W) {
    __shared__ float Ws[64][32];
    __shared__ float Eb[64][64];
    int o0 = blockIdx.x * 32;
    int kc = blockIdx.y;
    int tid = threadIdx.x;
    int o  = tid & 31;
    int bg = tid >> 5;
    float acc[8];
    #pragma unroll
    for (int j = 0; j < 8; j++) acc[j] = 0.f;

    for (int kk = kc * 128; kk < kc * 128 + 128; kk += 64) {
        {
            int oo = tid >> 3;
            int kq = tid & 7;
            const float* src = &W[(size_t)(o0 + oo) * 1024 + kk + kq * 8];
            float4 a = *(const float4*)(src);
            float4 c = *(const float4*)(src + 4);
            int kb = kq * 8;
            Ws[kb+0][oo] = a.x; Ws[kb+1][oo] = a.y; Ws[kb+2][oo] = a.z; Ws[kb+3][oo] = a.w;
            Ws[kb+4][oo] = c.x; Ws[kb+5][oo] = c.y; Ws[kb+6][oo] = c.z; Ws[kb+7][oo] = c.w;
        }
        #pragma unroll
        for (int r = 0; r < 16; r++) {
            int e = tid + (r << 8);
            int bq = e >> 6, k = e & 63;
            Eb[bq][k] = g_semb[bq * 1024 + kk + k];
        }
        __syncthreads();
        #pragma unroll 8
        for (int k = 0; k < 64; k++) {
            float wv = Ws[k][o];
            #pragma unroll
            for (int j = 0; j < 8; j++)
                acc[j] += Eb[bg * 8 + j][k] * wv;
        }
        __syncthreads();
    }
    #pragma unroll
    for (int j = 0; j < 8; j++)
        g_part[((size_t)kc * 64 + bg * 8 + j) * 2048 + o0 + o] = acc[j];
}

__global__ void __launch_bounds__(256) k_ada_reduce(const float* __restrict__ bias) {
    int idx = blockIdx.x * 256 + threadIdx.x;
    int b = idx >> 11, o = idx & 2047;
    float s = bias[o];
    #pragma unroll
    for (int kc = 0; kc < 8; kc++)
        s += g_part[((size_t)kc * 64 + b) * 2048 + o];
    g_ss[b * 2048 + o] = s;
}

// ---------------- AdaLayerNorm over L ----------------
__global__ void __launch_bounds__(256) k_adaln(const float* __restrict__ x) {
    int bh = blockIdx.x;
    int b = bh >> 8;
    int tid = threadIdx.x;
    const float4* xr = (const float4*)(x + (size_t)bh * 1024);
    float4 v = xr[tid];
    float s = v.x + v.y + v.z + v.w;
    float q = v.x*v.x + v.y*v.y + v.z*v.z + v.w*v.w;
    #pragma unroll
    for (int o = 16; o; o >>= 1) {
        s += __shfl_down_sync(0xffffffffu, s, o);
        q += __shfl_down_sync(0xffffffffu, q, o);
    }
    __shared__ float as_[8], aq_[8];
    if ((tid & 31) == 0) { as_[tid >> 5] = s; aq_[tid >> 5] = q; }
    __syncthreads();
    float S = 0.f, Q = 0.f;
    #pragma unroll
    for (int i = 0; i < 8; i++) { S += as_[i]; Q += aq_[i]; }
    float m  = S * (1.0f / 1024.0f);
    float va = Q * (1.0f / 1024.0f) - m * m;
    float rs = rsqrtf(va + 1e-5f);
    const float4* sc = (const float4*)(g_ss + b * 2048);
    const float4* sh = (const float4*)(g_ss + b * 2048 + 1024);
    float4 a = sc[tid], d = sh[tid];
    float4 o4;
    o4.x = (v.x - m) * rs * (1.0f + a.x) + d.x;
    o4.y = (v.y - m) * rs * (1.0f + a.y) + d.y;
    o4.z = (v.z - m) * rs * (1.0f + a.z) + d.z;
    o4.w = (v.w - m) * rs * (1.0f + a.w) + d.w;
    ((float4*)(g_x1 + (size_t)bh * 1024))[tid] = o4;
}

// ---------------- channel LayerNorm over H ----------------
__global__ void __launch_bounds__(256) k_chanln(const float* __restrict__ nw,
                                                const float* __restrict__ nb) {
    int b = blockIdx.x;
    int l0 = blockIdx.y * 32;
    int tid = threadIdx.x;
    int lx = tid & 31, hp = tid >> 5;
    float v[32];
    float s = 0.f, q = 0.f;
    const float* base = g_x1 + ((size_t)b * Hh) * Ll + l0 + lx;
    #pragma unroll 8
    for (int k = 0; k < 32; k++) {
        float xv = base[(size_t)(hp * 32 + k) * Ll];
        v[k] = xv; s += xv; q += xv * xv;
    }
    __shared__ float ps[8][32], pq[8][32];
    __shared__ float mean_[32], rstd_[32];
    ps[hp][lx] = s; pq[hp][lx] = q;
    __syncthreads();
    if (tid < 32) {
        float S = 0.f, Q = 0.f;
        #pragma unroll
        for (int p = 0; p < 8; p++) { S += ps[p][tid]; Q += pq[p][tid]; }
        float m  = S * (1.0f / 256.0f);
        float va = Q * (1.0f / 256.0f) - m * m;
        mean_[tid] = m; rstd_[tid] = rsqrtf(va + 1e-5f);
    }
    __syncthreads();
    float m = mean_[lx], r = rstd_[lx];
    float* zb = g_z + ((size_t)b * Hh) * Ll + l0 + lx;
    #pragma unroll 8
    for (int k = 0; k < 32; k++) {
        int h = hp * 32 + k;
        zb[(size_t)h * Ll] = (v[k] - m) * r * nw[h] + nb[h];
    }
}

// ---------------- SSM kernel ----------------
__global__ void __launch_bounds__(256) k_ssm(const float* __restrict__ log_dt,
                                             const float* __restrict__ A_re,
                                             const float* __restrict__ A_im,
                                             const float* __restrict__ C_re,
                                             const float* __restrict__ C_im) {
    __shared__ float pre[6][64];
    int h = blockIdx.x, tid = threadIdx.x;
    if (tid < 64) {
        int n = tid;
        float dt  = expf(log_dt[h]);
        float are = -expf(A_re[h * 64 + n]);
        float aim = A_im[h * 64 + n];
        float dre = dt * are, dim = dt * aim;
        float er = expf(dre);
        float sn, cs; sincosf(dim, &sn, &cs);
        float dAr = er * cs, dAi = er * sn;
        float numr = dAr - 1.0f, numi = dAi;
        float den = are * are + aim * aim;
        float fr = (numr * are + numi * aim) / den;
        float fi = (numi * are - numr * aim) / den;
        float c0re = C_re[h * 64 + n],             c0im = C_im[h * 64 + n];
        float c1re = C_re[Hh * 64 + h * 64 + n],   c1im = C_im[Hh * 64 + h * 64 + n];
        pre[0][n] = dre; pre[1][n] = dim;
        pre[2][n] = c0re * fr - c0im * fi; pre[3][n] = c0re * fi + c0im * fr;
        pre[4][n] = c1re * fr - c1im * fi; pre[5][n] = c1re * fi + c1im * fr;
    }
    __syncthreads();
    #pragma unroll
    for (int qq = 0; qq < 4; qq++) {
        int l = tid + (qq << 8);
        float lf = (float)l;
        float k0 = 0.f, k1 = 0.f;
        #pragma unroll 4
        for (int n = 0; n < 64; n++) {
            float pr = pre[0][n] * lf, pi = pre[1][n] * lf;
            float e = expf(pr);
            float sn, cs; sincosf(pi, &sn, &cs);
            float vr = e * cs, vi = e * sn;
            k0 += pre[2][n] * vr - pre[3][n] * vi;
            k1 += pre[4][n] * vr - pre[5][n] * vi;
        }
        g_ktime[h * 2048 + l]        = 2.0f * k0;
        g_ktime[h * 2048 + 2047 - l] = 2.0f * k1;
    }
}

// ---------------- radix-8 Stockham FFT, N=2048, 256 threads ----------------
__device__ __forceinline__ void fft2048_r8(float*& sr, float*& si, float*& dr, float*& di) {
    const float Cq = 0.70710678118654752440f;
    #pragma unroll
    for (int lm = 0; lm < 9; lm += 3) {
        const int m = 1 << lm;
        int i = threadIdx.x;
        int p = i >> lm;
        int r = i & (m - 1);
        float xr[8], xi[8];
        #pragma unroll
        for (int s = 0; s < 8; s++) { xr[s] = sr[i + (s << 8)]; xi[s] = si[i + (s << 8)]; }
        float pr_[4], pi_[4], qr[4], qi[4];
        #pragma unroll
        for (int s = 0; s < 4; s++) {
            pr_[s] = xr[s] + xr[s+4]; pi_[s] = xi[s] + xi[s+4];
            qr[s]  = xr[s] - xr[s+4]; qi[s]  = xi[s] - xi[s+4];
        }
        { float a=qr[1], b=qi[1]; qr[1] = Cq*(a+b); qi[1] = Cq*(b-a); }
        { float a=qr[2], b=qi[2]; qr[2] = b;        qi[2] = -a;       }
        { float a=qr[3], b=qi[3]; qr[3] = Cq*(b-a); qi[3] = -Cq*(a+b); }
        float Xr[8], Xi[8];
        {
            float r0r=pr_[0]+pr_[2], r0i=pi_[0]+pi_[2];
            float r1r=pr_[0]-pr_[2], r1i=pi_[0]-pi_[2];
            float r2r=pr_[1]+pr_[3], r2i=pi_[1]+pi_[3];
            float t3r=pr_[1]-pr_[3], t3i=pi_[1]-pi_[3];
            float r3r=t3i, r3i=-t3r;
            Xr[0]=r0r+r2r; Xi[0]=r0i+r2i;
            Xr[2]=r1r+r3r; Xi[2]=r1i+r3i;
            Xr[4]=r0r-r2r; Xi[4]=r0i-r2i;
            Xr[6]=r1r-r3r; Xi[6]=r1i-r3i;
        }
        {
            float r0r=qr[0]+qr[2], r0i=qi[0]+qi[2];
            float r1r=qr[0]-qr[2], r1i=qi[0]-qi[2];
            float r2r=qr[1]+qr[3], r2i=qi[1]+qi[3];
            float t3r=qr[1]-qr[3], t3i=qi[1]-qi[3];
            float r3r=t3i, r3i=-t3r;
            Xr[1]=r0r+r2r; Xi[1]=r0i+r2i;
            Xr[3]=r1r+r3r; Xi[3]=r1i+r3i;
            Xr[5]=r0r-r2r; Xi[5]=r0i-r2i;
            Xr[7]=r1r-r3r; Xi[7]=r1i-r3i;
        }
        float2 w = g_tw[m * p];
        float wjr = 1.f, wji = 0.f;
        int o = ((m * p) << 3) + r;
        dr[o] = Xr[0]; di[o] = Xi[0];
        #pragma unroll
        for (int j = 1; j < 8; j++) {
            float nr = wjr * w.x - wji * w.y;
            wji = wji * w.x + wjr * w.y;
            wjr = nr;
            dr[o + j * m] = Xr[j] * wjr - Xi[j] * wji;
            di[o + j * m] = Xi[j] * wjr + Xr[j] * wji;
        }
        __syncthreads();
        float* tp; tp=sr;sr=dr;dr=tp; tp=si;si=di;di=tp;
    }
    #pragma unroll
    for (int q = 0; q < 2; q++) {
        int r = threadIdx.x + (q << 8);
        float a0r=sr[r],      a0i=si[r];
        float a1r=sr[r+512],  a1i=si[r+512];
        float a2r=sr[r+1024], a2i=si[r+1024];
        float a3r=sr[r+1536], a3i=si[r+1536];
        float r0r=a0r+a2r, r0i=a0i+a2i;
        float r1r=a0r-a2r, r1i=a0i-a2i;
        float r2r=a1r+a3r, r2i=a1i+a3i;
        float t3r=a1r-a3r, t3i=a1i-a3i;
        float r3r=t3i, r3i=-t3r;
        dr[r]      = r0r+r2r; di[r]      = r0i+r2i;
        dr[r+512]  = r1r+r3r; di[r+512]  = r1i+r3i;
        dr[r+1024] = r0r-r2r; di[r+1024] = r0i-r2i;
        dr[r+1536] = r1r-r3r; di[r+1536] = r1i-r3i;
    }
    __syncthreads();
    float* tp; tp=sr;sr=dr;dr=tp; tp=si;si=di;di=tp;
}

// ---------------- FFT of kernel rows ----------------
__global__ void __launch_bounds__(256) k_kfft() {
    __shared__ float bAr[2048], bAi[2048], bBr[2048], bBi[2048];
    int tid = threadIdx.x;
    int h0 = blockIdx.x * 2, h1 = h0 + 1;
    #pragma unroll
    for (int qq = 0; qq < 8; qq++) {
        int idx = tid + (qq << 8);
        bAr[idx] = g_ktime[h0 * 2048 + idx];
        bAi[idx] = g_ktime[h1 * 2048 + idx];
    }
    __syncthreads();
    float *sr = bAr, *si = bAi, *dr = bBr, *di = bBi;
    fft2048_r8(sr, si, dr, di);
    #pragma unroll
    for (int qq = 0; qq < 8; qq++) {
        int f = tid + (qq << 8);
        int fr2 = (2048 - f) & 2047;
        float ur = sr[f],  ui = si[f];
        float vr = sr[fr2], vi = -si[fr2];
        g_khr[h0 * 2048 + f] = 0.5f * (ur + vr);
        g_khi[h0 * 2048 + f] = 0.5f * (ui + vi);
        g_khr[h1 * 2048 + f] = 0.5f * (ui - vi);
        g_khi[h1 * 2048 + f] = -0.5f * (ur - vr);
    }
}

// ---------------- main conv: epilogue +D*z, gelu, pack hi/lo bf16 ----------------
__global__ void __launch_bounds__(256) k_conv(const float* __restrict__ Dp) {
    __shared__ float bAr[2048], bAi[2048], bBr[2048], bBi[2048];
    int tid = threadIdx.x;
    int h  = blockIdx.x;
    int pb = blockIdx.y;
    const float* za = g_z + ((size_t)(2 * pb) * Hh + h) * Ll;
    const float* zb = za + (size_t)Hh * Ll;
    float ra[4], rb[4];
    #pragma unroll
    for (int qq = 0; qq < 4; qq++) {
        int idx = tid + (qq << 8);
        ra[qq] = za[idx]; rb[qq] = zb[idx];
        bAr[idx] = ra[qq]; bAi[idx] = rb[qq];
        bAr[idx + 1024] = 0.f; bAi[idx + 1024] = 0.f;
    }
    __syncthreads();
    float *sr = bAr, *si = bAi, *dr = bBr, *di = bBi;
    fft2048_r8(sr, si, dr, di);
    const float* khr = g_khr + h * 2048;
    const float* khi = g_khi + h * 2048;
    const float inv = 1.0f / 2048.0f;
    #pragma unroll
    for (int qq = 0; qq < 8; qq++) {
        int f = tid + (qq << 8);
        float kr = khr[f], ki = khi[f];
        float ar = sr[f], ai = si[f];
        float pr = ar * kr - ai * ki;
        float pi = ar * ki + ai * kr;
        sr[f] = pr * inv;
        si[f] = -pi * inv;
    }
    __syncthreads();
    fft2048_r8(sr, si, dr, di);
    float Dh = Dp[h];
    unsigned* ya = g_yg + ((size_t)(2 * pb) * Hh + h) * Ll;
    unsigned* yb = ya + (size_t)Hh * Ll;
    #pragma unroll
    for (int qq = 0; qq < 4; qq++) {
        int idx = tid + (qq << 8);
        float v1 = sr[idx]  + Dh * ra[qq];
        float v2 = -si[idx] + Dh * rb[qq];
        ya[idx] = packhl(geluf(v1));
        yb[idx] = packhl(geluf(v2));
    }
}

// ---- shared GEMM staging: packed X tile -> Xhi/Xlo smem ----
__device__ __forceinline__ void stage_x(const unsigned* __restrict__ Xpk, int b, int kk,
                                        int l0, int tid,
                                        __nv_bfloat16 (*Xhi)[136], __nv_bfloat16 (*Xlo)[136]) {
    int xk = tid >> 4, xl = (tid & 15) * 8;
    const unsigned* xp = &Xpk[((size_t)b * Hh + kk + xk) * Ll + l0 + xl];
    uint4 p0 = *(const uint4*)xp;
    uint4 p1 = *(const uint4*)(xp + 4);
    uint4 hi, lo;
    hi.x = __byte_perm(p0.x, p0.y, 0x5410); lo.x = __byte_perm(p0.x, p0.y, 0x7632);
    hi.y = __byte_perm(p0.z, p0.w, 0x5410); lo.y = __byte_perm(p0.z, p0.w, 0x7632);
    hi.z = __byte_perm(p1.x, p1.y, 0x5410); lo.z = __byte_perm(p1.x, p1.y, 0x7632);
    hi.w = __byte_perm(p1.z, p1.w, 0x5410); lo.w = __byte_perm(p1.z, p1.w, 0x7632);
    *(uint4*)&Xhi[xk][xl] = hi;
    *(uint4*)&Xlo[xk][xl] = lo;
}

// ---------------- GEMM1: g = gate(out_w@yg + out_b + x1), packed output ----------------
__global__ void __launch_bounds__(256) k_gemm1(const float* __restrict__ bias,
                                               const unsigned* __restrict__ Xpk,
                                               const float* __restrict__ resid,
                                               unsigned* __restrict__ Yout) {
    __shared__ __nv_bfloat16 Whi[128][24], Wlo[128][24];
    __shared__ __nv_bfloat16 Xhi[16][136], Xlo[16][136];
    int l0 = blockIdx.x * 128;
    int o0 = blockIdx.y * 128;
    int b  = blockIdx.z;
    int tid = threadIdx.x;
    int lane = tid & 31, warp = tid >> 5;
    int wm = warp & 1, wn = warp >> 1;

    float acc[4][4][4];
    #pragma unroll
    for (int m = 0; m < 4; m++)
        #pragma unroll
        for (int n = 0; n < 4; n++)
            #pragma unroll
            for (int c = 0; c < 4; c++) acc[m][n][c] = 0.f;

    int wo = tid >> 1, wk = (tid & 1) * 8;
    const __nv_bfloat16* whp = &g_whi[(size_t)(o0 + wo) * 256 + wk];
    const __nv_bfloat16* wlp = &g_wlo[(size_t)(o0 + wo) * 256 + wk];

    #pragma unroll 1
    for (int it = 0; it < 16; it++) {
        int kk = it * 16;
        *(uint4*)&Whi[wo][wk] = *(const uint4*)(whp + kk);
        *(uint4*)&Wlo[wo][wk] = *(const uint4*)(wlp + kk);
        stage_x(Xpk, b, kk, l0, tid, Xhi, Xlo);
        __syncthreads();
        int k0 = (lane & 3) * 2;
        int nb = wn * 32 + (lane >> 2);
        #pragma unroll
        for (int s = 0; s < 3; s++) {
            const __nv_bfloat16 (*Wa)[24]  = (s == 2) ? Wlo : Whi;
            const __nv_bfloat16 (*Xb)[136] = (s == 1) ? Xlo : Xhi;
            unsigned bf[4][2];
            #pragma unroll
            for (int nt = 0; nt < 4; nt++) {
                int n = nb + nt * 8;
                bf[nt][0] = pckbf(Xb[k0][n],     Xb[k0 + 1][n]);
                bf[nt][1] = pckbf(Xb[k0 + 8][n], Xb[k0 + 9][n]);
            }
            #pragma unroll
            for (int m = 0; m < 4; m++) {
                int r = wm * 64 + m * 16 + (lane >> 2);
                unsigned a0 = *(const unsigned*)&Wa[r][k0];
                unsigned a1 = *(const unsigned*)&Wa[r + 8][k0];
                unsigned a2 = *(const unsigned*)&Wa[r][k0 + 8];
                unsigned a3 = *(const unsigned*)&Wa[r + 8][k0 + 8];
                #pragma unroll
                for (int nt = 0; nt < 4; nt++)
                    asm volatile(
                        "mma.sync.aligned.m16n8k16.row.col.f32.bf16.bf16.f32 "
                        "{%0,%1,%2,%3}, {%4,%5,%6,%7}, {%8,%9}, {%0,%1,%2,%3};"
                        : "+f"(acc[m][nt][0]), "+f"(acc[m][nt][1]),
                          "+f"(acc[m][nt][2]), "+f"(acc[m][nt][3])
                        : "r"(a0), "r"(a1), "r"(a2), "r"(a3),
                          "r"(bf[nt][0]), "r"(bf[nt][1]));
            }
        }
        __syncthreads();
    }

    #pragma unroll
    for (int m = 0; m < 4; m++) {
        int o = o0 + wm * 64 + m * 16 + (lane >> 2);
        float bo0 = bias[o], bo8 = bias[o + 8];
        #pragma unroll
        for (int nt = 0; nt < 4; nt++) {
            int lc = l0 + wn * 32 + nt * 8 + (lane & 3) * 2;
            size_t base0 = ((size_t)b * Hh + o) * Ll + lc;
            size_t base8 = base0 + 8 * (size_t)Ll;
            float2 r0 = *(const float2*)&resid[base0];
            float2 r8 = *(const float2*)&resid[base8];
            unsigned p0 = packhl(gatef(acc[m][nt][0] + bo0 + r0.x));
            unsigned p1 = packhl(gatef(acc[m][nt][1] + bo0 + r0.y));
            unsigned p2 = packhl(gatef(acc[m][nt][2] + bo8 + r8.x));
            unsigned p3 = packhl(gatef(acc[m][nt][3] + bo8 + r8.y));
            *(uint2*)&Yout[base0] = make_uint2(p0, p1);
            *(uint2*)&Yout[base8] = make_uint2(p2, p3);
        }
    }
}

// ---------------- GEMM2+3 fused: out1 = lin1@g+b1+x1 ; out2 = lin2@g+b2 ----------------
__global__ void __launch_bounds__(256) k_gemm23(const float* __restrict__ b1,
                                                const float* __restrict__ b2,
                                                const unsigned* __restrict__ Xpk,
                                                const float* __restrict__ resid,
                                                float* __restrict__ out) {
    __shared__ __nv_bfloat16 W1hi[128][24], W1lo[128][24];
    __shared__ __nv_bfloat16 W2hi[128][24], W2lo[128][24];
    __shared__ __nv_bfloat16 Xhi[16][136], Xlo[16][136];
    int l0 = blockIdx.x * 128;
    int o0 = blockIdx.y * 128;
    int b  = blockIdx.z;
    int tid = threadIdx.x;
    int lane = tid & 31, warp = tid >> 5;
    int wm = warp & 1, wn = warp >> 1;

    float acc1[4][4][4], acc2[4][4][4];
    #pragma unroll
    for (int m = 0; m < 4; m++)
        #pragma unroll
        for (int n = 0; n < 4; n++)
            #pragma unroll
            for (int c = 0; c < 4; c++) { acc1[m][n][c] = 0.f; acc2[m][n][c] = 0.f; }

    int wo = tid >> 1, wk = (tid & 1) * 8;
    size_t wbase = (size_t)(o0 + wo) * 256 + wk;
    const __nv_bfloat16* w1h = &g_whi[Hh*Hh + wbase];
    const __nv_bfloat16* w1l = &g_wlo[Hh*Hh + wbase];
    const __nv_bfloat16* w2h = &g_whi[2*Hh*Hh + wbase];
    const __nv_bfloat16* w2l = &g_wlo[2*Hh*Hh + wbase];

    #pragma unroll 1
    for (int it = 0; it < 16; it++) {
        int kk = it * 16;
        *(uint4*)&W1hi[wo][wk] = *(const uint4*)(w1h + kk);
        *(uint4*)&W1lo[wo][wk] = *(const uint4*)(w1l + kk);
        *(uint4*)&W2hi[wo][wk] = *(const uint4*)(w2h + kk);
        *(uint4*)&W2lo[wo][wk] = *(const uint4*)(w2l + kk);
        stage_x(Xpk, b, kk, l0, tid, Xhi, Xlo);
        __syncthreads();
        int k0 = (lane & 3) * 2;
        int nb = wn * 32 + (lane >> 2);
        #pragma unroll
        for (int s = 0; s < 3; s++) {
            const __nv_bfloat16 (*Wa1)[24] = (s == 2) ? W1lo : W1hi;
            const __nv_bfloat16 (*Wa2)[24] = (s == 2) ? W2lo : W2hi;
            const __nv_bfloat16 (*Xb)[136] = (s == 1) ? Xlo : Xhi;
            unsigned bf[4][2];
            #pragma unroll
            for (int nt = 0; nt < 4; nt++) {
                int n = nb + nt * 8;
                bf[nt][0] = pckbf(Xb[k0][n],     Xb[k0 + 1][n]);
                bf[nt][1] = pckbf(Xb[k0 + 8][n], Xb[k0 + 9][n]);
            }
            #pragma unroll
            for (int m = 0; m < 4; m++) {
                int r = wm * 64 + m * 16 + (lane >> 2);
                unsigned a0 = *(const unsigned*)&Wa1[r][k0];
                unsigned a1 = *(const unsigned*)&Wa1[r + 8][k0];
                unsigned a2 = *(const unsigned*)&Wa1[r][k0 + 8];
                unsigned a3 = *(const unsigned*)&Wa1[r + 8][k0 + 8];
                unsigned c0 = *(const unsigned*)&Wa2[r][k0];
                unsigned c1 = *(const unsigned*)&Wa2[r + 8][k0];
                unsigned c2 = *(const unsigned*)&Wa2[r][k0 + 8];
                unsigned c3 = *(const unsigned*)&Wa2[r + 8][k0 + 8];
                #pragma unroll
                for (int nt = 0; nt < 4; nt++) {
                    asm volatile(
                        "mma.sync.aligned.m16n8k16.row.col.f32.bf16.bf16.f32 "
                        "{%0,%1,%2,%3}, {%4,%5,%6,%7}, {%8,%9}, {%0,%1,%2,%3};"
                        : "+f"(acc1[m][nt][0]), "+f"(acc1[m][nt][1]),
                          "+f"(acc1[m][nt][2]), "+f"(acc1[m][nt][3])
                        : "r"(a0), "r"(a1), "r"(a2), "r"(a3),
                          "r"(bf[nt][0]), "r"(bf[nt][1]));
                    asm volatile(
                        "mma.sync.aligned.m16n8k16.row.col.f32.bf16.bf16.f32 "
                        "{%0,%1,%2,%3}, {%4,%5,%6,%7}, {%8,%9}, {%0,%1,%2,%3};"
                        : "+f"(acc2[m][nt][0]), "+f"(acc2[m][nt][1]),
                          "+f"(acc2[m][nt][2]), "+f"(acc2[m][nt][3])
                        : "r"(c0), "r"(c1), "r"(c2), "r"(c3),
                          "r"(bf[nt][0]), "r"(bf[nt][1]));
                }
            }
        }
        __syncthreads();
    }

    #pragma unroll
    for (int m = 0; m < 4; m++) {
        int o = o0 + wm * 64 + m * 16 + (lane >> 2);
        float b10 = b1[o], b18 = b1[o + 8];
        float b20 = b2[o], b28 = b2[o + 8];
        #pragma unroll
        for (int nt = 0; nt < 4; nt++) {
            int lc = l0 + wn * 32 + nt * 8 + (lane & 3) * 2;
            size_t base0 = ((size_t)b * Hh + o) * Ll + lc;
            size_t base8 = base0 + 8 * (size_t)Ll;
            float2 r0 = *(const float2*)&resid[base0];
            float2 r8 = *(const float2*)&resid[base8];
            *(float2*)&out[base0] = make_float2(acc1[m][nt][0] + b10 + r0.x,
                                                acc1[m][nt][1] + b10 + r0.y);
            *(float2*)&out[base8] = make_float2(acc1[m][nt][2] + b18 + r8.x,
                                                acc1[m][nt][3] + b18 + r8.y);
            *(float2*)&out[(size_t)BHL + base0] = make_float2(acc2[m][nt][0] + b20,
                                                              acc2[m][nt][1] + b20);
            *(float2*)&out[(size_t)BHL + base8] = make_float2(acc2[m][nt][2] + b28,
                                                              acc2[m][nt][3] + b28);
        }
    }
}

// ---------------- launch ----------------
extern "C" void kernel_launch(void* const* d_in, const int* in_sizes, int n_in,
                              void* d_out, int out_size) {
    const float* x      = (const float*)d_in[0];
    const int*   t      = (const int*)  d_in[1];
    const float* ada_w  = (const float*)d_in[2];
    const float* ada_b  = (const float*)d_in[3];
    const float* norm_w = (const float*)d_in[4];
    const float* norm_b = (const float*)d_in[5];
    const float* log_dt = (const float*)d_in[6];
    const float* A_re   = (const float*)d_in[7];
    const float* A_im   = (const float*)d_in[8];
    const float* C_re   = (const float*)d_in[9];
    const float* C_im   = (const float*)d_in[10];
    const float* Dp     = (const float*)d_in[11];
    const float* out_w  = (const float*)d_in[12];
    const float* out_b  = (const float*)d_in[13];
    const float* lin1_w = (const float*)d_in[14];
    const float* lin1_b = (const float*)d_in[15];
    const float* lin2_w = (const float*)d_in[16];
    const float* lin2_b = (const float*)d_in[17];
    float* out = (float*)d_out;
    (void)in_sizes; (void)n_in; (void)out_size;

    float *p_x1, *p_z;
    unsigned *p_yg;
    cudaGetSymbolAddress((void**)&p_x1, g_x1);
    cudaGetSymbolAddress((void**)&p_z,  g_z);
    cudaGetSymbolAddress((void**)&p_yg, g_yg);

    k_twfill<<<4, 256>>>();
    k_semb<<<64, 256>>>(t);
    k_ssm<<<256, 256>>>(log_dt, A_re, A_im, C_re, C_im);
    k_kfft<<<128, 256>>>();
    k_wprep<<<768, 256>>>(out_w, lin1_w, lin2_w);
    k_ada_gemm<<<dim3(64, 8), 256>>>(ada_w);
    k_ada_reduce<<<512, 256>>>(ada_b);
    k_adaln<<<Bb * Hh, 256>>>(x);
    k_chanln<<<dim3(64, 32), 256>>>(norm_w, norm_b);
    k_conv<<<dim3(256, 32), 256>>>(Dp);
    k_gemm1<<<dim3(8, 2, 64), 256>>>(out_b, p_yg, p_x1, (unsigned*)p_z);
    k_gemm23<<<dim3(8, 2, 64), 256>>>(lin1_b, lin2_b, (unsigned*)p_z, p_x1, out);
}

// round 9
// speedup vs baseline: 1.0385x; 1.0385x over previous
#include <cuda_runtime.h>
#include <cuda_bf16.h>
#include <math.h>

#define Bb 64
#define Hh 256
#define Ll 1024
#define Nn 64
#define BHL (Bb*Hh*Ll)

// ---------------- scratch (device globals; no allocs allowed) ----------------
__device__ float g_x1[BHL];        // post-AdaLN x (residual source)
__device__ float g_z[BHL];         // z (pre-norm out); reused as packed gate g after conv
__device__ unsigned g_yg[BHL];     // gelu(conv out + D*z), packed (bf16 hi | bf16 lo<<16)
__device__ float g_ss[Bb*2048];    // scale(0:1024) / shift(1024:2048) per batch
__device__ float g_semb[Bb*1024];  // silu(sin/cos emb)
__device__ float g_ktime[Hh*2048]; // time-domain bidirectional kernel
__device__ float g_khr[Hh*2048];   // full complex spectrum of k (re)
__device__ float g_khi[Hh*2048];   // (im)
__device__ float g_part[8*Bb*2048];// ada split-K partials
__device__ float2 g_tw[1024];      // FFT twiddles exp(-i*pi*k/1024)
__device__ __nv_bfloat16 g_whi[3*Hh*Hh]; // pre-split weights (out_w, lin1_w, lin2_w)
__device__ __nv_bfloat16 g_wlo[3*Hh*Hh];

// ---------------- helpers ----------------
__device__ __forceinline__ float geluf(float x) {
    return 0.5f * x * (1.0f + erff(x * 0.70710678118654752440f));
}
__device__ __forceinline__ float gatef(float x) {
    float t  = __expf(-fmaxf(x, -30.0f));
    float t2 = t * t;
    return ((1.0f - t2) / (1.0f + t2)) * (1.0f / (1.0f + t));
}
__device__ __forceinline__ unsigned pckbf(__nv_bfloat16 a, __nv_bfloat16 b) {
    __nv_bfloat162 t; t.x = a; t.y = b;
    return *reinterpret_cast<unsigned*>(&t);
}
// pack fp32 -> (bf16 hi | bf16 lo<<16)
__device__ __forceinline__ unsigned packhl(float v) {
    __nv_bfloat16 h = __float2bfloat16(v);
    __nv_bfloat16 l = __float2bfloat16(v - __bfloat162float(h));
    unsigned short hb = *reinterpret_cast<unsigned short*>(&h);
    unsigned short lb = *reinterpret_cast<unsigned short*>(&l);
    return (unsigned)hb | ((unsigned)lb << 16);
}

// ---------------- weight pre-split ----------------
__global__ void k_wprep(const float* __restrict__ w0,
                        const float* __restrict__ w1,
                        const float* __restrict__ w2) {
    int i = blockIdx.x * 256 + threadIdx.x;      // 0 .. 3*65536-1
    int m = i >> 16, r = i & 65535;
    float v = (m == 0) ? w0[r] : (m == 1) ? w1[r] : w2[r];
    __nv_bfloat16 h = __float2bfloat16(v);
    g_whi[i] = h;
    g_wlo[i] = __float2bfloat16(v - __bfloat162float(h));
}

// ---------------- twiddle table ----------------
__global__ void k_twfill() {
    int i = blockIdx.x * 256 + threadIdx.x;
    float ang = -3.14159265358979323846f * (float)i * (1.0f / 1024.0f);
    float sn, cs; sincosf(ang, &sn, &cs);
    g_tw[i] = make_float2(cs, sn);
}

// ---------------- sinusoidal embedding + silu ----------------
__global__ void __launch_bounds__(256) k_semb(const int* __restrict__ t) {
    int b = blockIdx.x;
    float tf = (float)t[b];
    const float cfr = (float)(-9.210340371976184 / 511.0);
    #pragma unroll
    for (int r = 0; r < 4; r++) {
        int i = threadIdx.x + (r << 8);
        float v;
        if (i < 512) v = sinf(tf * expf((float)i * cfr));
        else         v = cosf(tf * expf((float)(i - 512) * cfr));
        float sg = 1.0f / (1.0f + expf(-v));
        g_semb[b * 1024 + i] = v * sg;
    }
}

// ---------------- emb @ ada_w.T  (split-K partials) ----------------
__global__ void __launch_bounds__(256) k_ada_gemm(const float* __restrict__ W) {
    __shared__ float Ws[64][32];
    __shared__ float Eb[64][64];
    int o0 = blockIdx.x * 32;
    int kc = blockIdx.y;
    int tid = threadIdx.x;
    int o  = tid & 31;
    int bg = tid >> 5;
    float acc[8];
    #pragma unroll
    for (int j = 0; j < 8; j++) acc[j] = 0.f;

    for (int kk = kc * 128; kk < kc * 128 + 128; kk += 64) {
        {
            int oo = tid >> 3;
            int kq = tid & 7;
            const float* src = &W[(size_t)(o0 + oo) * 1024 + kk + kq * 8];
            float4 a = *(const float4*)(src);
            float4 c = *(const float4*)(src + 4);
            int kb = kq * 8;
            Ws[kb+0][oo] = a.x; Ws[kb+1][oo] = a.y; Ws[kb+2][oo] = a.z; Ws[kb+3][oo] = a.w;
            Ws[kb+4][oo] = c.x; Ws[kb+5][oo] = c.y; Ws[kb+6][oo] = c.z; Ws[kb+7][oo] = c.w;
        }
        #pragma unroll
        for (int r = 0; r < 16; r++) {
            int e = tid + (r << 8);
            int bq = e >> 6, k = e & 63;
            Eb[bq][k] = g_semb[bq * 1024 + kk + k];
        }
        __syncthreads();
        #pragma unroll 8
        for (int k = 0; k < 64; k++) {
            float wv = Ws[k][o];
            #pragma unroll
            for (int j = 0; j < 8; j++)
                acc[j] += Eb[bg * 8 + j][k] * wv;
        }
        __syncthreads();
    }
    #pragma unroll
    for (int j = 0; j < 8; j++)
        g_part[((size_t)kc * 64 + bg * 8 + j) * 2048 + o0 + o] = acc[j];
}

__global__ void __launch_bounds__(256) k_ada_reduce(const float* __restrict__ bias) {
    int idx = blockIdx.x * 256 + threadIdx.x;
    int b = idx >> 11, o = idx & 2047;
    float s = bias[o];
    #pragma unroll
    for (int kc = 0; kc < 8; kc++)
        s += g_part[((size_t)kc * 64 + b) * 2048 + o];
    g_ss[b * 2048 + o] = s;
}

// ---------------- AdaLayerNorm over L ----------------
__global__ void __launch_bounds__(256) k_adaln(const float* __restrict__ x) {
    int bh = blockIdx.x;
    int b = bh >> 8;
    int tid = threadIdx.x;
    const float4* xr = (const float4*)(x + (size_t)bh * 1024);
    float4 v = xr[tid];
    float s = v.x + v.y + v.z + v.w;
    float q = v.x*v.x + v.y*v.y + v.z*v.z + v.w*v.w;
    #pragma unroll
    for (int o = 16; o; o >>= 1) {
        s += __shfl_down_sync(0xffffffffu, s, o);
        q += __shfl_down_sync(0xffffffffu, q, o);
    }
    __shared__ float as_[8], aq_[8];
    if ((tid & 31) == 0) { as_[tid >> 5] = s; aq_[tid >> 5] = q; }
    __syncthreads();
    float S = 0.f, Q = 0.f;
    #pragma unroll
    for (int i = 0; i < 8; i++) { S += as_[i]; Q += aq_[i]; }
    float m  = S * (1.0f / 1024.0f);
    float va = Q * (1.0f / 1024.0f) - m * m;
    float rs = rsqrtf(va + 1e-5f);
    const float4* sc = (const float4*)(g_ss + b * 2048);
    const float4* sh = (const float4*)(g_ss + b * 2048 + 1024);
    float4 a = sc[tid], d = sh[tid];
    float4 o4;
    o4.x = (v.x - m) * rs * (1.0f + a.x) + d.x;
    o4.y = (v.y - m) * rs * (1.0f + a.y) + d.y;
    o4.z = (v.z - m) * rs * (1.0f + a.z) + d.z;
    o4.w = (v.w - m) * rs * (1.0f + a.w) + d.w;
    ((float4*)(g_x1 + (size_t)bh * 1024))[tid] = o4;
}

// ---------------- channel LayerNorm over H ----------------
__global__ void __launch_bounds__(256) k_chanln(const float* __restrict__ nw,
                                                const float* __restrict__ nb) {
    int b = blockIdx.x;
    int l0 = blockIdx.y * 32;
    int tid = threadIdx.x;
    int lx = tid & 31, hp = tid >> 5;
    float v[32];
    float s = 0.f, q = 0.f;
    const float* base = g_x1 + ((size_t)b * Hh) * Ll + l0 + lx;
    #pragma unroll 8
    for (int k = 0; k < 32; k++) {
        float xv = base[(size_t)(hp * 32 + k) * Ll];
        v[k] = xv; s += xv; q += xv * xv;
    }
    __shared__ float ps[8][32], pq[8][32];
    __shared__ float mean_[32], rstd_[32];
    ps[hp][lx] = s; pq[hp][lx] = q;
    __syncthreads();
    if (tid < 32) {
        float S = 0.f, Q = 0.f;
        #pragma unroll
        for (int p = 0; p < 8; p++) { S += ps[p][tid]; Q += pq[p][tid]; }
        float m  = S * (1.0f / 256.0f);
        float va = Q * (1.0f / 256.0f) - m * m;
        mean_[tid] = m; rstd_[tid] = rsqrtf(va + 1e-5f);
    }
    __syncthreads();
    float m = mean_[lx], r = rstd_[lx];
    float* zb = g_z + ((size_t)b * Hh) * Ll + l0 + lx;
    #pragma unroll 8
    for (int k = 0; k < 32; k++) {
        int h = hp * 32 + k;
        zb[(size_t)h * Ll] = (v[k] - m) * r * nw[h] + nb[h];
    }
}

// ---------------- SSM kernel ----------------
__global__ void __launch_bounds__(256) k_ssm(const float* __restrict__ log_dt,
                                             const float* __restrict__ A_re,
                                             const float* __restrict__ A_im,
                                             const float* __restrict__ C_re,
                                             const float* __restrict__ C_im) {
    __shared__ float pre[6][64];
    int h = blockIdx.x, tid = threadIdx.x;
    if (tid < 64) {
        int n = tid;
        float dt  = expf(log_dt[h]);
        float are = -expf(A_re[h * 64 + n]);
        float aim = A_im[h * 64 + n];
        float dre = dt * are, dim = dt * aim;
        float er = expf(dre);
        float sn, cs; sincosf(dim, &sn, &cs);
        float dAr = er * cs, dAi = er * sn;
        float numr = dAr - 1.0f, numi = dAi;
        float den = are * are + aim * aim;
        float fr = (numr * are + numi * aim) / den;
        float fi = (numi * are - numr * aim) / den;
        float c0re = C_re[h * 64 + n],             c0im = C_im[h * 64 + n];
        float c1re = C_re[Hh * 64 + h * 64 + n],   c1im = C_im[Hh * 64 + h * 64 + n];
        pre[0][n] = dre; pre[1][n] = dim;
        pre[2][n] = c0re * fr - c0im * fi; pre[3][n] = c0re * fi + c0im * fr;
        pre[4][n] = c1re * fr - c1im * fi; pre[5][n] = c1re * fi + c1im * fr;
    }
    __syncthreads();
    #pragma unroll
    for (int qq = 0; qq < 4; qq++) {
        int l = tid + (qq << 8);
        float lf = (float)l;
        float k0 = 0.f, k1 = 0.f;
        #pragma unroll 4
        for (int n = 0; n < 64; n++) {
            float pr = pre[0][n] * lf, pi = pre[1][n] * lf;
            float e = expf(pr);
            float sn, cs; sincosf(pi, &sn, &cs);
            float vr = e * cs, vi = e * sn;
            k0 += pre[2][n] * vr - pre[3][n] * vi;
            k1 += pre[4][n] * vr - pre[5][n] * vi;
        }
        g_ktime[h * 2048 + l]        = 2.0f * k0;
        g_ktime[h * 2048 + 2047 - l] = 2.0f * k1;
    }
}

// ---------------- radix-8 Stockham FFT, N=2048, 256 threads ----------------
__device__ __forceinline__ void fft2048_r8(float*& sr, float*& si, float*& dr, float*& di) {
    const float Cq = 0.70710678118654752440f;
    #pragma unroll
    for (int lm = 0; lm < 9; lm += 3) {
        const int m = 1 << lm;
        int i = threadIdx.x;
        int p = i >> lm;
        int r = i & (m - 1);
        float xr[8], xi[8];
        #pragma unroll
        for (int s = 0; s < 8; s++) { xr[s] = sr[i + (s << 8)]; xi[s] = si[i + (s << 8)]; }
        float pr_[4], pi_[4], qr[4], qi[4];
        #pragma unroll
        for (int s = 0; s < 4; s++) {
            pr_[s] = xr[s] + xr[s+4]; pi_[s] = xi[s] + xi[s+4];
            qr[s]  = xr[s] - xr[s+4]; qi[s]  = xi[s] - xi[s+4];
        }
        { float a=qr[1], b=qi[1]; qr[1] = Cq*(a+b); qi[1] = Cq*(b-a); }
        { float a=qr[2], b=qi[2]; qr[2] = b;        qi[2] = -a;       }
        { float a=qr[3], b=qi[3]; qr[3] = Cq*(b-a); qi[3] = -Cq*(a+b); }
        float Xr[8], Xi[8];
        {
            float r0r=pr_[0]+pr_[2], r0i=pi_[0]+pi_[2];
            float r1r=pr_[0]-pr_[2], r1i=pi_[0]-pi_[2];
            float r2r=pr_[1]+pr_[3], r2i=pi_[1]+pi_[3];
            float t3r=pr_[1]-pr_[3], t3i=pi_[1]-pi_[3];
            float r3r=t3i, r3i=-t3r;
            Xr[0]=r0r+r2r; Xi[0]=r0i+r2i;
            Xr[2]=r1r+r3r; Xi[2]=r1i+r3i;
            Xr[4]=r0r-r2r; Xi[4]=r0i-r2i;
            Xr[6]=r1r-r3r; Xi[6]=r1i-r3i;
        }
        {
            float r0r=qr[0]+qr[2], r0i=qi[0]+qi[2];
            float r1r=qr[0]-qr[2], r1i=qi[0]-qi[2];
            float r2r=qr[1]+qr[3], r2i=qi[1]+qi[3];
            float t3r=qr[1]-qr[3], t3i=qi[1]-qi[3];
            float r3r=t3i, r3i=-t3r;
            Xr[1]=r0r+r2r; Xi[1]=r0i+r2i;
            Xr[3]=r1r+r3r; Xi[3]=r1i+r3i;
            Xr[5]=r0r-r2r; Xi[5]=r0i-r2i;
            Xr[7]=r1r-r3r; Xi[7]=r1i-r3i;
        }
        float2 w = g_tw[m * p];
        float wjr = 1.f, wji = 0.f;
        int o = ((m * p) << 3) + r;
        dr[o] = Xr[0]; di[o] = Xi[0];
        #pragma unroll
        for (int j = 1; j < 8; j++) {
            float nr = wjr * w.x - wji * w.y;
            wji = wji * w.x + wjr * w.y;
            wjr = nr;
            dr[o + j * m] = Xr[j] * wjr - Xi[j] * wji;
            di[o + j * m] = Xi[j] * wjr + Xr[j] * wji;
        }
        __syncthreads();
        float* tp; tp=sr;sr=dr;dr=tp; tp=si;si=di;di=tp;
    }
    #pragma unroll
    for (int q = 0; q < 2; q++) {
        int r = threadIdx.x + (q << 8);
        float a0r=sr[r],      a0i=si[r];
        float a1r=sr[r+512],  a1i=si[r+512];
        float a2r=sr[r+1024], a2i=si[r+1024];
        float a3r=sr[r+1536], a3i=si[r+1536];
        float r0r=a0r+a2r, r0i=a0i+a2i;
        float r1r=a0r-a2r, r1i=a0i-a2i;
        float r2r=a1r+a3r, r2i=a1i+a3i;
        float t3r=a1r-a3r, t3i=a1i-a3i;
        float r3r=t3i, r3i=-t3r;
        dr[r]      = r0r+r2r; di[r]      = r0i+r2i;
        dr[r+512]  = r1r+r3r; di[r+512]  = r1i+r3i;
        dr[r+1024] = r0r-r2r; di[r+1024] = r0i-r2i;
        dr[r+1536] = r1r-r3r; di[r+1536] = r1i-r3i;
    }
    __syncthreads();
    float* tp; tp=sr;sr=dr;dr=tp; tp=si;si=di;di=tp;
}

// ---------------- FFT of kernel rows ----------------
__global__ void __launch_bounds__(256) k_kfft() {
    __shared__ float bAr[2048], bAi[2048], bBr[2048], bBi[2048];
    int tid = threadIdx.x;
    int h0 = blockIdx.x * 2, h1 = h0 + 1;
    #pragma unroll
    for (int qq = 0; qq < 8; qq++) {
        int idx = tid + (qq << 8);
        bAr[idx] = g_ktime[h0 * 2048 + idx];
        bAi[idx] = g_ktime[h1 * 2048 + idx];
    }
    __syncthreads();
    float *sr = bAr, *si = bAi, *dr = bBr, *di = bBi;
    fft2048_r8(sr, si, dr, di);
    #pragma unroll
    for (int qq = 0; qq < 8; qq++) {
        int f = tid + (qq << 8);
        int fr2 = (2048 - f) & 2047;
        float ur = sr[f],  ui = si[f];
        float vr = sr[fr2], vi = -si[fr2];
        g_khr[h0 * 2048 + f] = 0.5f * (ur + vr);
        g_khi[h0 * 2048 + f] = 0.5f * (ui + vi);
        g_khr[h1 * 2048 + f] = 0.5f * (ui - vi);
        g_khi[h1 * 2048 + f] = -0.5f * (ur - vr);
    }
}

// ---------------- main conv: epilogue +D*z, gelu, pack hi/lo bf16 ----------------
__global__ void __launch_bounds__(256) k_conv(const float* __restrict__ Dp) {
    __shared__ float bAr[2048], bAi[2048], bBr[2048], bBi[2048];
    int tid = threadIdx.x;
    int h  = blockIdx.x;
    int pb = blockIdx.y;
    const float* za = g_z + ((size_t)(2 * pb) * Hh + h) * Ll;
    const float* zb = za + (size_t)Hh * Ll;
    float ra[4], rb[4];
    #pragma unroll
    for (int qq = 0; qq < 4; qq++) {
        int idx = tid + (qq << 8);
        ra[qq] = za[idx]; rb[qq] = zb[idx];
        bAr[idx] = ra[qq]; bAi[idx] = rb[qq];
        bAr[idx + 1024] = 0.f; bAi[idx + 1024] = 0.f;
    }
    __syncthreads();
    float *sr = bAr, *si = bAi, *dr = bBr, *di = bBi;
    fft2048_r8(sr, si, dr, di);
    const float* khr = g_khr + h * 2048;
    const float* khi = g_khi + h * 2048;
    const float inv = 1.0f / 2048.0f;
    #pragma unroll
    for (int qq = 0; qq < 8; qq++) {
        int f = tid + (qq << 8);
        float kr = khr[f], ki = khi[f];
        float ar = sr[f], ai = si[f];
        float pr = ar * kr - ai * ki;
        float pi = ar * ki + ai * kr;
        sr[f] = pr * inv;
        si[f] = -pi * inv;
    }
    __syncthreads();
    fft2048_r8(sr, si, dr, di);
    float Dh = Dp[h];
    unsigned* ya = g_yg + ((size_t)(2 * pb) * Hh + h) * Ll;
    unsigned* yb = ya + (size_t)Hh * Ll;
    #pragma unroll
    for (int qq = 0; qq < 4; qq++) {
        int idx = tid + (qq << 8);
        float v1 = sr[idx]  + Dh * ra[qq];
        float v2 = -si[idx] + Dh * rb[qq];
        ya[idx] = packhl(geluf(v1));
        yb[idx] = packhl(geluf(v2));
    }
}

// ---- shared GEMM staging: packed X tile -> Xhi/Xlo smem ----
__device__ __forceinline__ void stage_x(const unsigned* __restrict__ Xpk, int b, int kk,
                                        int l0, int tid,
                                        __nv_bfloat16 (*Xhi)[136], __nv_bfloat16 (*Xlo)[136]) {
    int xk = tid >> 4, xl = (tid & 15) * 8;
    const unsigned* xp = &Xpk[((size_t)b * Hh + kk + xk) * Ll + l0 + xl];
    uint4 p0 = *(const uint4*)xp;
    uint4 p1 = *(const uint4*)(xp + 4);
    uint4 hi, lo;
    hi.x = __byte_perm(p0.x, p0.y, 0x5410); lo.x = __byte_perm(p0.x, p0.y, 0x7632);
    hi.y = __byte_perm(p0.z, p0.w, 0x5410); lo.y = __byte_perm(p0.z, p0.w, 0x7632);
    hi.z = __byte_perm(p1.x, p1.y, 0x5410); lo.z = __byte_perm(p1.x, p1.y, 0x7632);
    hi.w = __byte_perm(p1.z, p1.w, 0x5410); lo.w = __byte_perm(p1.z, p1.w, 0x7632);
    *(uint4*)&Xhi[xk][xl] = hi;
    *(uint4*)&Xlo[xk][xl] = lo;
}

// ---------------- GEMM1: g = gate(out_w@yg + out_b + x1), packed output ----------------
__global__ void __launch_bounds__(256) k_gemm1(const float* __restrict__ bias,
                                               const unsigned* __restrict__ Xpk,
                                               const float* __restrict__ resid,
                                               unsigned* __restrict__ Yout) {
    __shared__ __nv_bfloat16 Whi[128][24], Wlo[128][24];
    __shared__ __nv_bfloat16 Xhi[16][136], Xlo[16][136];
    int l0 = blockIdx.x * 128;
    int o0 = blockIdx.y * 128;
    int b  = blockIdx.z;
    int tid = threadIdx.x;
    int lane = tid & 31, warp = tid >> 5;
    int wm = warp & 1, wn = warp >> 1;

    float acc[4][4][4];
    #pragma unroll
    for (int m = 0; m < 4; m++)
        #pragma unroll
        for (int n = 0; n < 4; n++)
            #pragma unroll
            for (int c = 0; c < 4; c++) acc[m][n][c] = 0.f;

    int wo = tid >> 1, wk = (tid & 1) * 8;
    const __nv_bfloat16* whp = &g_whi[(size_t)(o0 + wo) * 256 + wk];
    const __nv_bfloat16* wlp = &g_wlo[(size_t)(o0 + wo) * 256 + wk];

    #pragma unroll 1
    for (int it = 0; it < 16; it++) {
        int kk = it * 16;
        *(uint4*)&Whi[wo][wk] = *(const uint4*)(whp + kk);
        *(uint4*)&Wlo[wo][wk] = *(const uint4*)(wlp + kk);
        stage_x(Xpk, b, kk, l0, tid, Xhi, Xlo);
        __syncthreads();
        int k0 = (lane & 3) * 2;
        int nb = wn * 32 + (lane >> 2);
        // hoist B fragments: splits 0 and 2 share Xhi
        unsigned bfh[4][2], bfl[4][2];
        #pragma unroll
        for (int nt = 0; nt < 4; nt++) {
            int n = nb + nt * 8;
            bfh[nt][0] = pckbf(Xhi[k0][n],     Xhi[k0 + 1][n]);
            bfh[nt][1] = pckbf(Xhi[k0 + 8][n], Xhi[k0 + 9][n]);
            bfl[nt][0] = pckbf(Xlo[k0][n],     Xlo[k0 + 1][n]);
            bfl[nt][1] = pckbf(Xlo[k0 + 8][n], Xlo[k0 + 9][n]);
        }
        #pragma unroll
        for (int s = 0; s < 3; s++) {
            const __nv_bfloat16 (*Wa)[24] = (s == 2) ? Wlo : Whi;
            const unsigned (*bf)[2] = (s == 1) ? bfl : bfh;
            #pragma unroll
            for (int m = 0; m < 4; m++) {
                int r = wm * 64 + m * 16 + (lane >> 2);
                unsigned a0 = *(const unsigned*)&Wa[r][k0];
                unsigned a1 = *(const unsigned*)&Wa[r + 8][k0];
                unsigned a2 = *(const unsigned*)&Wa[r][k0 + 8];
                unsigned a3 = *(const unsigned*)&Wa[r + 8][k0 + 8];
                #pragma unroll
                for (int nt = 0; nt < 4; nt++)
                    asm volatile(
                        "mma.sync.aligned.m16n8k16.row.col.f32.bf16.bf16.f32 "
                        "{%0,%1,%2,%3}, {%4,%5,%6,%7}, {%8,%9}, {%0,%1,%2,%3};"
                        : "+f"(acc[m][nt][0]), "+f"(acc[m][nt][1]),
                          "+f"(acc[m][nt][2]), "+f"(acc[m][nt][3])
                        : "r"(a0), "r"(a1), "r"(a2), "r"(a3),
                          "r"(bf[nt][0]), "r"(bf[nt][1]));
            }
        }
        __syncthreads();
    }

    #pragma unroll
    for (int m = 0; m < 4; m++) {
        int o = o0 + wm * 64 + m * 16 + (lane >> 2);
        float bo0 = bias[o], bo8 = bias[o + 8];
        #pragma unroll
        for (int nt = 0; nt < 4; nt++) {
            int lc = l0 + wn * 32 + nt * 8 + (lane & 3) * 2;
            size_t base0 = ((size_t)b * Hh + o) * Ll + lc;
            size_t base8 = base0 + 8 * (size_t)Ll;
            float2 r0 = *(const float2*)&resid[base0];
            float2 r8 = *(const float2*)&resid[base8];
            unsigned p0 = packhl(gatef(acc[m][nt][0] + bo0 + r0.x));
            unsigned p1 = packhl(gatef(acc[m][nt][1] + bo0 + r0.y));
            unsigned p2 = packhl(gatef(acc[m][nt][2] + bo8 + r8.x));
            unsigned p3 = packhl(gatef(acc[m][nt][3] + bo8 + r8.y));
            *(uint2*)&Yout[base0] = make_uint2(p0, p1);
            *(uint2*)&Yout[base8] = make_uint2(p2, p3);
        }
    }
}

// ---------------- GEMM2/3: out = lin@g + b (+x1 if addres) ----------------
__global__ void __launch_bounds__(256) k_gemm2(int widx,
                                               const float* __restrict__ bias,
                                               const unsigned* __restrict__ Xpk,
                                               const float* __restrict__ resid,
                                               float* __restrict__ out,
                                               int addres) {
    __shared__ __nv_bfloat16 Whi[128][24], Wlo[128][24];
    __shared__ __nv_bfloat16 Xhi[16][136], Xlo[16][136];
    int l0 = blockIdx.x * 128;
    int o0 = blockIdx.y * 128;
    int b  = blockIdx.z;
    int tid = threadIdx.x;
    int lane = tid & 31, warp = tid >> 5;
    int wm = warp & 1, wn = warp >> 1;

    float acc[4][4][4];
    #pragma unroll
    for (int m = 0; m < 4; m++)
        #pragma unroll
        for (int n = 0; n < 4; n++)
            #pragma unroll
            for (int c = 0; c < 4; c++) acc[m][n][c] = 0.f;

    int wo = tid >> 1, wk = (tid & 1) * 8;
    size_t wbase = (size_t)widx * Hh * Hh + (size_t)(o0 + wo) * 256 + wk;
    const __nv_bfloat16* whp = &g_whi[wbase];
    const __nv_bfloat16* wlp = &g_wlo[wbase];

    #pragma unroll 1
    for (int it = 0; it < 16; it++) {
        int kk = it * 16;
        *(uint4*)&Whi[wo][wk] = *(const uint4*)(whp + kk);
        *(uint4*)&Wlo[wo][wk] = *(const uint4*)(wlp + kk);
        stage_x(Xpk, b, kk, l0, tid, Xhi, Xlo);
        __syncthreads();
        int k0 = (lane & 3) * 2;
        int nb = wn * 32 + (lane >> 2);
        unsigned bfh[4][2], bfl[4][2];
        #pragma unroll
        for (int nt = 0; nt < 4; nt++) {
            int n = nb + nt * 8;
            bfh[nt][0] = pckbf(Xhi[k0][n],     Xhi[k0 + 1][n]);
            bfh[nt][1] = pckbf(Xhi[k0 + 8][n], Xhi[k0 + 9][n]);
            bfl[nt][0] = pckbf(Xlo[k0][n],     Xlo[k0 + 1][n]);
            bfl[nt][1] = pckbf(Xlo[k0 + 8][n], Xlo[k0 + 9][n]);
        }
        #pragma unroll
        for (int s = 0; s < 3; s++) {
            const __nv_bfloat16 (*Wa)[24] = (s == 2) ? Wlo : Whi;
            const unsigned (*bf)[2] = (s == 1) ? bfl : bfh;
            #pragma unroll
            for (int m = 0; m < 4; m++) {
                int r = wm * 64 + m * 16 + (lane >> 2);
                unsigned a0 = *(const unsigned*)&Wa[r][k0];
                unsigned a1 = *(const unsigned*)&Wa[r + 8][k0];
                unsigned a2 = *(const unsigned*)&Wa[r][k0 + 8];
                unsigned a3 = *(const unsigned*)&Wa[r + 8][k0 + 8];
                #pragma unroll
                for (int nt = 0; nt < 4; nt++)
                    asm volatile(
                        "mma.sync.aligned.m16n8k16.row.col.f32.bf16.bf16.f32 "
                        "{%0,%1,%2,%3}, {%4,%5,%6,%7}, {%8,%9}, {%0,%1,%2,%3};"
                        : "+f"(acc[m][nt][0]), "+f"(acc[m][nt][1]),
                          "+f"(acc[m][nt][2]), "+f"(acc[m][nt][3])
                        : "r"(a0), "r"(a1), "r"(a2), "r"(a3),
                          "r"(bf[nt][0]), "r"(bf[nt][1]));
            }
        }
        __syncthreads();
    }

    #pragma unroll
    for (int m = 0; m < 4; m++) {
        int o = o0 + wm * 64 + m * 16 + (lane >> 2);
        float bo0 = bias[o], bo8 = bias[o + 8];
        #pragma unroll
        for (int nt = 0; nt < 4; nt++) {
            int lc = l0 + wn * 32 + nt * 8 + (lane & 3) * 2;
            size_t base0 = ((size_t)b * Hh + o) * Ll + lc;
            size_t base8 = base0 + 8 * (size_t)Ll;
            float v0 = acc[m][nt][0] + bo0;
            float v1 = acc[m][nt][1] + bo0;
            float v2 = acc[m][nt][2] + bo8;
            float v3 = acc[m][nt][3] + bo8;
            if (addres) {
                float2 r0 = *(const float2*)&resid[base0];
                float2 r8 = *(const float2*)&resid[base8];
                v0 += r0.x; v1 += r0.y; v2 += r8.x; v3 += r8.y;
            }
            *(float2*)&out[base0] = make_float2(v0, v1);
            *(float2*)&out[base8] = make_float2(v2, v3);
        }
    }
}

// ---------------- launch ----------------
extern "C" void kernel_launch(void* const* d_in, const int* in_sizes, int n_in,
                              void* d_out, int out_size) {
    const float* x      = (const float*)d_in[0];
    const int*   t      = (const int*)  d_in[1];
    const float* ada_w  = (const float*)d_in[2];
    const float* ada_b  = (const float*)d_in[3];
    const float* norm_w = (const float*)d_in[4];
    const float* norm_b = (const float*)d_in[5];
    const float* log_dt = (const float*)d_in[6];
    const float* A_re   = (const float*)d_in[7];
    const float* A_im   = (const float*)d_in[8];
    const float* C_re   = (const float*)d_in[9];
    const float* C_im   = (const float*)d_in[10];
    const float* Dp     = (const float*)d_in[11];
    const float* out_w  = (const float*)d_in[12];
    const float* out_b  = (const float*)d_in[13];
    const float* lin1_w = (const float*)d_in[14];
    const float* lin1_b = (const float*)d_in[15];
    const float* lin2_w = (const float*)d_in[16];
    const float* lin2_b = (const float*)d_in[17];
    float* out = (float*)d_out;
    (void)in_sizes; (void)n_in; (void)out_size;

    float *p_x1, *p_z;
    unsigned *p_yg;
    cudaGetSymbolAddress((void**)&p_x1, g_x1);
    cudaGetSymbolAddress((void**)&p_z,  g_z);
    cudaGetSymbolAddress((void**)&p_yg, g_yg);

    k_twfill<<<4, 256>>>();
    k_semb<<<64, 256>>>(t);
    k_ssm<<<256, 256>>>(log_dt, A_re, A_im, C_re, C_im);
    k_kfft<<<128, 256>>>();
    k_wprep<<<768, 256>>>(out_w, lin1_w, lin2_w);
    k_ada_gemm<<<dim3(64, 8), 256>>>(ada_w);
    k_ada_reduce<<<512, 256>>>(ada_b);
    k_adaln<<<Bb * Hh, 256>>>(x);
    k_chanln<<<dim3(64, 32), 256>>>(norm_w, norm_b);
    k_conv<<<dim3(256, 32), 256>>>(Dp);
    k_gemm1<<<dim3(8, 2, 64), 256>>>(out_b, p_yg, p_x1, (unsigned*)p_z);
    k_gemm2<<<dim3(8, 2, 64), 256>>>(1, lin1_b, (unsigned*)p_z, p_x1, out, 1);
    k_gemm2<<<dim3(8, 2, 64), 256>>>(2, lin2_b, (unsigned*)p_z, p_x1, out + BHL, 0);
}

// round 10
// speedup vs baseline: 1.1237x; 1.0820x over previous
#include <cuda_runtime.h>
#include <cuda_bf16.h>
#include <math.h>

#define Bb 64
#define Hh 256
#define Ll 1024
#define Nn 64
#define BHL (Bb*Hh*Ll)

// ---------------- scratch (device globals; no allocs allowed) ----------------
__device__ float g_x1[BHL];        // post-AdaLN x (residual source)
__device__ float g_z[BHL];         // z (pre-norm out); reused as packed gate g after conv
__device__ unsigned g_yg[BHL];     // gelu(conv out + D*z), packed (bf16 hi | bf16 lo<<16)
__device__ float g_ss[Bb*2048];    // scale(0:1024) / shift(1024:2048) per batch
__device__ float g_semb[Bb*1024];  // silu(sin/cos emb)
__device__ float g_ktime[Hh*2048]; // time-domain bidirectional kernel
__device__ float g_khr[Hh*2048];   // full complex spectrum of k (re)
__device__ float g_khi[Hh*2048];   // (im)
__device__ float g_part[8*Bb*2048];// ada split-K partials
__device__ float2 g_tw[1024];      // FFT twiddles exp(-i*pi*k/1024)
__device__ __nv_bfloat16 g_whi[3*Hh*Hh]; // pre-split weights (out_w, lin1_w, lin2_w)
__device__ __nv_bfloat16 g_wlo[3*Hh*Hh];

// ---------------- helpers ----------------
__device__ __forceinline__ float geluf(float x) {
    return 0.5f * x * (1.0f + erff(x * 0.70710678118654752440f));
}
__device__ __forceinline__ float gatef(float x) {
    float t  = __expf(-fmaxf(x, -30.0f));
    float t2 = t * t;
    return ((1.0f - t2) / (1.0f + t2)) * (1.0f / (1.0f + t));
}
__device__ __forceinline__ unsigned pckbf(__nv_bfloat16 a, __nv_bfloat16 b) {
    __nv_bfloat162 t; t.x = a; t.y = b;
    return *reinterpret_cast<unsigned*>(&t);
}
// pack fp32 -> (bf16 hi | bf16 lo<<16)
__device__ __forceinline__ unsigned packhl(float v) {
    __nv_bfloat16 h = __float2bfloat16(v);
    __nv_bfloat16 l = __float2bfloat16(v - __bfloat162float(h));
    unsigned short hb = *reinterpret_cast<unsigned short*>(&h);
    unsigned short lb = *reinterpret_cast<unsigned short*>(&l);
    return (unsigned)hb | ((unsigned)lb << 16);
}

// ---------------- weight pre-split ----------------
__global__ void k_wprep(const float* __restrict__ w0,
                        const float* __restrict__ w1,
                        const float* __restrict__ w2) {
    int i = blockIdx.x * 256 + threadIdx.x;      // 0 .. 3*65536-1
    int m = i >> 16, r = i & 65535;
    float v = (m == 0) ? w0[r] : (m == 1) ? w1[r] : w2[r];
    __nv_bfloat16 h = __float2bfloat16(v);
    g_whi[i] = h;
    g_wlo[i] = __float2bfloat16(v - __bfloat162float(h));
}

// ---------------- twiddle table ----------------
__global__ void k_twfill() {
    int i = blockIdx.x * 256 + threadIdx.x;
    float ang = -3.14159265358979323846f * (float)i * (1.0f / 1024.0f);
    float sn, cs; sincosf(ang, &sn, &cs);
    g_tw[i] = make_float2(cs, sn);
}

// ---------------- sinusoidal embedding + silu ----------------
__global__ void __launch_bounds__(256) k_semb(const int* __restrict__ t) {
    int b = blockIdx.x;
    float tf = (float)t[b];
    const float cfr = (float)(-9.210340371976184 / 511.0);
    #pragma unroll
    for (int r = 0; r < 4; r++) {
        int i = threadIdx.x + (r << 8);
        float v;
        if (i < 512) v = sinf(tf * expf((float)i * cfr));
        else         v = cosf(tf * expf((float)(i - 512) * cfr));
        float sg = 1.0f / (1.0f + expf(-v));
        g_semb[b * 1024 + i] = v * sg;
    }
}

// ---------------- emb @ ada_w.T  (split-K partials) ----------------
__global__ void __launch_bounds__(256) k_ada_gemm(const float* __restrict__ W) {
    __shared__ float Ws[64][32];
    __shared__ float Eb[64][64];
    int o0 = blockIdx.x * 32;
    int kc = blockIdx.y;
    int tid = threadIdx.x;
    int o  = tid & 31;
    int bg = tid >> 5;
    float acc[8];
    #pragma unroll
    for (int j = 0; j < 8; j++) acc[j] = 0.f;

    for (int kk = kc * 128; kk < kc * 128 + 128; kk += 64) {
        {
            int oo = tid >> 3;
            int kq = tid & 7;
            const float* src = &W[(size_t)(o0 + oo) * 1024 + kk + kq * 8];
            float4 a = *(const float4*)(src);
            float4 c = *(const float4*)(src + 4);
            int kb = kq * 8;
            Ws[kb+0][oo] = a.x; Ws[kb+1][oo] = a.y; Ws[kb+2][oo] = a.z; Ws[kb+3][oo] = a.w;
            Ws[kb+4][oo] = c.x; Ws[kb+5][oo] = c.y; Ws[kb+6][oo] = c.z; Ws[kb+7][oo] = c.w;
        }
        #pragma unroll
        for (int r = 0; r < 16; r++) {
            int e = tid + (r << 8);
            int bq = e >> 6, k = e & 63;
            Eb[bq][k] = g_semb[bq * 1024 + kk + k];
        }
        __syncthreads();
        #pragma unroll 8
        for (int k = 0; k < 64; k++) {
            float wv = Ws[k][o];
            #pragma unroll
            for (int j = 0; j < 8; j++)
                acc[j] += Eb[bg * 8 + j][k] * wv;
        }
        __syncthreads();
    }
    #pragma unroll
    for (int j = 0; j < 8; j++)
        g_part[((size_t)kc * 64 + bg * 8 + j) * 2048 + o0 + o] = acc[j];
}

__global__ void __launch_bounds__(256) k_ada_reduce(const float* __restrict__ bias) {
    int idx = blockIdx.x * 256 + threadIdx.x;
    int b = idx >> 11, o = idx & 2047;
    float s = bias[o];
    #pragma unroll
    for (int kc = 0; kc < 8; kc++)
        s += g_part[((size_t)kc * 64 + b) * 2048 + o];
    g_ss[b * 2048 + o] = s;
}

// ---------------- AdaLayerNorm over L ----------------
__global__ void __launch_bounds__(256) k_adaln(const float* __restrict__ x) {
    int bh = blockIdx.x;
    int b = bh >> 8;
    int tid = threadIdx.x;
    const float4* xr = (const float4*)(x + (size_t)bh * 1024);
    float4 v = xr[tid];
    float s = v.x + v.y + v.z + v.w;
    float q = v.x*v.x + v.y*v.y + v.z*v.z + v.w*v.w;
    #pragma unroll
    for (int o = 16; o; o >>= 1) {
        s += __shfl_down_sync(0xffffffffu, s, o);
        q += __shfl_down_sync(0xffffffffu, q, o);
    }
    __shared__ float as_[8], aq_[8];
    if ((tid & 31) == 0) { as_[tid >> 5] = s; aq_[tid >> 5] = q; }
    __syncthreads();
    float S = 0.f, Q = 0.f;
    #pragma unroll
    for (int i = 0; i < 8; i++) { S += as_[i]; Q += aq_[i]; }
    float m  = S * (1.0f / 1024.0f);
    float va = Q * (1.0f / 1024.0f) - m * m;
    float rs = rsqrtf(va + 1e-5f);
    const float4* sc = (const float4*)(g_ss + b * 2048);
    const float4* sh = (const float4*)(g_ss + b * 2048 + 1024);
    float4 a = sc[tid], d = sh[tid];
    float4 o4;
    o4.x = (v.x - m) * rs * (1.0f + a.x) + d.x;
    o4.y = (v.y - m) * rs * (1.0f + a.y) + d.y;
    o4.z = (v.z - m) * rs * (1.0f + a.z) + d.z;
    o4.w = (v.w - m) * rs * (1.0f + a.w) + d.w;
    ((float4*)(g_x1 + (size_t)bh * 1024))[tid] = o4;
}

// ---------------- channel LayerNorm over H ----------------
__global__ void __launch_bounds__(256) k_chanln(const float* __restrict__ nw,
                                                const float* __restrict__ nb) {
    int b = blockIdx.x;
    int l0 = blockIdx.y * 32;
    int tid = threadIdx.x;
    int lx = tid & 31, hp = tid >> 5;
    float v[32];
    float s = 0.f, q = 0.f;
    const float* base = g_x1 + ((size_t)b * Hh) * Ll + l0 + lx;
    #pragma unroll 8
    for (int k = 0; k < 32; k++) {
        float xv = base[(size_t)(hp * 32 + k) * Ll];
        v[k] = xv; s += xv; q += xv * xv;
    }
    __shared__ float ps[8][32], pq[8][32];
    __shared__ float mean_[32], rstd_[32];
    ps[hp][lx] = s; pq[hp][lx] = q;
    __syncthreads();
    if (tid < 32) {
        float S = 0.f, Q = 0.f;
        #pragma unroll
        for (int p = 0; p < 8; p++) { S += ps[p][tid]; Q += pq[p][tid]; }
        float m  = S * (1.0f / 256.0f);
        float va = Q * (1.0f / 256.0f) - m * m;
        mean_[tid] = m; rstd_[tid] = rsqrtf(va + 1e-5f);
    }
    __syncthreads();
    float m = mean_[lx], r = rstd_[lx];
    float* zb = g_z + ((size_t)b * Hh) * Ll + l0 + lx;
    #pragma unroll 8
    for (int k = 0; k < 32; k++) {
        int h = hp * 32 + k;
        zb[(size_t)h * Ll] = (v[k] - m) * r * nw[h] + nb[h];
    }
}

// ---------------- SSM kernel ----------------
__global__ void __launch_bounds__(256) k_ssm(const float* __restrict__ log_dt,
                                             const float* __restrict__ A_re,
                                             const float* __restrict__ A_im,
                                             const float* __restrict__ C_re,
                                             const float* __restrict__ C_im) {
    __shared__ float pre[6][64];
    int h = blockIdx.x, tid = threadIdx.x;
    if (tid < 64) {
        int n = tid;
        float dt  = expf(log_dt[h]);
        float are = -expf(A_re[h * 64 + n]);
        float aim = A_im[h * 64 + n];
        float dre = dt * are, dim = dt * aim;
        float er = expf(dre);
        float sn, cs; sincosf(dim, &sn, &cs);
        float dAr = er * cs, dAi = er * sn;
        float numr = dAr - 1.0f, numi = dAi;
        float den = are * are + aim * aim;
        float fr = (numr * are + numi * aim) / den;
        float fi = (numi * are - numr * aim) / den;
        float c0re = C_re[h * 64 + n],             c0im = C_im[h * 64 + n];
        float c1re = C_re[Hh * 64 + h * 64 + n],   c1im = C_im[Hh * 64 + h * 64 + n];
        pre[0][n] = dre; pre[1][n] = dim;
        pre[2][n] = c0re * fr - c0im * fi; pre[3][n] = c0re * fi + c0im * fr;
        pre[4][n] = c1re * fr - c1im * fi; pre[5][n] = c1re * fi + c1im * fr;
    }
    __syncthreads();
    #pragma unroll
    for (int qq = 0; qq < 4; qq++) {
        int l = tid + (qq << 8);
        float lf = (float)l;
        float k0 = 0.f, k1 = 0.f;
        #pragma unroll 4
        for (int n = 0; n < 64; n++) {
            float pr = pre[0][n] * lf, pi = pre[1][n] * lf;
            float e = expf(pr);
            float sn, cs; sincosf(pi, &sn, &cs);
            float vr = e * cs, vi = e * sn;
            k0 += pre[2][n] * vr - pre[3][n] * vi;
            k1 += pre[4][n] * vr - pre[5][n] * vi;
        }
        g_ktime[h * 2048 + l]        = 2.0f * k0;
        g_ktime[h * 2048 + 2047 - l] = 2.0f * k1;
    }
}

// ---------------- radix-8 Stockham FFT, N=2048, 256 threads ----------------
__device__ __forceinline__ void fft2048_r8(float*& sr, float*& si, float*& dr, float*& di) {
    const float Cq = 0.70710678118654752440f;
    #pragma unroll
    for (int lm = 0; lm < 9; lm += 3) {
        const int m = 1 << lm;
        int i = threadIdx.x;
        int p = i >> lm;
        int r = i & (m - 1);
        float xr[8], xi[8];
        #pragma unroll
        for (int s = 0; s < 8; s++) { xr[s] = sr[i + (s << 8)]; xi[s] = si[i + (s << 8)]; }
        float pr_[4], pi_[4], qr[4], qi[4];
        #pragma unroll
        for (int s = 0; s < 4; s++) {
            pr_[s] = xr[s] + xr[s+4]; pi_[s] = xi[s] + xi[s+4];
            qr[s]  = xr[s] - xr[s+4]; qi[s]  = xi[s] - xi[s+4];
        }
        { float a=qr[1], b=qi[1]; qr[1] = Cq*(a+b); qi[1] = Cq*(b-a); }
        { float a=qr[2], b=qi[2]; qr[2] = b;        qi[2] = -a;       }
        { float a=qr[3], b=qi[3]; qr[3] = Cq*(b-a); qi[3] = -Cq*(a+b); }
        float Xr[8], Xi[8];
        {
            float r0r=pr_[0]+pr_[2], r0i=pi_[0]+pi_[2];
            float r1r=pr_[0]-pr_[2], r1i=pi_[0]-pi_[2];
            float r2r=pr_[1]+pr_[3], r2i=pi_[1]+pi_[3];
            float t3r=pr_[1]-pr_[3], t3i=pi_[1]-pi_[3];
            float r3r=t3i, r3i=-t3r;
            Xr[0]=r0r+r2r; Xi[0]=r0i+r2i;
            Xr[2]=r1r+r3r; Xi[2]=r1i+r3i;
            Xr[4]=r0r-r2r; Xi[4]=r0i-r2i;
            Xr[6]=r1r-r3r; Xi[6]=r1i-r3i;
        }
        {
            float r0r=qr[0]+qr[2], r0i=qi[0]+qi[2];
            float r1r=qr[0]-qr[2], r1i=qi[0]-qi[2];
            float r2r=qr[1]+qr[3], r2i=qi[1]+qi[3];
            float t3r=qr[1]-qr[3], t3i=qi[1]-qi[3];
            float r3r=t3i, r3i=-t3r;
            Xr[1]=r0r+r2r; Xi[1]=r0i+r2i;
            Xr[3]=r1r+r3r; Xi[3]=r1i+r3i;
            Xr[5]=r0r-r2r; Xi[5]=r0i-r2i;
            Xr[7]=r1r-r3r; Xi[7]=r1i-r3i;
        }
        float2 w = g_tw[m * p];
        float wjr = 1.f, wji = 0.f;
        int o = ((m * p) << 3) + r;
        dr[o] = Xr[0]; di[o] = Xi[0];
        #pragma unroll
        for (int j = 1; j < 8; j++) {
            float nr = wjr * w.x - wji * w.y;
            wji = wji * w.x + wjr * w.y;
            wjr = nr;
            dr[o + j * m] = Xr[j] * wjr - Xi[j] * wji;
            di[o + j * m] = Xi[j] * wjr + Xr[j] * wji;
        }
        __syncthreads();
        float* tp; tp=sr;sr=dr;dr=tp; tp=si;si=di;di=tp;
    }
    #pragma unroll
    for (int q = 0; q < 2; q++) {
        int r = threadIdx.x + (q << 8);
        float a0r=sr[r],      a0i=si[r];
        float a1r=sr[r+512],  a1i=si[r+512];
        float a2r=sr[r+1024], a2i=si[r+1024];
        float a3r=sr[r+1536], a3i=si[r+1536];
        float r0r=a0r+a2r, r0i=a0i+a2i;
        float r1r=a0r-a2r, r1i=a0i-a2i;
        float r2r=a1r+a3r, r2i=a1i+a3i;
        float t3r=a1r-a3r, t3i=a1i-a3i;
        float r3r=t3i, r3i=-t3r;
        dr[r]      = r0r+r2r; di[r]      = r0i+r2i;
        dr[r+512]  = r1r+r3r; di[r+512]  = r1i+r3i;
        dr[r+1024] = r0r-r2r; di[r+1024] = r0i-r2i;
        dr[r+1536] = r1r-r3r; di[r+1536] = r1i-r3i;
    }
    __syncthreads();
    float* tp; tp=sr;sr=dr;dr=tp; tp=si;si=di;di=tp;
}

// ---------------- FFT of kernel rows ----------------
__global__ void __launch_bounds__(256) k_kfft() {
    __shared__ float bAr[2048], bAi[2048], bBr[2048], bBi[2048];
    int tid = threadIdx.x;
    int h0 = blockIdx.x * 2, h1 = h0 + 1;
    #pragma unroll
    for (int qq = 0; qq < 8; qq++) {
        int idx = tid + (qq << 8);
        bAr[idx] = g_ktime[h0 * 2048 + idx];
        bAi[idx] = g_ktime[h1 * 2048 + idx];
    }
    __syncthreads();
    float *sr = bAr, *si = bAi, *dr = bBr, *di = bBi;
    fft2048_r8(sr, si, dr, di);
    #pragma unroll
    for (int qq = 0; qq < 8; qq++) {
        int f = tid + (qq << 8);
        int fr2 = (2048 - f) & 2047;
        float ur = sr[f],  ui = si[f];
        float vr = sr[fr2], vi = -si[fr2];
        g_khr[h0 * 2048 + f] = 0.5f * (ur + vr);
        g_khi[h0 * 2048 + f] = 0.5f * (ui + vi);
        g_khr[h1 * 2048 + f] = 0.5f * (ui - vi);
        g_khi[h1 * 2048 + f] = -0.5f * (ur - vr);
    }
}

// ---------------- main conv: epilogue +D*z, gelu, pack hi/lo bf16 ----------------
__global__ void __launch_bounds__(256) k_conv(const float* __restrict__ Dp) {
    __shared__ float bAr[2048], bAi[2048], bBr[2048], bBi[2048];
    int tid = threadIdx.x;
    int h  = blockIdx.x;
    int pb = blockIdx.y;
    const float* za = g_z + ((size_t)(2 * pb) * Hh + h) * Ll;
    const float* zb = za + (size_t)Hh * Ll;
    float ra[4], rb[4];
    #pragma unroll
    for (int qq = 0; qq < 4; qq++) {
        int idx = tid + (qq << 8);
        ra[qq] = za[idx]; rb[qq] = zb[idx];
        bAr[idx] = ra[qq]; bAi[idx] = rb[qq];
        bAr[idx + 1024] = 0.f; bAi[idx + 1024] = 0.f;
    }
    __syncthreads();
    float *sr = bAr, *si = bAi, *dr = bBr, *di = bBi;
    fft2048_r8(sr, si, dr, di);
    const float* khr = g_khr + h * 2048;
    const float* khi = g_khi + h * 2048;
    const float inv = 1.0f / 2048.0f;
    #pragma unroll
    for (int qq = 0; qq < 8; qq++) {
        int f = tid + (qq << 8);
        float kr = khr[f], ki = khi[f];
        float ar = sr[f], ai = si[f];
        float pr = ar * kr - ai * ki;
        float pi = ar * ki + ai * kr;
        sr[f] = pr * inv;
        si[f] = -pi * inv;
    }
    __syncthreads();
    fft2048_r8(sr, si, dr, di);
    float Dh = Dp[h];
    unsigned* ya = g_yg + ((size_t)(2 * pb) * Hh + h) * Ll;
    unsigned* yb = ya + (size_t)Hh * Ll;
    #pragma unroll
    for (int qq = 0; qq < 4; qq++) {
        int idx = tid + (qq << 8);
        float v1 = sr[idx]  + Dh * ra[qq];
        float v2 = -si[idx] + Dh * rb[qq];
        ya[idx] = packhl(geluf(v1));
        yb[idx] = packhl(geluf(v2));
    }
}

// ---- stage packed pair (p0,p1) -> Xhi/Xlo smem ----
__device__ __forceinline__ void stage_x_store(uint4 p0, uint4 p1, int tid,
                                              __nv_bfloat16 (*Xhi)[136],
                                              __nv_bfloat16 (*Xlo)[136]) {
    int xk = tid >> 4, xl = (tid & 15) * 8;
    uint4 hi, lo;
    hi.x = __byte_perm(p0.x, p0.y, 0x5410); lo.x = __byte_perm(p0.x, p0.y, 0x7632);
    hi.y = __byte_perm(p0.z, p0.w, 0x5410); lo.y = __byte_perm(p0.z, p0.w, 0x7632);
    hi.z = __byte_perm(p1.x, p1.y, 0x5410); lo.z = __byte_perm(p1.x, p1.y, 0x7632);
    hi.w = __byte_perm(p1.z, p1.w, 0x5410); lo.w = __byte_perm(p1.z, p1.w, 0x7632);
    *(uint4*)&Xhi[xk][xl] = hi;
    *(uint4*)&Xlo[xk][xl] = lo;
}

// ---------------- GEMM1: g = gate(out_w@yg + out_b + x1), packed output ----------------
__global__ void __launch_bounds__(256) k_gemm1(const float* __restrict__ bias,
                                               const unsigned* __restrict__ Xpk,
                                               const float* __restrict__ resid,
                                               unsigned* __restrict__ Yout) {
    __shared__ __nv_bfloat16 Whi[128][24], Wlo[128][24];
    __shared__ __nv_bfloat16 Xhi[16][136], Xlo[16][136];
    int l0 = blockIdx.x * 128;
    int o0 = blockIdx.y * 128;
    int b  = blockIdx.z;
    int tid = threadIdx.x;
    int lane = tid & 31, warp = tid >> 5;
    int wm = warp & 1, wn = warp >> 1;

    float acc[4][4][4];
    #pragma unroll
    for (int m = 0; m < 4; m++)
        #pragma unroll
        for (int n = 0; n < 4; n++)
            #pragma unroll
            for (int c = 0; c < 4; c++) acc[m][n][c] = 0.f;

    int wo = tid >> 1, wk = (tid & 1) * 8;
    const __nv_bfloat16* whp = &g_whi[(size_t)(o0 + wo) * 256 + wk];
    const __nv_bfloat16* wlp = &g_wlo[(size_t)(o0 + wo) * 256 + wk];
    int xk = tid >> 4, xl = (tid & 15) * 8;
    const unsigned* xpb = &Xpk[((size_t)b * Hh + xk) * Ll + l0 + xl];

    // prefetch iteration 0
    uint4 wh = *(const uint4*)(whp);
    uint4 wl = *(const uint4*)(wlp);
    uint4 p0 = *(const uint4*)(xpb);
    uint4 p1 = *(const uint4*)(xpb + 4);

    #pragma unroll 1
    for (int it = 0; it < 16; it++) {
        *(uint4*)&Whi[wo][wk] = wh;
        *(uint4*)&Wlo[wo][wk] = wl;
        stage_x_store(p0, p1, tid, Xhi, Xlo);
        __syncthreads();
        if (it < 15) {   // prefetch next chunk under the MMA phase
            int kk = (it + 1) * 16;
            wh = *(const uint4*)(whp + kk);
            wl = *(const uint4*)(wlp + kk);
            const unsigned* xp = xpb + (size_t)kk * Ll;
            p0 = *(const uint4*)(xp);
            p1 = *(const uint4*)(xp + 4);
        }
        int k0 = (lane & 3) * 2;
        int nb = wn * 32 + (lane >> 2);
        unsigned bfh[4][2], bfl[4][2];
        #pragma unroll
        for (int nt = 0; nt < 4; nt++) {
            int n = nb + nt * 8;
            bfh[nt][0] = pckbf(Xhi[k0][n],     Xhi[k0 + 1][n]);
            bfh[nt][1] = pckbf(Xhi[k0 + 8][n], Xhi[k0 + 9][n]);
            bfl[nt][0] = pckbf(Xlo[k0][n],     Xlo[k0 + 1][n]);
            bfl[nt][1] = pckbf(Xlo[k0 + 8][n], Xlo[k0 + 9][n]);
        }
        #pragma unroll
        for (int s = 0; s < 3; s++) {
            const __nv_bfloat16 (*Wa)[24] = (s == 2) ? Wlo : Whi;
            const unsigned (*bf)[2] = (s == 1) ? bfl : bfh;
            #pragma unroll
            for (int m = 0; m < 4; m++) {
                int r = wm * 64 + m * 16 + (lane >> 2);
                unsigned a0 = *(const unsigned*)&Wa[r][k0];
                unsigned a1 = *(const unsigned*)&Wa[r + 8][k0];
                unsigned a2 = *(const unsigned*)&Wa[r][k0 + 8];
                unsigned a3 = *(const unsigned*)&Wa[r + 8][k0 + 8];
                #pragma unroll
                for (int nt = 0; nt < 4; nt++)
                    asm volatile(
                        "mma.sync.aligned.m16n8k16.row.col.f32.bf16.bf16.f32 "
                        "{%0,%1,%2,%3}, {%4,%5,%6,%7}, {%8,%9}, {%0,%1,%2,%3};"
                        : "+f"(acc[m][nt][0]), "+f"(acc[m][nt][1]),
                          "+f"(acc[m][nt][2]), "+f"(acc[m][nt][3])
                        : "r"(a0), "r"(a1), "r"(a2), "r"(a3),
                          "r"(bf[nt][0]), "r"(bf[nt][1]));
            }
        }
        __syncthreads();
    }

    #pragma unroll
    for (int m = 0; m < 4; m++) {
        int o = o0 + wm * 64 + m * 16 + (lane >> 2);
        float bo0 = bias[o], bo8 = bias[o + 8];
        #pragma unroll
        for (int nt = 0; nt < 4; nt++) {
            int lc = l0 + wn * 32 + nt * 8 + (lane & 3) * 2;
            size_t base0 = ((size_t)b * Hh + o) * Ll + lc;
            size_t base8 = base0 + 8 * (size_t)Ll;
            float2 r0 = *(const float2*)&resid[base0];
            float2 r8 = *(const float2*)&resid[base8];
            unsigned q0 = packhl(gatef(acc[m][nt][0] + bo0 + r0.x));
            unsigned q1 = packhl(gatef(acc[m][nt][1] + bo0 + r0.y));
            unsigned q2 = packhl(gatef(acc[m][nt][2] + bo8 + r8.x));
            unsigned q3 = packhl(gatef(acc[m][nt][3] + bo8 + r8.y));
            *(uint2*)&Yout[base0] = make_uint2(q0, q1);
            *(uint2*)&Yout[base8] = make_uint2(q2, q3);
        }
    }
}

// ---------------- GEMM2/3: out = lin@g + b (+x1 if addres) ----------------
__global__ void __launch_bounds__(256) k_gemm2(int widx,
                                               const float* __restrict__ bias,
                                               const unsigned* __restrict__ Xpk,
                                               const float* __restrict__ resid,
                                               float* __restrict__ out,
                                               int addres) {
    __shared__ __nv_bfloat16 Whi[128][24], Wlo[128][24];
    __shared__ __nv_bfloat16 Xhi[16][136], Xlo[16][136];
    int l0 = blockIdx.x * 128;
    int o0 = blockIdx.y * 128;
    int b  = blockIdx.z;
    int tid = threadIdx.x;
    int lane = tid & 31, warp = tid >> 5;
    int wm = warp & 1, wn = warp >> 1;

    float acc[4][4][4];
    #pragma unroll
    for (int m = 0; m < 4; m++)
        #pragma unroll
        for (int n = 0; n < 4; n++)
            #pragma unroll
            for (int c = 0; c < 4; c++) acc[m][n][c] = 0.f;

    int wo = tid >> 1, wk = (tid & 1) * 8;
    size_t wbase = (size_t)widx * Hh * Hh + (size_t)(o0 + wo) * 256 + wk;
    const __nv_bfloat16* whp = &g_whi[wbase];
    const __nv_bfloat16* wlp = &g_wlo[wbase];
    int xk = tid >> 4, xl = (tid & 15) * 8;
    const unsigned* xpb = &Xpk[((size_t)b * Hh + xk) * Ll + l0 + xl];

    uint4 wh = *(const uint4*)(whp);
    uint4 wl = *(const uint4*)(wlp);
    uint4 p0 = *(const uint4*)(xpb);
    uint4 p1 = *(const uint4*)(xpb + 4);

    #pragma unroll 1
    for (int it = 0; it < 16; it++) {
        *(uint4*)&Whi[wo][wk] = wh;
        *(uint4*)&Wlo[wo][wk] = wl;
        stage_x_store(p0, p1, tid, Xhi, Xlo);
        __syncthreads();
        if (it < 15) {
            int kk = (it + 1) * 16;
            wh = *(const uint4*)(whp + kk);
            wl = *(const uint4*)(wlp + kk);
            const unsigned* xp = xpb + (size_t)kk * Ll;
            p0 = *(const uint4*)(xp);
            p1 = *(const uint4*)(xp + 4);
        }
        int k0 = (lane & 3) * 2;
        int nb = wn * 32 + (lane >> 2);
        unsigned bfh[4][2], bfl[4][2];
        #pragma unroll
        for (int nt = 0; nt < 4; nt++) {
            int n = nb + nt * 8;
            bfh[nt][0] = pckbf(Xhi[k0][n],     Xhi[k0 + 1][n]);
            bfh[nt][1] = pckbf(Xhi[k0 + 8][n], Xhi[k0 + 9][n]);
            bfl[nt][0] = pckbf(Xlo[k0][n],     Xlo[k0 + 1][n]);
            bfl[nt][1] = pckbf(Xlo[k0 + 8][n], Xlo[k0 + 9][n]);
        }
        #pragma unroll
        for (int s = 0; s < 3; s++) {
            const __nv_bfloat16 (*Wa)[24] = (s == 2) ? Wlo : Whi;
            const unsigned (*bf)[2] = (s == 1) ? bfl : bfh;
            #pragma unroll
            for (int m = 0; m < 4; m++) {
                int r = wm * 64 + m * 16 + (lane >> 2);
                unsigned a0 = *(const unsigned*)&Wa[r][k0];
                unsigned a1 = *(const unsigned*)&Wa[r + 8][k0];
                unsigned a2 = *(const unsigned*)&Wa[r][k0 + 8];
                unsigned a3 = *(const unsigned*)&Wa[r + 8][k0 + 8];
                #pragma unroll
                for (int nt = 0; nt < 4; nt++)
                    asm volatile(
                        "mma.sync.aligned.m16n8k16.row.col.f32.bf16.bf16.f32 "
                        "{%0,%1,%2,%3}, {%4,%5,%6,%7}, {%8,%9}, {%0,%1,%2,%3};"
                        : "+f"(acc[m][nt][0]), "+f"(acc[m][nt][1]),
                          "+f"(acc[m][nt][2]), "+f"(acc[m][nt][3])
                        : "r"(a0), "r"(a1), "r"(a2), "r"(a3),
                          "r"(bf[nt][0]), "r"(bf[nt][1]));
            }
        }
        __syncthreads();
    }

    #pragma unroll
    for (int m = 0; m < 4; m++) {
        int o = o0 + wm * 64 + m * 16 + (lane >> 2);
        float bo0 = bias[o], bo8 = bias[o + 8];
        #pragma unroll
        for (int nt = 0; nt < 4; nt++) {
            int lc = l0 + wn * 32 + nt * 8 + (lane & 3) * 2;
            size_t base0 = ((size_t)b * Hh + o) * Ll + lc;
            size_t base8 = base0 + 8 * (size_t)Ll;
            float v0 = acc[m][nt][0] + bo0;
            float v1 = acc[m][nt][1] + bo0;
            float v2 = acc[m][nt][2] + bo8;
            float v3 = acc[m][nt][3] + bo8;
            if (addres) {
                float2 r0 = *(const float2*)&resid[base0];
                float2 r8 = *(const float2*)&resid[base8];
                v0 += r0.x; v1 += r0.y; v2 += r8.x; v3 += r8.y;
            }
            *(float2*)&out[base0] = make_float2(v0, v1);
            *(float2*)&out[base8] = make_float2(v2, v3);
        }
    }
}

// ---------------- launch ----------------
extern "C" void kernel_launch(void* const* d_in, const int* in_sizes, int n_in,
                              void* d_out, int out_size) {
    const float* x      = (const float*)d_in[0];
    const int*   t      = (const int*)  d_in[1];
    const float* ada_w  = (const float*)d_in[2];
    const float* ada_b  = (const float*)d_in[3];
    const float* norm_w = (const float*)d_in[4];
    const float* norm_b = (const float*)d_in[5];
    const float* log_dt = (const float*)d_in[6];
    const float* A_re   = (const float*)d_in[7];
    const float* A_im   = (const float*)d_in[8];
    const float* C_re   = (const float*)d_in[9];
    const float* C_im   = (const float*)d_in[10];
    const float* Dp     = (const float*)d_in[11];
    const float* out_w  = (const float*)d_in[12];
    const float* out_b  = (const float*)d_in[13];
    const float* lin1_w = (const float*)d_in[14];
    const float* lin1_b = (const float*)d_in[15];
    const float* lin2_w = (const float*)d_in[16];
    const float* lin2_b = (const float*)d_in[17];
    float* out = (float*)d_out;
    (void)in_sizes; (void)n_in; (void)out_size;

    float *p_x1, *p_z;
    unsigned *p_yg;
    cudaGetSymbolAddress((void**)&p_x1, g_x1);
    cudaGetSymbolAddress((void**)&p_z,  g_z);
    cudaGetSymbolAddress((void**)&p_yg, g_yg);

    k_twfill<<<4, 256>>>();
    k_semb<<<64, 256>>>(t);
    k_ssm<<<256, 256>>>(log_dt, A_re, A_im, C_re, C_im);
    k_kfft<<<128, 256>>>();
    k_wprep<<<768, 256>>>(out_w, lin1_w, lin2_w);
    k_ada_gemm<<<dim3(64, 8), 256>>>(ada_w);
    k_ada_reduce<<<512, 256>>>(ada_b);
    k_adaln<<<Bb * Hh, 256>>>(x);
    k_chanln<<<dim3(64, 32), 256>>>(norm_w, norm_b);
    k_conv<<<dim3(256, 32), 256>>>(Dp);
    k_gemm1<<<dim3(8, 2, 64), 256>>>(out_b, p_yg, p_x1, (unsigned*)p_z);
    k_gemm2<<<dim3(8, 2, 64), 256>>>(1, lin1_b, (unsigned*)p_z, p_x1, out, 1);
    k_gemm2<<<dim3(8, 2, 64), 256>>>(2, lin2_b, (unsigned*)p_z, p_x1, out + BHL, 0);
}

// round 11
// speedup vs baseline: 1.1681x; 1.0395x over previous
#include <cuda_runtime.h>
#include <cuda_bf16.h>
#include <math.h>

#define Bb 64
#define Hh 256
#define Ll 1024
#define Nn 64
#define BHL (Bb*Hh*Ll)

// ---------------- scratch (device globals; no allocs allowed) ----------------
__device__ float g_x1[BHL];        // post-AdaLN x (residual source)
__device__ float g_z[BHL];         // z (pre-norm out); reused as packed gate g after conv
__device__ unsigned g_yg[BHL];     // gelu(conv out + D*z), packed (bf16 hi | bf16 lo<<16)
__device__ float g_ss[Bb*2048];    // scale(0:1024) / shift(1024:2048) per batch
__device__ float g_semb[Bb*1024];  // silu(sin/cos emb)
__device__ float g_ktime[Hh*2048]; // time-domain bidirectional kernel
__device__ float g_khr[Hh*2048];   // full complex spectrum of k (re)
__device__ float g_khi[Hh*2048];   // (im)
__device__ float g_part[8*Bb*2048];// ada split-K partials
__device__ float2 g_tw[1024];      // FFT twiddles exp(-i*pi*k/1024)
__device__ __nv_bfloat16 g_whi[3*Hh*Hh]; // pre-split weights (out_w, lin1_w, lin2_w)
__device__ __nv_bfloat16 g_wlo[3*Hh*Hh];

// ---------------- helpers ----------------
__device__ __forceinline__ float geluf(float x) {
    return 0.5f * x * (1.0f + erff(x * 0.70710678118654752440f));
}
__device__ __forceinline__ float gatef(float x) {
    float t  = __expf(-fmaxf(x, -30.0f));
    float t2 = t * t;
    return ((1.0f - t2) / (1.0f + t2)) * (1.0f / (1.0f + t));
}
__device__ __forceinline__ unsigned pckbf(__nv_bfloat16 a, __nv_bfloat16 b) {
    __nv_bfloat162 t; t.x = a; t.y = b;
    return *reinterpret_cast<unsigned*>(&t);
}
// pack fp32 -> (bf16 hi | bf16 lo<<16)
__device__ __forceinline__ unsigned packhl(float v) {
    __nv_bfloat16 h = __float2bfloat16(v);
    __nv_bfloat16 l = __float2bfloat16(v - __bfloat162float(h));
    unsigned short hb = *reinterpret_cast<unsigned short*>(&h);
    unsigned short lb = *reinterpret_cast<unsigned short*>(&l);
    return (unsigned)hb | ((unsigned)lb << 16);
}

// ---------------- weight pre-split ----------------
__global__ void k_wprep(const float* __restrict__ w0,
                        const float* __restrict__ w1,
                        const float* __restrict__ w2) {
    int i = blockIdx.x * 256 + threadIdx.x;      // 0 .. 3*65536-1
    int m = i >> 16, r = i & 65535;
    float v = (m == 0) ? w0[r] : (m == 1) ? w1[r] : w2[r];
    __nv_bfloat16 h = __float2bfloat16(v);
    g_whi[i] = h;
    g_wlo[i] = __float2bfloat16(v - __bfloat162float(h));
}

// ---------------- twiddle table ----------------
__global__ void k_twfill() {
    int i = blockIdx.x * 256 + threadIdx.x;
    float ang = -3.14159265358979323846f * (float)i * (1.0f / 1024.0f);
    float sn, cs; sincosf(ang, &sn, &cs);
    g_tw[i] = make_float2(cs, sn);
}

// ---------------- sinusoidal embedding + silu ----------------
__global__ void __launch_bounds__(256) k_semb(const int* __restrict__ t) {
    int b = blockIdx.x;
    float tf = (float)t[b];
    const float cfr = (float)(-9.210340371976184 / 511.0);
    #pragma unroll
    for (int r = 0; r < 4; r++) {
        int i = threadIdx.x + (r << 8);
        float v;
        if (i < 512) v = sinf(tf * expf((float)i * cfr));
        else         v = cosf(tf * expf((float)(i - 512) * cfr));
        float sg = 1.0f / (1.0f + expf(-v));
        g_semb[b * 1024 + i] = v * sg;
    }
}

// ---------------- emb @ ada_w.T  (split-K partials) ----------------
__global__ void __launch_bounds__(256) k_ada_gemm(const float* __restrict__ W) {
    __shared__ float Ws[64][32];
    __shared__ float Eb[64][64];
    int o0 = blockIdx.x * 32;
    int kc = blockIdx.y;
    int tid = threadIdx.x;
    int o  = tid & 31;
    int bg = tid >> 5;
    float acc[8];
    #pragma unroll
    for (int j = 0; j < 8; j++) acc[j] = 0.f;

    for (int kk = kc * 128; kk < kc * 128 + 128; kk += 64) {
        {
            int oo = tid >> 3;
            int kq = tid & 7;
            const float* src = &W[(size_t)(o0 + oo) * 1024 + kk + kq * 8];
            float4 a = *(const float4*)(src);
            float4 c = *(const float4*)(src + 4);
            int kb = kq * 8;
            Ws[kb+0][oo] = a.x; Ws[kb+1][oo] = a.y; Ws[kb+2][oo] = a.z; Ws[kb+3][oo] = a.w;
            Ws[kb+4][oo] = c.x; Ws[kb+5][oo] = c.y; Ws[kb+6][oo] = c.z; Ws[kb+7][oo] = c.w;
        }
        #pragma unroll
        for (int r = 0; r < 16; r++) {
            int e = tid + (r << 8);
            int bq = e >> 6, k = e & 63;
            Eb[bq][k] = g_semb[bq * 1024 + kk + k];
        }
        __syncthreads();
        #pragma unroll 8
        for (int k = 0; k < 64; k++) {
            float wv = Ws[k][o];
            #pragma unroll
            for (int j = 0; j < 8; j++)
                acc[j] += Eb[bg * 8 + j][k] * wv;
        }
        __syncthreads();
    }
    #pragma unroll
    for (int j = 0; j < 8; j++)
        g_part[((size_t)kc * 64 + bg * 8 + j) * 2048 + o0 + o] = acc[j];
}

__global__ void __launch_bounds__(256) k_ada_reduce(const float* __restrict__ bias) {
    int idx = blockIdx.x * 256 + threadIdx.x;
    int b = idx >> 11, o = idx & 2047;
    float s = bias[o];
    #pragma unroll
    for (int kc = 0; kc < 8; kc++)
        s += g_part[((size_t)kc * 64 + b) * 2048 + o];
    g_ss[b * 2048 + o] = s;
}

// ---------------- AdaLayerNorm over L ----------------
__global__ void __launch_bounds__(256) k_adaln(const float* __restrict__ x) {
    int bh = blockIdx.x;
    int b = bh >> 8;
    int tid = threadIdx.x;
    const float4* xr = (const float4*)(x + (size_t)bh * 1024);
    float4 v = xr[tid];
    float s = v.x + v.y + v.z + v.w;
    float q = v.x*v.x + v.y*v.y + v.z*v.z + v.w*v.w;
    #pragma unroll
    for (int o = 16; o; o >>= 1) {
        s += __shfl_down_sync(0xffffffffu, s, o);
        q += __shfl_down_sync(0xffffffffu, q, o);
    }
    __shared__ float as_[8], aq_[8];
    if ((tid & 31) == 0) { as_[tid >> 5] = s; aq_[tid >> 5] = q; }
    __syncthreads();
    float S = 0.f, Q = 0.f;
    #pragma unroll
    for (int i = 0; i < 8; i++) { S += as_[i]; Q += aq_[i]; }
    float m  = S * (1.0f / 1024.0f);
    float va = Q * (1.0f / 1024.0f) - m * m;
    float rs = rsqrtf(va + 1e-5f);
    const float4* sc = (const float4*)(g_ss + b * 2048);
    const float4* sh = (const float4*)(g_ss + b * 2048 + 1024);
    float4 a = sc[tid], d = sh[tid];
    float4 o4;
    o4.x = (v.x - m) * rs * (1.0f + a.x) + d.x;
    o4.y = (v.y - m) * rs * (1.0f + a.y) + d.y;
    o4.z = (v.z - m) * rs * (1.0f + a.z) + d.z;
    o4.w = (v.w - m) * rs * (1.0f + a.w) + d.w;
    ((float4*)(g_x1 + (size_t)bh * 1024))[tid] = o4;
}

// ---------------- channel LayerNorm over H ----------------
__global__ void __launch_bounds__(256) k_chanln(const float* __restrict__ nw,
                                                const float* __restrict__ nb) {
    int b = blockIdx.x;
    int l0 = blockIdx.y * 32;
    int tid = threadIdx.x;
    int lx = tid & 31, hp = tid >> 5;
    float v[32];
    float s = 0.f, q = 0.f;
    const float* base = g_x1 + ((size_t)b * Hh) * Ll + l0 + lx;
    #pragma unroll 8
    for (int k = 0; k < 32; k++) {
        float xv = base[(size_t)(hp * 32 + k) * Ll];
        v[k] = xv; s += xv; q += xv * xv;
    }
    __shared__ float ps[8][32], pq[8][32];
    __shared__ float mean_[32], rstd_[32];
    ps[hp][lx] = s; pq[hp][lx] = q;
    __syncthreads();
    if (tid < 32) {
        float S = 0.f, Q = 0.f;
        #pragma unroll
        for (int p = 0; p < 8; p++) { S += ps[p][tid]; Q += pq[p][tid]; }
        float m  = S * (1.0f / 256.0f);
        float va = Q * (1.0f / 256.0f) - m * m;
        mean_[tid] = m; rstd_[tid] = rsqrtf(va + 1e-5f);
    }
    __syncthreads();
    float m = mean_[lx], r = rstd_[lx];
    float* zb = g_z + ((size_t)b * Hh) * Ll + l0 + lx;
    #pragma unroll 8
    for (int k = 0; k < 32; k++) {
        int h = hp * 32 + k;
        zb[(size_t)h * Ll] = (v[k] - m) * r * nw[h] + nb[h];
    }
}

// ---------------- SSM kernel ----------------
__global__ void __launch_bounds__(256) k_ssm(const float* __restrict__ log_dt,
                                             const float* __restrict__ A_re,
                                             const float* __restrict__ A_im,
                                             const float* __restrict__ C_re,
                                             const float* __restrict__ C_im) {
    __shared__ float pre[6][64];
    int h = blockIdx.x, tid = threadIdx.x;
    if (tid < 64) {
        int n = tid;
        float dt  = expf(log_dt[h]);
        float are = -expf(A_re[h * 64 + n]);
        float aim = A_im[h * 64 + n];
        float dre = dt * are, dim = dt * aim;
        float er = expf(dre);
        float sn, cs; sincosf(dim, &sn, &cs);
        float dAr = er * cs, dAi = er * sn;
        float numr = dAr - 1.0f, numi = dAi;
        float den = are * are + aim * aim;
        float fr = (numr * are + numi * aim) / den;
        float fi = (numi * are - numr * aim) / den;
        float c0re = C_re[h * 64 + n],             c0im = C_im[h * 64 + n];
        float c1re = C_re[Hh * 64 + h * 64 + n],   c1im = C_im[Hh * 64 + h * 64 + n];
        pre[0][n] = dre; pre[1][n] = dim;
        pre[2][n] = c0re * fr - c0im * fi; pre[3][n] = c0re * fi + c0im * fr;
        pre[4][n] = c1re * fr - c1im * fi; pre[5][n] = c1re * fi + c1im * fr;
    }
    __syncthreads();
    #pragma unroll
    for (int qq = 0; qq < 4; qq++) {
        int l = tid + (qq << 8);
        float lf = (float)l;
        float k0 = 0.f, k1 = 0.f;
        #pragma unroll 4
        for (int n = 0; n < 64; n++) {
            float pr = pre[0][n] * lf, pi = pre[1][n] * lf;
            float e = expf(pr);
            float sn, cs; sincosf(pi, &sn, &cs);
            float vr = e * cs, vi = e * sn;
            k0 += pre[2][n] * vr - pre[3][n] * vi;
            k1 += pre[4][n] * vr - pre[5][n] * vi;
        }
        g_ktime[h * 2048 + l]        = 2.0f * k0;
        g_ktime[h * 2048 + 2047 - l] = 2.0f * k1;
    }
}

// ---------------- generic radix-8 Stockham stage (256 threads, N=2048) ----------------
__device__ __forceinline__ void r8_stage(const float* __restrict__ sr,
                                         const float* __restrict__ si,
                                         float* __restrict__ dr,
                                         float* __restrict__ di, int lm) {
    const float Cq = 0.70710678118654752440f;
    const int m = 1 << lm;
    int i = threadIdx.x;
    int p = i >> lm;
    int r = i & (m - 1);
    float xr[8], xi[8];
    #pragma unroll
    for (int s = 0; s < 8; s++) { xr[s] = sr[i + (s << 8)]; xi[s] = si[i + (s << 8)]; }
    float pr_[4], pi_[4], qr[4], qi[4];
    #pragma unroll
    for (int s = 0; s < 4; s++) {
        pr_[s] = xr[s] + xr[s+4]; pi_[s] = xi[s] + xi[s+4];
        qr[s]  = xr[s] - xr[s+4]; qi[s]  = xi[s] - xi[s+4];
    }
    { float a=qr[1], b=qi[1]; qr[1] = Cq*(a+b); qi[1] = Cq*(b-a); }
    { float a=qr[2], b=qi[2]; qr[2] = b;        qi[2] = -a;       }
    { float a=qr[3], b=qi[3]; qr[3] = Cq*(b-a); qi[3] = -Cq*(a+b); }
    float Xr[8], Xi[8];
    {
        float r0r=pr_[0]+pr_[2], r0i=pi_[0]+pi_[2];
        float r1r=pr_[0]-pr_[2], r1i=pi_[0]-pi_[2];
        float r2r=pr_[1]+pr_[3], r2i=pi_[1]+pi_[3];
        float t3r=pr_[1]-pr_[3], t3i=pi_[1]-pi_[3];
        float r3r=t3i, r3i=-t3r;
        Xr[0]=r0r+r2r; Xi[0]=r0i+r2i;
        Xr[2]=r1r+r3r; Xi[2]=r1i+r3i;
        Xr[4]=r0r-r2r; Xi[4]=r0i-r2i;
        Xr[6]=r1r-r3r; Xi[6]=r1i-r3i;
    }
    {
        float r0r=qr[0]+qr[2], r0i=qi[0]+qi[2];
        float r1r=qr[0]-qr[2], r1i=qi[0]-qi[2];
        float r2r=qr[1]+qr[3], r2i=qi[1]+qi[3];
        float t3r=qr[1]-qr[3], t3i=qi[1]-qi[3];
        float r3r=t3i, r3i=-t3r;
        Xr[1]=r0r+r2r; Xi[1]=r0i+r2i;
        Xr[3]=r1r+r3r; Xi[3]=r1i+r3i;
        Xr[5]=r0r-r2r; Xi[5]=r0i-r2i;
        Xr[7]=r1r-r3r; Xi[7]=r1i-r3i;
    }
    float2 w = g_tw[m * p];
    float wjr = 1.f, wji = 0.f;
    int o = ((m * p) << 3) + r;
    dr[o] = Xr[0]; di[o] = Xi[0];
    #pragma unroll
    for (int j = 1; j < 8; j++) {
        float nr = wjr * w.x - wji * w.y;
        wji = wji * w.x + wjr * w.y;
        wjr = nr;
        dr[o + j * m] = Xr[j] * wjr - Xi[j] * wji;
        di[o + j * m] = Xi[j] * wjr + Xr[j] * wji;
    }
}

// ---------------- full radix-8 FFT (generic; used by kfft) ----------------
__device__ __forceinline__ void fft2048_r8(float*& sr, float*& si, float*& dr, float*& di) {
    #pragma unroll
    for (int lm = 0; lm < 9; lm += 3) {
        r8_stage(sr, si, dr, di, lm);
        __syncthreads();
        float* tp; tp=sr;sr=dr;dr=tp; tp=si;si=di;di=tp;
    }
    #pragma unroll
    for (int q = 0; q < 2; q++) {
        int r = threadIdx.x + (q << 8);
        float a0r=sr[r],      a0i=si[r];
        float a1r=sr[r+512],  a1i=si[r+512];
        float a2r=sr[r+1024], a2i=si[r+1024];
        float a3r=sr[r+1536], a3i=si[r+1536];
        float r0r=a0r+a2r, r0i=a0i+a2i;
        float r1r=a0r-a2r, r1i=a0i-a2i;
        float r2r=a1r+a3r, r2i=a1i+a3i;
        float t3r=a1r-a3r, t3i=a1i-a3i;
        float r3r=t3i, r3i=-t3r;
        dr[r]      = r0r+r2r; di[r]      = r0i+r2i;
        dr[r+512]  = r1r+r3r; di[r+512]  = r1i+r3i;
        dr[r+1024] = r0r-r2r; di[r+1024] = r0i-r2i;
        dr[r+1536] = r1r-r3r; di[r+1536] = r1i-r3i;
    }
    __syncthreads();
    float* tp; tp=sr;sr=dr;dr=tp; tp=si;si=di;di=tp;
}

// ---------------- FFT of kernel rows ----------------
__global__ void __launch_bounds__(256) k_kfft() {
    __shared__ float bAr[2048], bAi[2048], bBr[2048], bBi[2048];
    int tid = threadIdx.x;
    int h0 = blockIdx.x * 2, h1 = h0 + 1;
    #pragma unroll
    for (int qq = 0; qq < 8; qq++) {
        int idx = tid + (qq << 8);
        bAr[idx] = g_ktime[h0 * 2048 + idx];
        bAi[idx] = g_ktime[h1 * 2048 + idx];
    }
    __syncthreads();
    float *sr = bAr, *si = bAi, *dr = bBr, *di = bBi;
    fft2048_r8(sr, si, dr, di);
    #pragma unroll
    for (int qq = 0; qq < 8; qq++) {
        int f = tid + (qq << 8);
        int fr2 = (2048 - f) & 2047;
        float ur = sr[f],  ui = si[f];
        float vr = sr[fr2], vi = -si[fr2];
        g_khr[h0 * 2048 + f] = 0.5f * (ur + vr);
        g_khi[h0 * 2048 + f] = 0.5f * (ui + vi);
        g_khr[h1 * 2048 + f] = 0.5f * (ui - vi);
        g_khi[h1 * 2048 + f] = -0.5f * (ur - vr);
    }
}

// ---------------- main conv: fused pointwise + fused epilogue ----------------
// fwd: stage1 (zero top half) -> r8(m=8) -> r8(m=64) -> r4 fused with spectrum mult
// inv: r8(m=1) -> r8(m=8) -> r8(m=64) -> r4 computing only outputs [0,1024) fused
//      with +D*z, gelu, hi/lo pack, global store.
__global__ void __launch_bounds__(256) k_conv(const float* __restrict__ Dp) {
    __shared__ float bAr[2048], bAi[2048], bBr[2048], bBi[2048];
    const float Cq = 0.70710678118654752440f;
    int tid = threadIdx.x;
    int h  = blockIdx.x;
    int pb = blockIdx.y;
    const float* za = g_z + ((size_t)(2 * pb) * Hh + h) * Ll;
    const float* zb = za + (size_t)Hh * Ll;
    float ra[4], rb[4];
    #pragma unroll
    for (int qq = 0; qq < 4; qq++) {
        int idx = tid + (qq << 8);
        ra[qq] = za[idx]; rb[qq] = zb[idx];
        bAr[idx] = ra[qq]; bAi[idx] = rb[qq];
    }
    __syncthreads();

    // ---- forward stage 1 (m=1): inputs s>=4 are the zero pad ----
    {
        float xr[4], xi[4];
        #pragma unroll
        for (int s = 0; s < 4; s++) { xr[s] = bAr[tid + (s << 8)]; xi[s] = bAi[tid + (s << 8)]; }
        // p[s] = x[s] + 0 ; q[s] = x[s] - 0
        float qr[4], qi[4];
        #pragma unroll
        for (int s = 0; s < 4; s++) { qr[s] = xr[s]; qi[s] = xi[s]; }
        { float a=qr[1], b=qi[1]; qr[1] = Cq*(a+b); qi[1] = Cq*(b-a); }
        { float a=qr[2], b=qi[2]; qr[2] = b;        qi[2] = -a;       }
        { float a=qr[3], b=qi[3]; qr[3] = Cq*(b-a); qi[3] = -Cq*(a+b); }
        float Xr[8], Xi[8];
        {
            float r0r=xr[0]+xr[2], r0i=xi[0]+xi[2];
            float r1r=xr[0]-xr[2], r1i=xi[0]-xi[2];
            float r2r=xr[1]+xr[3], r2i=xi[1]+xi[3];
            float t3r=xr[1]-xr[3], t3i=xi[1]-xi[3];
            float r3r=t3i, r3i=-t3r;
            Xr[0]=r0r+r2r; Xi[0]=r0i+r2i;
            Xr[2]=r1r+r3r; Xi[2]=r1i+r3i;
            Xr[4]=r0r-r2r; Xi[4]=r0i-r2i;
            Xr[6]=r1r-r3r; Xi[6]=r1i-r3i;
        }
        {
            float r0r=qr[0]+qr[2], r0i=qi[0]+qi[2];
            float r1r=qr[0]-qr[2], r1i=qi[0]-qi[2];
            float r2r=qr[1]+qr[3], r2i=qi[1]+qi[3];
            float t3r=qr[1]-qr[3], t3i=qi[1]-qi[3];
            float r3r=t3i, r3i=-t3r;
            Xr[1]=r0r+r2r; Xi[1]=r0i+r2i;
            Xr[3]=r1r+r3r; Xi[3]=r1i+r3i;
            Xr[5]=r0r-r2r; Xi[5]=r0i-r2i;
            Xr[7]=r1r-r3r; Xi[7]=r1i-r3i;
        }
        float2 w = g_tw[tid];
        float wjr = 1.f, wji = 0.f;
        int o = tid << 3;
        bBr[o] = Xr[0]; bBi[o] = Xi[0];
        #pragma unroll
        for (int j = 1; j < 8; j++) {
            float nr = wjr * w.x - wji * w.y;
            wji = wji * w.x + wjr * w.y;
            wjr = nr;
            bBr[o + j] = Xr[j] * wjr - Xi[j] * wji;
            bBi[o + j] = Xi[j] * wjr + Xr[j] * wji;
        }
    }
    __syncthreads();
    r8_stage(bBr, bBi, bAr, bAi, 3); __syncthreads();
    r8_stage(bAr, bAi, bBr, bBi, 6); __syncthreads();

    // ---- forward final r4 fused with spectrum multiply (+conj, +1/N) -> bA ----
    {
        const float* khr = g_khr + h * 2048;
        const float* khi = g_khi + h * 2048;
        const float inv = 1.0f / 2048.0f;
        #pragma unroll
        for (int q = 0; q < 2; q++) {
            int r = tid + (q << 8);
            float a0r=bBr[r],      a0i=bBi[r];
            float a1r=bBr[r+512],  a1i=bBi[r+512];
            float a2r=bBr[r+1024], a2i=bBi[r+1024];
            float a3r=bBr[r+1536], a3i=bBi[r+1536];
            float r0r=a0r+a2r, r0i=a0i+a2i;
            float r1r=a0r-a2r, r1i=a0i-a2i;
            float r2r=a1r+a3r, r2i=a1i+a3i;
            float t3r=a1r-a3r, t3i=a1i-a3i;
            float r3r=t3i, r3i=-t3r;
            float Xr4[4], Xi4[4];
            Xr4[0]=r0r+r2r; Xi4[0]=r0i+r2i;
            Xr4[1]=r1r+r3r; Xi4[1]=r1i+r3i;
            Xr4[2]=r0r-r2r; Xi4[2]=r0i-r2i;
            Xr4[3]=r1r-r3r; Xi4[3]=r1i-r3i;
            #pragma unroll
            for (int j = 0; j < 4; j++) {
                int f = r + j * 512;
                float kr = khr[f], ki = khi[f];
                float ar = Xr4[j], ai = Xi4[j];
                bAr[f] = (ar * kr - ai * ki) * inv;
                bAi[f] = -(ar * ki + ai * kr) * inv;
            }
        }
    }
    __syncthreads();

    // ---- inverse FFT ----
    r8_stage(bAr, bAi, bBr, bBi, 0); __syncthreads();
    r8_stage(bBr, bBi, bAr, bAi, 3); __syncthreads();
    r8_stage(bAr, bAi, bBr, bBi, 6); __syncthreads();

    // ---- inverse final r4 (outputs [0,1024) only) fused with epilogue ----
    float Dh = Dp[h];
    unsigned* ya = g_yg + ((size_t)(2 * pb) * Hh + h) * Ll;
    unsigned* yb = ya + (size_t)Hh * Ll;
    #pragma unroll
    for (int q = 0; q < 2; q++) {
        int r = tid + (q << 8);
        float a0r=bBr[r],      a0i=bBi[r];
        float a1r=bBr[r+512],  a1i=bBi[r+512];
        float a2r=bBr[r+1024], a2i=bBi[r+1024];
        float a3r=bBr[r+1536], a3i=bBi[r+1536];
        float r0r=a0r+a2r, r0i=a0i+a2i;
        float r1r=a0r-a2r, r1i=a0i-a2i;
        float r2r=a1r+a3r, r2i=a1i+a3i;
        float t3r=a1r-a3r, t3i=a1i-a3i;
        float r3r=t3i, r3i=-t3r;
        // output f1 = r  (z regs index q), f2 = r+512 (z regs index q+2)
        float o1r = r0r + r2r, o1i = r0i + r2i;
        float o2r = r1r + r3r, o2i = r1i + r3i;
        float v1 = o1r  + Dh * ra[q];
        float v2 = -o1i + Dh * rb[q];
        float v3 = o2r  + Dh * ra[q + 2];
        float v4 = -o2i + Dh * rb[q + 2];
        ya[r]       = packhl(geluf(v1));
        yb[r]       = packhl(geluf(v2));
        ya[r + 512] = packhl(geluf(v3));
        yb[r + 512] = packhl(geluf(v4));
    }
}

// ---- stage packed pair (p0,p1) -> Xhi/Xlo smem ----
__device__ __forceinline__ void stage_x_store(uint4 p0, uint4 p1, int tid,
                                              __nv_bfloat16 (*Xhi)[136],
                                              __nv_bfloat16 (*Xlo)[136]) {
    int xk = tid >> 4, xl = (tid & 15) * 8;
    uint4 hi, lo;
    hi.x = __byte_perm(p0.x, p0.y, 0x5410); lo.x = __byte_perm(p0.x, p0.y, 0x7632);
    hi.y = __byte_perm(p0.z, p0.w, 0x5410); lo.y = __byte_perm(p0.z, p0.w, 0x7632);
    hi.z = __byte_perm(p1.x, p1.y, 0x5410); lo.z = __byte_perm(p1.x, p1.y, 0x7632);
    hi.w = __byte_perm(p1.z, p1.w, 0x5410); lo.w = __byte_perm(p1.z, p1.w, 0x7632);
    *(uint4*)&Xhi[xk][xl] = hi;
    *(uint4*)&Xlo[xk][xl] = lo;
}

// ---------------- GEMM1: g = gate(out_w@yg + out_b + x1), packed output ----------------
__global__ void __launch_bounds__(256) k_gemm1(const float* __restrict__ bias,
                                               const unsigned* __restrict__ Xpk,
                                               const float* __restrict__ resid,
                                               unsigned* __restrict__ Yout) {
    __shared__ __nv_bfloat16 Whi[128][24], Wlo[128][24];
    __shared__ __nv_bfloat16 Xhi[16][136], Xlo[16][136];
    int l0 = blockIdx.x * 128;
    int o0 = blockIdx.y * 128;
    int b  = blockIdx.z;
    int tid = threadIdx.x;
    int lane = tid & 31, warp = tid >> 5;
    int wm = warp & 1, wn = warp >> 1;

    float acc[4][4][4];
    #pragma unroll
    for (int m = 0; m < 4; m++)
        #pragma unroll
        for (int n = 0; n < 4; n++)
            #pragma unroll
            for (int c = 0; c < 4; c++) acc[m][n][c] = 0.f;

    int wo = tid >> 1, wk = (tid & 1) * 8;
    const __nv_bfloat16* whp = &g_whi[(size_t)(o0 + wo) * 256 + wk];
    const __nv_bfloat16* wlp = &g_wlo[(size_t)(o0 + wo) * 256 + wk];
    int xk = tid >> 4, xl = (tid & 15) * 8;
    const unsigned* xpb = &Xpk[((size_t)b * Hh + xk) * Ll + l0 + xl];

    uint4 wh = *(const uint4*)(whp);
    uint4 wl = *(const uint4*)(wlp);
    uint4 p0 = *(const uint4*)(xpb);
    uint4 p1 = *(const uint4*)(xpb + 4);

    #pragma unroll 1
    for (int it = 0; it < 16; it++) {
        *(uint4*)&Whi[wo][wk] = wh;
        *(uint4*)&Wlo[wo][wk] = wl;
        stage_x_store(p0, p1, tid, Xhi, Xlo);
        __syncthreads();
        if (it < 15) {
            int kk = (it + 1) * 16;
            wh = *(const uint4*)(whp + kk);
            wl = *(const uint4*)(wlp + kk);
            const unsigned* xp = xpb + (size_t)kk * Ll;
            p0 = *(const uint4*)(xp);
            p1 = *(const uint4*)(xp + 4);
        }
        int k0 = (lane & 3) * 2;
        int nb = wn * 32 + (lane >> 2);
        unsigned bfh[4][2], bfl[4][2];
        #pragma unroll
        for (int nt = 0; nt < 4; nt++) {
            int n = nb + nt * 8;
            bfh[nt][0] = pckbf(Xhi[k0][n],     Xhi[k0 + 1][n]);
            bfh[nt][1] = pckbf(Xhi[k0 + 8][n], Xhi[k0 + 9][n]);
            bfl[nt][0] = pckbf(Xlo[k0][n],     Xlo[k0 + 1][n]);
            bfl[nt][1] = pckbf(Xlo[k0 + 8][n], Xlo[k0 + 9][n]);
        }
        #pragma unroll
        for (int s = 0; s < 3; s++) {
            const __nv_bfloat16 (*Wa)[24] = (s == 2) ? Wlo : Whi;
            const unsigned (*bf)[2] = (s == 1) ? bfl : bfh;
            #pragma unroll
            for (int m = 0; m < 4; m++) {
                int r = wm * 64 + m * 16 + (lane >> 2);
                unsigned a0 = *(const unsigned*)&Wa[r][k0];
                unsigned a1 = *(const unsigned*)&Wa[r + 8][k0];
                unsigned a2 = *(const unsigned*)&Wa[r][k0 + 8];
                unsigned a3 = *(const unsigned*)&Wa[r + 8][k0 + 8];
                #pragma unroll
                for (int nt = 0; nt < 4; nt++)
                    asm volatile(
                        "mma.sync.aligned.m16n8k16.row.col.f32.bf16.bf16.f32 "
                        "{%0,%1,%2,%3}, {%4,%5,%6,%7}, {%8,%9}, {%0,%1,%2,%3};"
                        : "+f"(acc[m][nt][0]), "+f"(acc[m][nt][1]),
                          "+f"(acc[m][nt][2]), "+f"(acc[m][nt][3])
                        : "r"(a0), "r"(a1), "r"(a2), "r"(a3),
                          "r"(bf[nt][0]), "r"(bf[nt][1]));
            }
        }
        __syncthreads();
    }

    #pragma unroll
    for (int m = 0; m < 4; m++) {
        int o = o0 + wm * 64 + m * 16 + (lane >> 2);
        float bo0 = bias[o], bo8 = bias[o + 8];
        #pragma unroll
        for (int nt = 0; nt < 4; nt++) {
            int lc = l0 + wn * 32 + nt * 8 + (lane & 3) * 2;
            size_t base0 = ((size_t)b * Hh + o) * Ll + lc;
            size_t base8 = base0 + 8 * (size_t)Ll;
            float2 r0 = *(const float2*)&resid[base0];
            float2 r8 = *(const float2*)&resid[base8];
            unsigned q0 = packhl(gatef(acc[m][nt][0] + bo0 + r0.x));
            unsigned q1 = packhl(gatef(acc[m][nt][1] + bo0 + r0.y));
            unsigned q2 = packhl(gatef(acc[m][nt][2] + bo8 + r8.x));
            unsigned q3 = packhl(gatef(acc[m][nt][3] + bo8 + r8.y));
            *(uint2*)&Yout[base0] = make_uint2(q0, q1);
            *(uint2*)&Yout[base8] = make_uint2(q2, q3);
        }
    }
}

// ---------------- GEMM2/3: out = lin@g + b (+x1 if addres) ----------------
__global__ void __launch_bounds__(256) k_gemm2(int widx,
                                               const float* __restrict__ bias,
                                               const unsigned* __restrict__ Xpk,
                                               const float* __restrict__ resid,
                                               float* __restrict__ out,
                                               int addres) {
    __shared__ __nv_bfloat16 Whi[128][24], Wlo[128][24];
    __shared__ __nv_bfloat16 Xhi[16][136], Xlo[16][136];
    int l0 = blockIdx.x * 128;
    int o0 = blockIdx.y * 128;
    int b  = blockIdx.z;
    int tid = threadIdx.x;
    int lane = tid & 31, warp = tid >> 5;
    int wm = warp & 1, wn = warp >> 1;

    float acc[4][4][4];
    #pragma unroll
    for (int m = 0; m < 4; m++)
        #pragma unroll
        for (int n = 0; n < 4; n++)
            #pragma unroll
            for (int c = 0; c < 4; c++) acc[m][n][c] = 0.f;

    int wo = tid >> 1, wk = (tid & 1) * 8;
    size_t wbase = (size_t)widx * Hh * Hh + (size_t)(o0 + wo) * 256 + wk;
    const __nv_bfloat16* whp = &g_whi[wbase];
    const __nv_bfloat16* wlp = &g_wlo[wbase];
    int xk = tid >> 4, xl = (tid & 15) * 8;
    const unsigned* xpb = &Xpk[((size_t)b * Hh + xk) * Ll + l0 + xl];

    uint4 wh = *(const uint4*)(whp);
    uint4 wl = *(const uint4*)(wlp);
    uint4 p0 = *(const uint4*)(xpb);
    uint4 p1 = *(const uint4*)(xpb + 4);

    #pragma unroll 1
    for (int it = 0; it < 16; it++) {
        *(uint4*)&Whi[wo][wk] = wh;
        *(uint4*)&Wlo[wo][wk] = wl;
        stage_x_store(p0, p1, tid, Xhi, Xlo);
        __syncthreads();
        if (it < 15) {
            int kk = (it + 1) * 16;
            wh = *(const uint4*)(whp + kk);
            wl = *(const uint4*)(wlp + kk);
            const unsigned* xp = xpb + (size_t)kk * Ll;
            p0 = *(const uint4*)(xp);
            p1 = *(const uint4*)(xp + 4);
        }
        int k0 = (lane & 3) * 2;
        int nb = wn * 32 + (lane >> 2);
        unsigned bfh[4][2], bfl[4][2];
        #pragma unroll
        for (int nt = 0; nt < 4; nt++) {
            int n = nb + nt * 8;
            bfh[nt][0] = pckbf(Xhi[k0][n],     Xhi[k0 + 1][n]);
            bfh[nt][1] = pckbf(Xhi[k0 + 8][n], Xhi[k0 + 9][n]);
            bfl[nt][0] = pckbf(Xlo[k0][n],     Xlo[k0 + 1][n]);
            bfl[nt][1] = pckbf(Xlo[k0 + 8][n], Xlo[k0 + 9][n]);
        }
        #pragma unroll
        for (int s = 0; s < 3; s++) {
            const __nv_bfloat16 (*Wa)[24] = (s == 2) ? Wlo : Whi;
            const unsigned (*bf)[2] = (s == 1) ? bfl : bfh;
            #pragma unroll
            for (int m = 0; m < 4; m++) {
                int r = wm * 64 + m * 16 + (lane >> 2);
                unsigned a0 = *(const unsigned*)&Wa[r][k0];
                unsigned a1 = *(const unsigned*)&Wa[r + 8][k0];
                unsigned a2 = *(const unsigned*)&Wa[r][k0 + 8];
                unsigned a3 = *(const unsigned*)&Wa[r + 8][k0 + 8];
                #pragma unroll
                for (int nt = 0; nt < 4; nt++)
                    asm volatile(
                        "mma.sync.aligned.m16n8k16.row.col.f32.bf16.bf16.f32 "
                        "{%0,%1,%2,%3}, {%4,%5,%6,%7}, {%8,%9}, {%0,%1,%2,%3};"
                        : "+f"(acc[m][nt][0]), "+f"(acc[m][nt][1]),
                          "+f"(acc[m][nt][2]), "+f"(acc[m][nt][3])
                        : "r"(a0), "r"(a1), "r"(a2), "r"(a3),
                          "r"(bf[nt][0]), "r"(bf[nt][1]));
            }
        }
        __syncthreads();
    }

    #pragma unroll
    for (int m = 0; m < 4; m++) {
        int o = o0 + wm * 64 + m * 16 + (lane >> 2);
        float bo0 = bias[o], bo8 = bias[o + 8];
        #pragma unroll
        for (int nt = 0; nt < 4; nt++) {
            int lc = l0 + wn * 32 + nt * 8 + (lane & 3) * 2;
            size_t base0 = ((size_t)b * Hh + o) * Ll + lc;
            size_t base8 = base0 + 8 * (size_t)Ll;
            float v0 = acc[m][nt][0] + bo0;
            float v1 = acc[m][nt][1] + bo0;
            float v2 = acc[m][nt][2] + bo8;
            float v3 = acc[m][nt][3] + bo8;
            if (addres) {
                float2 r0 = *(const float2*)&resid[base0];
                float2 r8 = *(const float2*)&resid[base8];
                v0 += r0.x; v1 += r0.y; v2 += r8.x; v3 += r8.y;
            }
            *(float2*)&out[base0] = make_float2(v0, v1);
            *(float2*)&out[base8] = make_float2(v2, v3);
        }
    }
}

// ---------------- launch ----------------
extern "C" void kernel_launch(void* const* d_in, const int* in_sizes, int n_in,
                              void* d_out, int out_size) {
    const float* x      = (const float*)d_in[0];
    const int*   t      = (const int*)  d_in[1];
    const float* ada_w  = (const float*)d_in[2];
    const float* ada_b  = (const float*)d_in[3];
    const float* norm_w = (const float*)d_in[4];
    const float* norm_b = (const float*)d_in[5];
    const float* log_dt = (const float*)d_in[6];
    const float* A_re   = (const float*)d_in[7];
    const float* A_im   = (const float*)d_in[8];
    const float* C_re   = (const float*)d_in[9];
    const float* C_im   = (const float*)d_in[10];
    const float* Dp     = (const float*)d_in[11];
    const float* out_w  = (const float*)d_in[12];
    const float* out_b  = (const float*)d_in[13];
    const float* lin1_w = (const float*)d_in[14];
    const float* lin1_b = (const float*)d_in[15];
    const float* lin2_w = (const float*)d_in[16];
    const float* lin2_b = (const float*)d_in[17];
    float* out = (float*)d_out;
    (void)in_sizes; (void)n_in; (void)out_size;

    float *p_x1, *p_z;
    unsigned *p_yg;
    cudaGetSymbolAddress((void**)&p_x1, g_x1);
    cudaGetSymbolAddress((void**)&p_z,  g_z);
    cudaGetSymbolAddress((void**)&p_yg, g_yg);

    k_twfill<<<4, 256>>>();
    k_semb<<<64, 256>>>(t);
    k_ssm<<<256, 256>>>(log_dt, A_re, A_im, C_re, C_im);
    k_kfft<<<128, 256>>>();
    k_wprep<<<768, 256>>>(out_w, lin1_w, lin2_w);
    k_ada_gemm<<<dim3(64, 8), 256>>>(ada_w);
    k_ada_reduce<<<512, 256>>>(ada_b);
    k_adaln<<<Bb * Hh, 256>>>(x);
    k_chanln<<<dim3(64, 32), 256>>>(norm_w, norm_b);
    k_conv<<<dim3(256, 32), 256>>>(Dp);
    k_gemm1<<<dim3(8, 2, 64), 256>>>(out_b, p_yg, p_x1, (unsigned*)p_z);
    k_gemm2<<<dim3(8, 2, 64), 256>>>(1, lin1_b, (unsigned*)p_z, p_x1, out, 1);
    k_gemm2<<<dim3(8, 2, 64), 256>>>(2, lin2_b, (unsigned*)p_z, p_x1, out + BHL, 0);
}

// round 12
// speedup vs baseline: 1.3856x; 1.1862x over previous
#include <cuda_runtime.h>
#include <cuda_fp16.h>
#include <math.h>

#define Bb 64
#define Hh 256
#define Ll 1024
#define Nn 64
#define BHL (Bb*Hh*Ll)

// ---------------- scratch (device globals; no allocs allowed) ----------------
__device__ float g_x1[BHL];        // post-AdaLN x (residual source)
__device__ float g_z[BHL];         // z (pre-norm out); low half reused as fp16 gate g
__device__ __half g_yg[BHL];       // gelu(conv out + D*z), fp16
__device__ float g_ss[Bb*2048];    // scale(0:1024) / shift(1024:2048) per batch
__device__ float g_semb[Bb*1024];  // silu(sin/cos emb)
__device__ float g_ktime[Hh*2048]; // time-domain bidirectional kernel
__device__ float g_khr[Hh*2048];   // full complex spectrum of k (re)
__device__ float g_khi[Hh*2048];   // (im)
__device__ float g_part[8*Bb*2048];// ada split-K partials
__device__ float2 g_tw[1024];      // FFT twiddles exp(-i*pi*k/1024)
__device__ __half g_wh[3*Hh*Hh];   // fp16 weights (out_w, lin1_w, lin2_w)

// ---------------- helpers ----------------
__device__ __forceinline__ float geluf(float x) {
    return 0.5f * x * (1.0f + erff(x * 0.70710678118654752440f));
}
__device__ __forceinline__ float gatef(float x) {
    float t  = __expf(-fmaxf(x, -30.0f));
    float t2 = t * t;
    return ((1.0f - t2) / (1.0f + t2)) * (1.0f / (1.0f + t));
}
__device__ __forceinline__ unsigned pckh(__half a, __half b) {
    __half2 t; t.x = a; t.y = b;
    return *reinterpret_cast<unsigned*>(&t);
}

// ---------------- weight fp16 prep ----------------
__global__ void k_wprep(const float* __restrict__ w0,
                        const float* __restrict__ w1,
                        const float* __restrict__ w2) {
    int i = blockIdx.x * 256 + threadIdx.x;      // 0 .. 3*65536-1
    int m = i >> 16, r = i & 65535;
    float v = (m == 0) ? w0[r] : (m == 1) ? w1[r] : w2[r];
    g_wh[i] = __float2half_rn(v);
}

// ---------------- twiddle table ----------------
__global__ void k_twfill() {
    int i = blockIdx.x * 256 + threadIdx.x;
    float ang = -3.14159265358979323846f * (float)i * (1.0f / 1024.0f);
    float sn, cs; sincosf(ang, &sn, &cs);
    g_tw[i] = make_float2(cs, sn);
}

// ---------------- sinusoidal embedding + silu ----------------
__global__ void __launch_bounds__(256) k_semb(const int* __restrict__ t) {
    int b = blockIdx.x;
    float tf = (float)t[b];
    const float cfr = (float)(-9.210340371976184 / 511.0);
    #pragma unroll
    for (int r = 0; r < 4; r++) {
        int i = threadIdx.x + (r << 8);
        float v;
        if (i < 512) v = sinf(tf * expf((float)i * cfr));
        else         v = cosf(tf * expf((float)(i - 512) * cfr));
        float sg = 1.0f / (1.0f + expf(-v));
        g_semb[b * 1024 + i] = v * sg;
    }
}

// ---------------- emb @ ada_w.T  (split-K partials) ----------------
__global__ void __launch_bounds__(256) k_ada_gemm(const float* __restrict__ W) {
    __shared__ float Ws[64][32];
    __shared__ float Eb[64][64];
    int o0 = blockIdx.x * 32;
    int kc = blockIdx.y;
    int tid = threadIdx.x;
    int o  = tid & 31;
    int bg = tid >> 5;
    float acc[8];
    #pragma unroll
    for (int j = 0; j < 8; j++) acc[j] = 0.f;

    for (int kk = kc * 128; kk < kc * 128 + 128; kk += 64) {
        {
            int oo = tid >> 3;
            int kq = tid & 7;
            const float* src = &W[(size_t)(o0 + oo) * 1024 + kk + kq * 8];
            float4 a = *(const float4*)(src);
            float4 c = *(const float4*)(src + 4);
            int kb = kq * 8;
            Ws[kb+0][oo] = a.x; Ws[kb+1][oo] = a.y; Ws[kb+2][oo] = a.z; Ws[kb+3][oo] = a.w;
            Ws[kb+4][oo] = c.x; Ws[kb+5][oo] = c.y; Ws[kb+6][oo] = c.z; Ws[kb+7][oo] = c.w;
        }
        #pragma unroll
        for (int r = 0; r < 16; r++) {
            int e = tid + (r << 8);
            int bq = e >> 6, k = e & 63;
            Eb[bq][k] = g_semb[bq * 1024 + kk + k];
        }
        __syncthreads();
        #pragma unroll 8
        for (int k = 0; k < 64; k++) {
            float wv = Ws[k][o];
            #pragma unroll
            for (int j = 0; j < 8; j++)
                acc[j] += Eb[bg * 8 + j][k] * wv;
        }
        __syncthreads();
    }
    #pragma unroll
    for (int j = 0; j < 8; j++)
        g_part[((size_t)kc * 64 + bg * 8 + j) * 2048 + o0 + o] = acc[j];
}

__global__ void __launch_bounds__(256) k_ada_reduce(const float* __restrict__ bias) {
    int idx = blockIdx.x * 256 + threadIdx.x;
    int b = idx >> 11, o = idx & 2047;
    float s = bias[o];
    #pragma unroll
    for (int kc = 0; kc < 8; kc++)
        s += g_part[((size_t)kc * 64 + b) * 2048 + o];
    g_ss[b * 2048 + o] = s;
}

// ---------------- AdaLayerNorm over L ----------------
__global__ void __launch_bounds__(256) k_adaln(const float* __restrict__ x) {
    int bh = blockIdx.x;
    int b = bh >> 8;
    int tid = threadIdx.x;
    const float4* xr = (const float4*)(x + (size_t)bh * 1024);
    float4 v = xr[tid];
    float s = v.x + v.y + v.z + v.w;
    float q = v.x*v.x + v.y*v.y + v.z*v.z + v.w*v.w;
    #pragma unroll
    for (int o = 16; o; o >>= 1) {
        s += __shfl_down_sync(0xffffffffu, s, o);
        q += __shfl_down_sync(0xffffffffu, q, o);
    }
    __shared__ float as_[8], aq_[8];
    if ((tid & 31) == 0) { as_[tid >> 5] = s; aq_[tid >> 5] = q; }
    __syncthreads();
    float S = 0.f, Q = 0.f;
    #pragma unroll
    for (int i = 0; i < 8; i++) { S += as_[i]; Q += aq_[i]; }
    float m  = S * (1.0f / 1024.0f);
    float va = Q * (1.0f / 1024.0f) - m * m;
    float rs = rsqrtf(va + 1e-5f);
    const float4* sc = (const float4*)(g_ss + b * 2048);
    const float4* sh = (const float4*)(g_ss + b * 2048 + 1024);
    float4 a = sc[tid], d = sh[tid];
    float4 o4;
    o4.x = (v.x - m) * rs * (1.0f + a.x) + d.x;
    o4.y = (v.y - m) * rs * (1.0f + a.y) + d.y;
    o4.z = (v.z - m) * rs * (1.0f + a.z) + d.z;
    o4.w = (v.w - m) * rs * (1.0f + a.w) + d.w;
    ((float4*)(g_x1 + (size_t)bh * 1024))[tid] = o4;
}

// ---------------- channel LayerNorm over H ----------------
__global__ void __launch_bounds__(256) k_chanln(const float* __restrict__ nw,
                                                const float* __restrict__ nb) {
    int b = blockIdx.x;
    int l0 = blockIdx.y * 32;
    int tid = threadIdx.x;
    int lx = tid & 31, hp = tid >> 5;
    float v[32];
    float s = 0.f, q = 0.f;
    const float* base = g_x1 + ((size_t)b * Hh) * Ll + l0 + lx;
    #pragma unroll 8
    for (int k = 0; k < 32; k++) {
        float xv = base[(size_t)(hp * 32 + k) * Ll];
        v[k] = xv; s += xv; q += xv * xv;
    }
    __shared__ float ps[8][32], pq[8][32];
    __shared__ float mean_[32], rstd_[32];
    ps[hp][lx] = s; pq[hp][lx] = q;
    __syncthreads();
    if (tid < 32) {
        float S = 0.f, Q = 0.f;
        #pragma unroll
        for (int p = 0; p < 8; p++) { S += ps[p][tid]; Q += pq[p][tid]; }
        float m  = S * (1.0f / 256.0f);
        float va = Q * (1.0f / 256.0f) - m * m;
        mean_[tid] = m; rstd_[tid] = rsqrtf(va + 1e-5f);
    }
    __syncthreads();
    float m = mean_[lx], r = rstd_[lx];
    float* zb = g_z + ((size_t)b * Hh) * Ll + l0 + lx;
    #pragma unroll 8
    for (int k = 0; k < 32; k++) {
        int h = hp * 32 + k;
        zb[(size_t)h * Ll] = (v[k] - m) * r * nw[h] + nb[h];
    }
}

// ---------------- SSM kernel ----------------
__global__ void __launch_bounds__(256) k_ssm(const float* __restrict__ log_dt,
                                             const float* __restrict__ A_re,
                                             const float* __restrict__ A_im,
                                             const float* __restrict__ C_re,
                                             const float* __restrict__ C_im) {
    __shared__ float pre[6][64];
    int h = blockIdx.x, tid = threadIdx.x;
    if (tid < 64) {
        int n = tid;
        float dt  = expf(log_dt[h]);
        float are = -expf(A_re[h * 64 + n]);
        float aim = A_im[h * 64 + n];
        float dre = dt * are, dim = dt * aim;
        float er = expf(dre);
        float sn, cs; sincosf(dim, &sn, &cs);
        float dAr = er * cs, dAi = er * sn;
        float numr = dAr - 1.0f, numi = dAi;
        float den = are * are + aim * aim;
        float fr = (numr * are + numi * aim) / den;
        float fi = (numi * are - numr * aim) / den;
        float c0re = C_re[h * 64 + n],             c0im = C_im[h * 64 + n];
        float c1re = C_re[Hh * 64 + h * 64 + n],   c1im = C_im[Hh * 64 + h * 64 + n];
        pre[0][n] = dre; pre[1][n] = dim;
        pre[2][n] = c0re * fr - c0im * fi; pre[3][n] = c0re * fi + c0im * fr;
        pre[4][n] = c1re * fr - c1im * fi; pre[5][n] = c1re * fi + c1im * fr;
    }
    __syncthreads();
    #pragma unroll
    for (int qq = 0; qq < 4; qq++) {
        int l = tid + (qq << 8);
        float lf = (float)l;
        float k0 = 0.f, k1 = 0.f;
        #pragma unroll 4
        for (int n = 0; n < 64; n++) {
            float pr = pre[0][n] * lf, pi = pre[1][n] * lf;
            float e = expf(pr);
            float sn, cs; sincosf(pi, &sn, &cs);
            float vr = e * cs, vi = e * sn;
            k0 += pre[2][n] * vr - pre[3][n] * vi;
            k1 += pre[4][n] * vr - pre[5][n] * vi;
        }
        g_ktime[h * 2048 + l]        = 2.0f * k0;
        g_ktime[h * 2048 + 2047 - l] = 2.0f * k1;
    }
}

// ---------------- generic radix-8 Stockham stage (256 threads, N=2048) ----------------
__device__ __forceinline__ void r8_stage(const float* __restrict__ sr,
                                         const float* __restrict__ si,
                                         float* __restrict__ dr,
                                         float* __restrict__ di, int lm) {
    const float Cq = 0.70710678118654752440f;
    const int m = 1 << lm;
    int i = threadIdx.x;
    int p = i >> lm;
    int r = i & (m - 1);
    float xr[8], xi[8];
    #pragma unroll
    for (int s = 0; s < 8; s++) { xr[s] = sr[i + (s << 8)]; xi[s] = si[i + (s << 8)]; }
    float pr_[4], pi_[4], qr[4], qi[4];
    #pragma unroll
    for (int s = 0; s < 4; s++) {
        pr_[s] = xr[s] + xr[s+4]; pi_[s] = xi[s] + xi[s+4];
        qr[s]  = xr[s] - xr[s+4]; qi[s]  = xi[s] - xi[s+4];
    }
    { float a=qr[1], b=qi[1]; qr[1] = Cq*(a+b); qi[1] = Cq*(b-a); }
    { float a=qr[2], b=qi[2]; qr[2] = b;        qi[2] = -a;       }
    { float a=qr[3], b=qi[3]; qr[3] = Cq*(b-a); qi[3] = -Cq*(a+b); }
    float Xr[8], Xi[8];
    {
        float r0r=pr_[0]+pr_[2], r0i=pi_[0]+pi_[2];
        float r1r=pr_[0]-pr_[2], r1i=pi_[0]-pi_[2];
        float r2r=pr_[1]+pr_[3], r2i=pi_[1]+pi_[3];
        float t3r=pr_[1]-pr_[3], t3i=pi_[1]-pi_[3];
        float r3r=t3i, r3i=-t3r;
        Xr[0]=r0r+r2r; Xi[0]=r0i+r2i;
        Xr[2]=r1r+r3r; Xi[2]=r1i+r3i;
        Xr[4]=r0r-r2r; Xi[4]=r0i-r2i;
        Xr[6]=r1r-r3r; Xi[6]=r1i-r3i;
    }
    {
        float r0r=qr[0]+qr[2], r0i=qi[0]+qi[2];
        float r1r=qr[0]-qr[2], r1i=qi[0]-qi[2];
        float r2r=qr[1]+qr[3], r2i=qi[1]+qi[3];
        float t3r=qr[1]-qr[3], t3i=qi[1]-qi[3];
        float r3r=t3i, r3i=-t3r;
        Xr[1]=r0r+r2r; Xi[1]=r0i+r2i;
        Xr[3]=r1r+r3r; Xi[3]=r1i+r3i;
        Xr[5]=r0r-r2r; Xi[5]=r0i-r2i;
        Xr[7]=r1r-r3r; Xi[7]=r1i-r3i;
    }
    float2 w = g_tw[m * p];
    float wjr = 1.f, wji = 0.f;
    int o = ((m * p) << 3) + r;
    dr[o] = Xr[0]; di[o] = Xi[0];
    #pragma unroll
    for (int j = 1; j < 8; j++) {
        float nr = wjr * w.x - wji * w.y;
        wji = wji * w.x + wjr * w.y;
        wjr = nr;
        dr[o + j * m] = Xr[j] * wjr - Xi[j] * wji;
        di[o + j * m] = Xi[j] * wjr + Xr[j] * wji;
    }
}

// ---------------- full radix-8 FFT (generic; used by kfft) ----------------
__device__ __forceinline__ void fft2048_r8(float*& sr, float*& si, float*& dr, float*& di) {
    #pragma unroll
    for (int lm = 0; lm < 9; lm += 3) {
        r8_stage(sr, si, dr, di, lm);
        __syncthreads();
        float* tp; tp=sr;sr=dr;dr=tp; tp=si;si=di;di=tp;
    }
    #pragma unroll
    for (int q = 0; q < 2; q++) {
        int r = threadIdx.x + (q << 8);
        float a0r=sr[r],      a0i=si[r];
        float a1r=sr[r+512],  a1i=si[r+512];
        float a2r=sr[r+1024], a2i=si[r+1024];
        float a3r=sr[r+1536], a3i=si[r+1536];
        float r0r=a0r+a2r, r0i=a0i+a2i;
        float r1r=a0r-a2r, r1i=a0i-a2i;
        float r2r=a1r+a3r, r2i=a1i+a3i;
        float t3r=a1r-a3r, t3i=a1i-a3i;
        float r3r=t3i, r3i=-t3r;
        dr[r]      = r0r+r2r; di[r]      = r0i+r2i;
        dr[r+512]  = r1r+r3r; di[r+512]  = r1i+r3i;
        dr[r+1024] = r0r-r2r; di[r+1024] = r0i-r2i;
        dr[r+1536] = r1r-r3r; di[r+1536] = r1i-r3i;
    }
    __syncthreads();
    float* tp; tp=sr;sr=dr;dr=tp; tp=si;si=di;di=tp;
}

// ---------------- FFT of kernel rows ----------------
__global__ void __launch_bounds__(256) k_kfft() {
    __shared__ float bAr[2048], bAi[2048], bBr[2048], bBi[2048];
    int tid = threadIdx.x;
    int h0 = blockIdx.x * 2, h1 = h0 + 1;
    #pragma unroll
    for (int qq = 0; qq < 8; qq++) {
        int idx = tid + (qq << 8);
        bAr[idx] = g_ktime[h0 * 2048 + idx];
        bAi[idx] = g_ktime[h1 * 2048 + idx];
    }
    __syncthreads();
    float *sr = bAr, *si = bAi, *dr = bBr, *di = bBi;
    fft2048_r8(sr, si, dr, di);
    #pragma unroll
    for (int qq = 0; qq < 8; qq++) {
        int f = tid + (qq << 8);
        int fr2 = (2048 - f) & 2047;
        float ur = sr[f],  ui = si[f];
        float vr = sr[fr2], vi = -si[fr2];
        g_khr[h0 * 2048 + f] = 0.5f * (ur + vr);
        g_khi[h0 * 2048 + f] = 0.5f * (ui + vi);
        g_khr[h1 * 2048 + f] = 0.5f * (ui - vi);
        g_khi[h1 * 2048 + f] = -0.5f * (ur - vr);
    }
}

// ---------------- main conv: fused pointwise + fused epilogue, fp16 output ----------------
__global__ void __launch_bounds__(256) k_conv(const float* __restrict__ Dp) {
    __shared__ float bAr[2048], bAi[2048], bBr[2048], bBi[2048];
    const float Cq = 0.70710678118654752440f;
    int tid = threadIdx.x;
    int h  = blockIdx.x;
    int pb = blockIdx.y;
    const float* za = g_z + ((size_t)(2 * pb) * Hh + h) * Ll;
    const float* zb = za + (size_t)Hh * Ll;
    float ra[4], rb[4];
    #pragma unroll
    for (int qq = 0; qq < 4; qq++) {
        int idx = tid + (qq << 8);
        ra[qq] = za[idx]; rb[qq] = zb[idx];
        bAr[idx] = ra[qq]; bAi[idx] = rb[qq];
    }
    __syncthreads();

    // ---- forward stage 1 (m=1): inputs s>=4 are the zero pad ----
    {
        float xr[4], xi[4];
        #pragma unroll
        for (int s = 0; s < 4; s++) { xr[s] = bAr[tid + (s << 8)]; xi[s] = bAi[tid + (s << 8)]; }
        float qr[4], qi[4];
        #pragma unroll
        for (int s = 0; s < 4; s++) { qr[s] = xr[s]; qi[s] = xi[s]; }
        { float a=qr[1], b=qi[1]; qr[1] = Cq*(a+b); qi[1] = Cq*(b-a); }
        { float a=qr[2], b=qi[2]; qr[2] = b;        qi[2] = -a;       }
        { float a=qr[3], b=qi[3]; qr[3] = Cq*(b-a); qi[3] = -Cq*(a+b); }
        float Xr[8], Xi[8];
        {
            float r0r=xr[0]+xr[2], r0i=xi[0]+xi[2];
            float r1r=xr[0]-xr[2], r1i=xi[0]-xi[2];
            float r2r=xr[1]+xr[3], r2i=xi[1]+xi[3];
            float t3r=xr[1]-xr[3], t3i=xi[1]-xi[3];
            float r3r=t3i, r3i=-t3r;
            Xr[0]=r0r+r2r; Xi[0]=r0i+r2i;
            Xr[2]=r1r+r3r; Xi[2]=r1i+r3i;
            Xr[4]=r0r-r2r; Xi[4]=r0i-r2i;
            Xr[6]=r1r-r3r; Xi[6]=r1i-r3i;
        }
        {
            float r0r=qr[0]+qr[2], r0i=qi[0]+qi[2];
            float r1r=qr[0]-qr[2], r1i=qi[0]-qi[2];
            float r2r=qr[1]+qr[3], r2i=qi[1]+qi[3];
            float t3r=qr[1]-qr[3], t3i=qi[1]-qi[3];
            float r3r=t3i, r3i=-t3r;
            Xr[1]=r0r+r2r; Xi[1]=r0i+r2i;
            Xr[3]=r1r+r3r; Xi[3]=r1i+r3i;
            Xr[5]=r0r-r2r; Xi[5]=r0i-r2i;
            Xr[7]=r1r-r3r; Xi[7]=r1i-r3i;
        }
        float2 w = g_tw[tid];
        float wjr = 1.f, wji = 0.f;
        int o = tid << 3;
        bBr[o] = Xr[0]; bBi[o] = Xi[0];
        #pragma unroll
        for (int j = 1; j < 8; j++) {
            float nr = wjr * w.x - wji * w.y;
            wji = wji * w.x + wjr * w.y;
            wjr = nr;
            bBr[o + j] = Xr[j] * wjr - Xi[j] * wji;
            bBi[o + j] = Xi[j] * wjr + Xr[j] * wji;
        }
    }
    __syncthreads();
    r8_stage(bBr, bBi, bAr, bAi, 3); __syncthreads();
    r8_stage(bAr, bAi, bBr, bBi, 6); __syncthreads();

    // ---- forward final r4 fused with spectrum multiply (+conj, +1/N) -> bA ----
    {
        const float* khr = g_khr + h * 2048;
        const float* khi = g_khi + h * 2048;
        const float inv = 1.0f / 2048.0f;
        #pragma unroll
        for (int q = 0; q < 2; q++) {
            int r = tid + (q << 8);
            float a0r=bBr[r],      a0i=bBi[r];
            float a1r=bBr[r+512],  a1i=bBi[r+512];
            float a2r=bBr[r+1024], a2i=bBi[r+1024];
            float a3r=bBr[r+1536], a3i=bBi[r+1536];
            float r0r=a0r+a2r, r0i=a0i+a2i;
            float r1r=a0r-a2r, r1i=a0i-a2i;
            float r2r=a1r+a3r, r2i=a1i+a3i;
            float t3r=a1r-a3r, t3i=a1i-a3i;
            float r3r=t3i, r3i=-t3r;
            float Xr4[4], Xi4[4];
            Xr4[0]=r0r+r2r; Xi4[0]=r0i+r2i;
            Xr4[1]=r1r+r3r; Xi4[1]=r1i+r3i;
            Xr4[2]=r0r-r2r; Xi4[2]=r0i-r2i;
            Xr4[3]=r1r-r3r; Xi4[3]=r1i-r3i;
            #pragma unroll
            for (int j = 0; j < 4; j++) {
                int f = r + j * 512;
                float kr = khr[f], ki = khi[f];
                float ar = Xr4[j], ai = Xi4[j];
                bAr[f] = (ar * kr - ai * ki) * inv;
                bAi[f] = -(ar * ki + ai * kr) * inv;
            }
        }
    }
    __syncthreads();

    // ---- inverse FFT ----
    r8_stage(bAr, bAi, bBr, bBi, 0); __syncthreads();
    r8_stage(bBr, bBi, bAr, bAi, 3); __syncthreads();
    r8_stage(bAr, bAi, bBr, bBi, 6); __syncthreads();

    // ---- inverse final r4 (outputs [0,1024) only) fused with epilogue, fp16 store ----
    float Dh = Dp[h];
    __half* ya = g_yg + ((size_t)(2 * pb) * Hh + h) * Ll;
    __half* yb = ya + (size_t)Hh * Ll;
    #pragma unroll
    for (int q = 0; q < 2; q++) {
        int r = tid + (q << 8);
        float a0r=bBr[r],      a0i=bBi[r];
        float a1r=bBr[r+512],  a1i=bBi[r+512];
        float a2r=bBr[r+1024], a2i=bBi[r+1024];
        float a3r=bBr[r+1536], a3i=bBi[r+1536];
        float r0r=a0r+a2r, r0i=a0i+a2i;
        float r1r=a0r-a2r, r1i=a0i-a2i;
        float r2r=a1r+a3r, r2i=a1i+a3i;
        float t3r=a1r-a3r, t3i=a1i-a3i;
        float r3r=t3i, r3i=-t3r;
        float o1r = r0r + r2r, o1i = r0i + r2i;
        float o2r = r1r + r3r, o2i = r1i + r3i;
        float v1 = o1r  + Dh * ra[q];
        float v2 = -o1i + Dh * rb[q];
        float v3 = o2r  + Dh * ra[q + 2];
        float v4 = -o2i + Dh * rb[q + 2];
        ya[r]       = __float2half_rn(geluf(v1));
        yb[r]       = __float2half_rn(geluf(v2));
        ya[r + 512] = __float2half_rn(geluf(v3));
        yb[r + 512] = __float2half_rn(geluf(v4));
    }
}

// ---------------- GEMM1: g = gate(out_w@yg + out_b + x1), fp16 output ----------------
__global__ void __launch_bounds__(256) k_gemm1(const float* __restrict__ bias,
                                               const __half* __restrict__ X,
                                               const float* __restrict__ resid,
                                               __half* __restrict__ Yout) {
    __shared__ __half Ws[128][24];
    __shared__ __half Xs[16][136];
    int l0 = blockIdx.x * 128;
    int o0 = blockIdx.y * 128;
    int b  = blockIdx.z;
    int tid = threadIdx.x;
    int lane = tid & 31, warp = tid >> 5;
    int wm = warp & 1, wn = warp >> 1;

    float acc[4][4][4];
    #pragma unroll
    for (int m = 0; m < 4; m++)
        #pragma unroll
        for (int n = 0; n < 4; n++)
            #pragma unroll
            for (int c = 0; c < 4; c++) acc[m][n][c] = 0.f;

    int wo = tid >> 1, wk = (tid & 1) * 8;
    const __half* whp = &g_wh[(size_t)(o0 + wo) * 256 + wk];
    int xk = tid >> 4, xl = (tid & 15) * 8;
    const __half* xpb = &X[((size_t)b * Hh + xk) * Ll + l0 + xl];

    uint4 wv = *(const uint4*)(whp);
    uint4 xv = *(const uint4*)(xpb);

    #pragma unroll 1
    for (int it = 0; it < 16; it++) {
        *(uint4*)&Ws[wo][wk] = wv;
        *(uint4*)&Xs[xk][xl] = xv;
        __syncthreads();
        if (it < 15) {
            int kk = (it + 1) * 16;
            wv = *(const uint4*)(whp + kk);
            xv = *(const uint4*)(xpb + (size_t)kk * Ll);
        }
        int k0 = (lane & 3) * 2;
        int nb = wn * 32 + (lane >> 2);
        unsigned bf[4][2];
        #pragma unroll
        for (int nt = 0; nt < 4; nt++) {
            int n = nb + nt * 8;
            bf[nt][0] = pckh(Xs[k0][n],     Xs[k0 + 1][n]);
            bf[nt][1] = pckh(Xs[k0 + 8][n], Xs[k0 + 9][n]);
        }
        #pragma unroll
        for (int m = 0; m < 4; m++) {
            int r = wm * 64 + m * 16 + (lane >> 2);
            unsigned a0 = *(const unsigned*)&Ws[r][k0];
            unsigned a1 = *(const unsigned*)&Ws[r + 8][k0];
            unsigned a2 = *(const unsigned*)&Ws[r][k0 + 8];
            unsigned a3 = *(const unsigned*)&Ws[r + 8][k0 + 8];
            #pragma unroll
            for (int nt = 0; nt < 4; nt++)
                asm volatile(
                    "mma.sync.aligned.m16n8k16.row.col.f32.f16.f16.f32 "
                    "{%0,%1,%2,%3}, {%4,%5,%6,%7}, {%8,%9}, {%0,%1,%2,%3};"
                    : "+f"(acc[m][nt][0]), "+f"(acc[m][nt][1]),
                      "+f"(acc[m][nt][2]), "+f"(acc[m][nt][3])
                    : "r"(a0), "r"(a1), "r"(a2), "r"(a3),
                      "r"(bf[nt][0]), "r"(bf[nt][1]));
        }
        __syncthreads();
    }

    #pragma unroll
    for (int m = 0; m < 4; m++) {
        int o = o0 + wm * 64 + m * 16 + (lane >> 2);
        float bo0 = bias[o], bo8 = bias[o + 8];
        #pragma unroll
        for (int nt = 0; nt < 4; nt++) {
            int lc = l0 + wn * 32 + nt * 8 + (lane & 3) * 2;
            size_t base0 = ((size_t)b * Hh + o) * Ll + lc;
            size_t base8 = base0 + 8 * (size_t)Ll;
            float2 r0 = *(const float2*)&resid[base0];
            float2 r8 = *(const float2*)&resid[base8];
            __half q0 = __float2half_rn(gatef(acc[m][nt][0] + bo0 + r0.x));
            __half q1 = __float2half_rn(gatef(acc[m][nt][1] + bo0 + r0.y));
            __half q2 = __float2half_rn(gatef(acc[m][nt][2] + bo8 + r8.x));
            __half q3 = __float2half_rn(gatef(acc[m][nt][3] + bo8 + r8.y));
            *(unsigned*)&Yout[base0] = pckh(q0, q1);
            *(unsigned*)&Yout[base8] = pckh(q2, q3);
        }
    }
}

// ---------------- GEMM2/3: out = lin@g + b (+x1 if addres) ----------------
__global__ void __launch_bounds__(256) k_gemm2(int widx,
                                               const float* __restrict__ bias,
                                               const __half* __restrict__ X,
                                               const float* __restrict__ resid,
                                               float* __restrict__ out,
                                               int addres) {
    __shared__ __half Ws[128][24];
    __shared__ __half Xs[16][136];
    int l0 = blockIdx.x * 128;
    int o0 = blockIdx.y * 128;
    int b  = blockIdx.z;
    int tid = threadIdx.x;
    int lane = tid & 31, warp = tid >> 5;
    int wm = warp & 1, wn = warp >> 1;

    float acc[4][4][4];
    #pragma unroll
    for (int m = 0; m < 4; m++)
        #pragma unroll
        for (int n = 0; n < 4; n++)
            #pragma unroll
            for (int c = 0; c < 4; c++) acc[m][n][c] = 0.f;

    int wo = tid >> 1, wk = (tid & 1) * 8;
    const __half* whp = &g_wh[(size_t)widx * Hh * Hh + (size_t)(o0 + wo) * 256 + wk];
    int xk = tid >> 4, xl = (tid & 15) * 8;
    const __half* xpb = &X[((size_t)b * Hh + xk) * Ll + l0 + xl];

    uint4 wv = *(const uint4*)(whp);
    uint4 xv = *(const uint4*)(xpb);

    #pragma unroll 1
    for (int it = 0; it < 16; it++) {
        *(uint4*)&Ws[wo][wk] = wv;
        *(uint4*)&Xs[xk][xl] = xv;
        __syncthreads();
        if (it < 15) {
            int kk = (it + 1) * 16;
            wv = *(const uint4*)(whp + kk);
            xv = *(const uint4*)(xpb + (size_t)kk * Ll);
        }
        int k0 = (lane & 3) * 2;
        int nb = wn * 32 + (lane >> 2);
        unsigned bf[4][2];
        #pragma unroll
        for (int nt = 0; nt < 4; nt++) {
            int n = nb + nt * 8;
            bf[nt][0] = pckh(Xs[k0][n],     Xs[k0 + 1][n]);
            bf[nt][1] = pckh(Xs[k0 + 8][n], Xs[k0 + 9][n]);
        }
        #pragma unroll
        for (int m = 0; m < 4; m++) {
            int r = wm * 64 + m * 16 + (lane >> 2);
            unsigned a0 = *(const unsigned*)&Ws[r][k0];
            unsigned a1 = *(const unsigned*)&Ws[r + 8][k0];
            unsigned a2 = *(const unsigned*)&Ws[r][k0 + 8];
            unsigned a3 = *(const unsigned*)&Ws[r + 8][k0 + 8];
            #pragma unroll
            for (int nt = 0; nt < 4; nt++)
                asm volatile(
                    "mma.sync.aligned.m16n8k16.row.col.f32.f16.f16.f32 "
                    "{%0,%1,%2,%3}, {%4,%5,%6,%7}, {%8,%9}, {%0,%1,%2,%3};"
                    : "+f"(acc[m][nt][0]), "+f"(acc[m][nt][1]),
                      "+f"(acc[m][nt][2]), "+f"(acc[m][nt][3])
                    : "r"(a0), "r"(a1), "r"(a2), "r"(a3),
                      "r"(bf[nt][0]), "r"(bf[nt][1]));
        }
        __syncthreads();
    }

    #pragma unroll
    for (int m = 0; m < 4; m++) {
        int o = o0 + wm * 64 + m * 16 + (lane >> 2);
        float bo0 = bias[o], bo8 = bias[o + 8];
        #pragma unroll
        for (int nt = 0; nt < 4; nt++) {
            int lc = l0 + wn * 32 + nt * 8 + (lane & 3) * 2;
            size_t base0 = ((size_t)b * Hh + o) * Ll + lc;
            size_t base8 = base0 + 8 * (size_t)Ll;
            float v0 = acc[m][nt][0] + bo0;
            float v1 = acc[m][nt][1] + bo0;
            float v2 = acc[m][nt][2] + bo8;
            float v3 = acc[m][nt][3] + bo8;
            if (addres) {
                float2 r0 = *(const float2*)&resid[base0];
                float2 r8 = *(const float2*)&resid[base8];
                v0 += r0.x; v1 += r0.y; v2 += r8.x; v3 += r8.y;
            }
            *(float2*)&out[base0] = make_float2(v0, v1);
            *(float2*)&out[base8] = make_float2(v2, v3);
        }
    }
}

// ---------------- launch ----------------
extern "C" void kernel_launch(void* const* d_in, const int* in_sizes, int n_in,
                              void* d_out, int out_size) {
    const float* x      = (const float*)d_in[0];
    const int*   t      = (const int*)  d_in[1];
    const float* ada_w  = (const float*)d_in[2];
    const float* ada_b  = (const float*)d_in[3];
    const float* norm_w = (const float*)d_in[4];
    const float* norm_b = (const float*)d_in[5];
    const float* log_dt = (const float*)d_in[6];
    const float* A_re   = (const float*)d_in[7];
    const float* A_im   = (const float*)d_in[8];
    const float* C_re   = (const float*)d_in[9];
    const float* C_im   = (const float*)d_in[10];
    const float* Dp     = (const float*)d_in[11];
    const float* out_w  = (const float*)d_in[12];
    const float* out_b  = (const float*)d_in[13];
    const float* lin1_w = (const float*)d_in[14];
    const float* lin1_b = (const float*)d_in[15];
    const float* lin2_w = (const float*)d_in[16];
    const float* lin2_b = (const float*)d_in[17];
    float* out = (float*)d_out;
    (void)in_sizes; (void)n_in; (void)out_size;

    float *p_x1, *p_z;
    __half *p_yg;
    cudaGetSymbolAddress((void**)&p_x1, g_x1);
    cudaGetSymbolAddress((void**)&p_z,  g_z);
    cudaGetSymbolAddress((void**)&p_yg, g_yg);

    k_twfill<<<4, 256>>>();
    k_semb<<<64, 256>>>(t);
    k_ssm<<<256, 256>>>(log_dt, A_re, A_im, C_re, C_im);
    k_kfft<<<128, 256>>>();
    k_wprep<<<768, 256>>>(out_w, lin1_w, lin2_w);
    k_ada_gemm<<<dim3(64, 8), 256>>>(ada_w);
    k_ada_reduce<<<512, 256>>>(ada_b);
    k_adaln<<<Bb * Hh, 256>>>(x);
    k_chanln<<<dim3(64, 32), 256>>>(norm_w, norm_b);
    k_conv<<<dim3(256, 32), 256>>>(Dp);
    k_gemm1<<<dim3(8, 2, 64), 256>>>(out_b, p_yg, p_x1, (__half*)p_z);
    k_gemm2<<<dim3(8, 2, 64), 256>>>(1, lin1_b, (const __half*)p_z, p_x1, out, 1);
    k_gemm2<<<dim3(8, 2, 64), 256>>>(2, lin2_b, (const __half*)p_z, p_x1, out + BHL, 0);
}

// round 13
// speedup vs baseline: 1.4247x; 1.0283x over previous
#include <cuda_runtime.h>
#include <cuda_fp16.h>
#include <math.h>

#define Bb 64
#define Hh 256
#define Ll 1024
#define Nn 64
#define BHL (Bb*Hh*Ll)

// ---------------- scratch (device globals; no allocs allowed) ----------------
__device__ float g_x1[BHL];        // post-AdaLN x (residual source)
__device__ float g_z[BHL];         // z (pre-norm out); low half reused as fp16 gate g
__device__ __half g_yg[BHL];       // gelu(conv out + D*z), fp16
__device__ float g_ss[Bb*2048];    // scale(0:1024) / shift(1024:2048) per batch
__device__ float g_semb[Bb*1024];  // silu(sin/cos emb)
__device__ float g_ktime[Hh*2048]; // time-domain bidirectional kernel
__device__ float g_khr[Hh*2048];   // full complex spectrum of k (re)
__device__ float g_khi[Hh*2048];   // (im)
__device__ float g_part[8*Bb*2048];// ada split-K partials
__device__ float2 g_tw[1024];      // FFT twiddles exp(-i*pi*k/1024)
__device__ __half g_wh[3*Hh*Hh];   // fp16 weights (out_w, lin1_w, lin2_w)

// ---------------- helpers ----------------
__device__ __forceinline__ float geluf(float x) {
    return 0.5f * x * (1.0f + erff(x * 0.70710678118654752440f));
}
__device__ __forceinline__ float gatef(float x) {
    float t  = __expf(-fmaxf(x, -30.0f));
    float t2 = t * t;
    return ((1.0f - t2) / (1.0f + t2)) * (1.0f / (1.0f + t));
}
__device__ __forceinline__ unsigned pckh(__half a, __half b) {
    __half2 t; t.x = a; t.y = b;
    return *reinterpret_cast<unsigned*>(&t);
}

// ---------------- fused prep: twiddles + sinusoidal emb + weight fp16 ----------------
__global__ void __launch_bounds__(256) k_prep(const int* __restrict__ t,
                                              const float* __restrict__ w0,
                                              const float* __restrict__ w1,
                                              const float* __restrict__ w2) {
    int bid = blockIdx.x;
    int tid = threadIdx.x;
    if (bid < 4) {                       // twiddle table
        int i = bid * 256 + tid;
        float ang = -3.14159265358979323846f * (float)i * (1.0f / 1024.0f);
        float sn, cs; sincosf(ang, &sn, &cs);
        g_tw[i] = make_float2(cs, sn);
    } else if (bid < 68) {               // sinusoidal embedding + silu
        int b = bid - 4;
        float tf = (float)t[b];
        const float cfr = (float)(-9.210340371976184 / 511.0);
        #pragma unroll
        for (int r = 0; r < 4; r++) {
            int i = tid + (r << 8);
            float v;
            if (i < 512) v = sinf(tf * expf((float)i * cfr));
            else         v = cosf(tf * expf((float)(i - 512) * cfr));
            float sg = 1.0f / (1.0f + expf(-v));
            g_semb[b * 1024 + i] = v * sg;
        }
    } else {                             // weight fp16 conversion
        int i = (bid - 68) * 256 + tid;  // 0 .. 3*65536-1
        int m = i >> 16, r = i & 65535;
        float v = (m == 0) ? w0[r] : (m == 1) ? w1[r] : w2[r];
        g_wh[i] = __float2half_rn(v);
    }
}

// ---------------- emb @ ada_w.T  (split-K partials) ----------------
__global__ void __launch_bounds__(256) k_ada_gemm(const float* __restrict__ W) {
    __shared__ float Ws[64][32];
    __shared__ float Eb[64][64];
    int o0 = blockIdx.x * 32;
    int kc = blockIdx.y;
    int tid = threadIdx.x;
    int o  = tid & 31;
    int bg = tid >> 5;
    float acc[8];
    #pragma unroll
    for (int j = 0; j < 8; j++) acc[j] = 0.f;

    for (int kk = kc * 128; kk < kc * 128 + 128; kk += 64) {
        {
            int oo = tid >> 3;
            int kq = tid & 7;
            const float* src = &W[(size_t)(o0 + oo) * 1024 + kk + kq * 8];
            float4 a = *(const float4*)(src);
            float4 c = *(const float4*)(src + 4);
            int kb = kq * 8;
            Ws[kb+0][oo] = a.x; Ws[kb+1][oo] = a.y; Ws[kb+2][oo] = a.z; Ws[kb+3][oo] = a.w;
            Ws[kb+4][oo] = c.x; Ws[kb+5][oo] = c.y; Ws[kb+6][oo] = c.z; Ws[kb+7][oo] = c.w;
        }
        #pragma unroll
        for (int r = 0; r < 16; r++) {
            int e = tid + (r << 8);
            int bq = e >> 6, k = e & 63;
            Eb[bq][k] = g_semb[bq * 1024 + kk + k];
        }
        __syncthreads();
        #pragma unroll 8
        for (int k = 0; k < 64; k++) {
            float wv = Ws[k][o];
            #pragma unroll
            for (int j = 0; j < 8; j++)
                acc[j] += Eb[bg * 8 + j][k] * wv;
        }
        __syncthreads();
    }
    #pragma unroll
    for (int j = 0; j < 8; j++)
        g_part[((size_t)kc * 64 + bg * 8 + j) * 2048 + o0 + o] = acc[j];
}

__global__ void __launch_bounds__(256) k_ada_reduce(const float* __restrict__ bias) {
    int idx = blockIdx.x * 256 + threadIdx.x;
    int b = idx >> 11, o = idx & 2047;
    float s = bias[o];
    #pragma unroll
    for (int kc = 0; kc < 8; kc++)
        s += g_part[((size_t)kc * 64 + b) * 2048 + o];
    g_ss[b * 2048 + o] = s;
}

// ---------------- AdaLayerNorm over L ----------------
__global__ void __launch_bounds__(256) k_adaln(const float* __restrict__ x) {
    int bh = blockIdx.x;
    int b = bh >> 8;
    int tid = threadIdx.x;
    const float4* xr = (const float4*)(x + (size_t)bh * 1024);
    float4 v = xr[tid];
    float s = v.x + v.y + v.z + v.w;
    float q = v.x*v.x + v.y*v.y + v.z*v.z + v.w*v.w;
    #pragma unroll
    for (int o = 16; o; o >>= 1) {
        s += __shfl_down_sync(0xffffffffu, s, o);
        q += __shfl_down_sync(0xffffffffu, q, o);
    }
    __shared__ float as_[8], aq_[8];
    if ((tid & 31) == 0) { as_[tid >> 5] = s; aq_[tid >> 5] = q; }
    __syncthreads();
    float S = 0.f, Q = 0.f;
    #pragma unroll
    for (int i = 0; i < 8; i++) { S += as_[i]; Q += aq_[i]; }
    float m  = S * (1.0f / 1024.0f);
    float va = Q * (1.0f / 1024.0f) - m * m;
    float rs = rsqrtf(va + 1e-5f);
    const float4* sc = (const float4*)(g_ss + b * 2048);
    const float4* sh = (const float4*)(g_ss + b * 2048 + 1024);
    float4 a = sc[tid], d = sh[tid];
    float4 o4;
    o4.x = (v.x - m) * rs * (1.0f + a.x) + d.x;
    o4.y = (v.y - m) * rs * (1.0f + a.y) + d.y;
    o4.z = (v.z - m) * rs * (1.0f + a.z) + d.z;
    o4.w = (v.w - m) * rs * (1.0f + a.w) + d.w;
    ((float4*)(g_x1 + (size_t)bh * 1024))[tid] = o4;
}

// ---------------- channel LayerNorm over H ----------------
__global__ void __launch_bounds__(256) k_chanln(const float* __restrict__ nw,
                                                const float* __restrict__ nb) {
    int b = blockIdx.x;
    int l0 = blockIdx.y * 32;
    int tid = threadIdx.x;
    int lx = tid & 31, hp = tid >> 5;
    float v[32];
    float s = 0.f, q = 0.f;
    const float* base = g_x1 + ((size_t)b * Hh) * Ll + l0 + lx;
    #pragma unroll 8
    for (int k = 0; k < 32; k++) {
        float xv = base[(size_t)(hp * 32 + k) * Ll];
        v[k] = xv; s += xv; q += xv * xv;
    }
    __shared__ float ps[8][32], pq[8][32];
    __shared__ float mean_[32], rstd_[32];
    ps[hp][lx] = s; pq[hp][lx] = q;
    __syncthreads();
    if (tid < 32) {
        float S = 0.f, Q = 0.f;
        #pragma unroll
        for (int p = 0; p < 8; p++) { S += ps[p][tid]; Q += pq[p][tid]; }
        float m  = S * (1.0f / 256.0f);
        float va = Q * (1.0f / 256.0f) - m * m;
        mean_[tid] = m; rstd_[tid] = rsqrtf(va + 1e-5f);
    }
    __syncthreads();
    float m = mean_[lx], r = rstd_[lx];
    float* zb = g_z + ((size_t)b * Hh) * Ll + l0 + lx;
    #pragma unroll 8
    for (int k = 0; k < 32; k++) {
        int h = hp * 32 + k;
        zb[(size_t)h * Ll] = (v[k] - m) * r * nw[h] + nb[h];
    }
}

// ---------------- SSM kernel ----------------
__global__ void __launch_bounds__(256) k_ssm(const float* __restrict__ log_dt,
                                             const float* __restrict__ A_re,
                                             const float* __restrict__ A_im,
                                             const float* __restrict__ C_re,
                                             const float* __restrict__ C_im) {
    __shared__ float pre[6][64];
    int h = blockIdx.x, tid = threadIdx.x;
    if (tid < 64) {
        int n = tid;
        float dt  = expf(log_dt[h]);
        float are = -expf(A_re[h * 64 + n]);
        float aim = A_im[h * 64 + n];
        float dre = dt * are, dim = dt * aim;
        float er = expf(dre);
        float sn, cs; sincosf(dim, &sn, &cs);
        float dAr = er * cs, dAi = er * sn;
        float numr = dAr - 1.0f, numi = dAi;
        float den = are * are + aim * aim;
        float fr = (numr * are + numi * aim) / den;
        float fi = (numi * are - numr * aim) / den;
        float c0re = C_re[h * 64 + n],             c0im = C_im[h * 64 + n];
        float c1re = C_re[Hh * 64 + h * 64 + n],   c1im = C_im[Hh * 64 + h * 64 + n];
        pre[0][n] = dre; pre[1][n] = dim;
        pre[2][n] = c0re * fr - c0im * fi; pre[3][n] = c0re * fi + c0im * fr;
        pre[4][n] = c1re * fr - c1im * fi; pre[5][n] = c1re * fi + c1im * fr;
    }
    __syncthreads();
    #pragma unroll
    for (int qq = 0; qq < 4; qq++) {
        int l = tid + (qq << 8);
        float lf = (float)l;
        float k0 = 0.f, k1 = 0.f;
        #pragma unroll 4
        for (int n = 0; n < 64; n++) {
            float pr = pre[0][n] * lf, pi = pre[1][n] * lf;
            float e = expf(pr);
            float sn, cs; sincosf(pi, &sn, &cs);
            float vr = e * cs, vi = e * sn;
            k0 += pre[2][n] * vr - pre[3][n] * vi;
            k1 += pre[4][n] * vr - pre[5][n] * vi;
        }
        g_ktime[h * 2048 + l]        = 2.0f * k0;
        g_ktime[h * 2048 + 2047 - l] = 2.0f * k1;
    }
}

// ---------------- generic radix-8 Stockham stage (256 threads, N=2048) ----------------
__device__ __forceinline__ void r8_stage(const float* __restrict__ sr,
                                         const float* __restrict__ si,
                                         float* __restrict__ dr,
                                         float* __restrict__ di, int lm) {
    const float Cq = 0.70710678118654752440f;
    const int m = 1 << lm;
    int i = threadIdx.x;
    int p = i >> lm;
    int r = i & (m - 1);
    float xr[8], xi[8];
    #pragma unroll
    for (int s = 0; s < 8; s++) { xr[s] = sr[i + (s << 8)]; xi[s] = si[i + (s << 8)]; }
    float pr_[4], pi_[4], qr[4], qi[4];
    #pragma unroll
    for (int s = 0; s < 4; s++) {
        pr_[s] = xr[s] + xr[s+4]; pi_[s] = xi[s] + xi[s+4];
        qr[s]  = xr[s] - xr[s+4]; qi[s]  = xi[s] - xi[s+4];
    }
    { float a=qr[1], b=qi[1]; qr[1] = Cq*(a+b); qi[1] = Cq*(b-a); }
    { float a=qr[2], b=qi[2]; qr[2] = b;        qi[2] = -a;       }
    { float a=qr[3], b=qi[3]; qr[3] = Cq*(b-a); qi[3] = -Cq*(a+b); }
    float Xr[8], Xi[8];
    {
        float r0r=pr_[0]+pr_[2], r0i=pi_[0]+pi_[2];
        float r1r=pr_[0]-pr_[2], r1i=pi_[0]-pi_[2];
        float r2r=pr_[1]+pr_[3], r2i=pi_[1]+pi_[3];
        float t3r=pr_[1]-pr_[3], t3i=pi_[1]-pi_[3];
        float r3r=t3i, r3i=-t3r;
        Xr[0]=r0r+r2r; Xi[0]=r0i+r2i;
        Xr[2]=r1r+r3r; Xi[2]=r1i+r3i;
        Xr[4]=r0r-r2r; Xi[4]=r0i-r2i;
        Xr[6]=r1r-r3r; Xi[6]=r1i-r3i;
    }
    {
        float r0r=qr[0]+qr[2], r0i=qi[0]+qi[2];
        float r1r=qr[0]-qr[2], r1i=qi[0]-qi[2];
        float r2r=qr[1]+qr[3], r2i=qi[1]+qi[3];
        float t3r=qr[1]-qr[3], t3i=qi[1]-qi[3];
        float r3r=t3i, r3i=-t3r;
        Xr[1]=r0r+r2r; Xi[1]=r0i+r2i;
        Xr[3]=r1r+r3r; Xi[3]=r1i+r3i;
        Xr[5]=r0r-r2r; Xi[5]=r0i-r2i;
        Xr[7]=r1r-r3r; Xi[7]=r1i-r3i;
    }
    float2 w = g_tw[m * p];
    float wjr = 1.f, wji = 0.f;
    int o = ((m * p) << 3) + r;
    dr[o] = Xr[0]; di[o] = Xi[0];
    #pragma unroll
    for (int j = 1; j < 8; j++) {
        float nr = wjr * w.x - wji * w.y;
        wji = wji * w.x + wjr * w.y;
        wjr = nr;
        dr[o + j * m] = Xr[j] * wjr - Xi[j] * wji;
        di[o + j * m] = Xi[j] * wjr + Xr[j] * wji;
    }
}

// ---------------- full radix-8 FFT (generic; used by kfft) ----------------
__device__ __forceinline__ void fft2048_r8(float*& sr, float*& si, float*& dr, float*& di) {
    #pragma unroll
    for (int lm = 0; lm < 9; lm += 3) {
        r8_stage(sr, si, dr, di, lm);
        __syncthreads();
        float* tp; tp=sr;sr=dr;dr=tp; tp=si;si=di;di=tp;
    }
    #pragma unroll
    for (int q = 0; q < 2; q++) {
        int r = threadIdx.x + (q << 8);
        float a0r=sr[r],      a0i=si[r];
        float a1r=sr[r+512],  a1i=si[r+512];
        float a2r=sr[r+1024], a2i=si[r+1024];
        float a3r=sr[r+1536], a3i=si[r+1536];
        float r0r=a0r+a2r, r0i=a0i+a2i;
        float r1r=a0r-a2r, r1i=a0i-a2i;
        float r2r=a1r+a3r, r2i=a1i+a3i;
        float t3r=a1r-a3r, t3i=a1i-a3i;
        float r3r=t3i, r3i=-t3r;
        dr[r]      = r0r+r2r; di[r]      = r0i+r2i;
        dr[r+512]  = r1r+r3r; di[r+512]  = r1i+r3i;
        dr[r+1024] = r0r-r2r; di[r+1024] = r0i-r2i;
        dr[r+1536] = r1r-r3r; di[r+1536] = r1i-r3i;
    }
    __syncthreads();
    float* tp; tp=sr;sr=dr;dr=tp; tp=si;si=di;di=tp;
}

// ---------------- FFT of kernel rows ----------------
__global__ void __launch_bounds__(256) k_kfft() {
    __shared__ float bAr[2048], bAi[2048], bBr[2048], bBi[2048];
    int tid = threadIdx.x;
    int h0 = blockIdx.x * 2, h1 = h0 + 1;
    #pragma unroll
    for (int qq = 0; qq < 8; qq++) {
        int idx = tid + (qq << 8);
        bAr[idx] = g_ktime[h0 * 2048 + idx];
        bAi[idx] = g_ktime[h1 * 2048 + idx];
    }
    __syncthreads();
    float *sr = bAr, *si = bAi, *dr = bBr, *di = bBi;
    fft2048_r8(sr, si, dr, di);
    #pragma unroll
    for (int qq = 0; qq < 8; qq++) {
        int f = tid + (qq << 8);
        int fr2 = (2048 - f) & 2047;
        float ur = sr[f],  ui = si[f];
        float vr = sr[fr2], vi = -si[fr2];
        g_khr[h0 * 2048 + f] = 0.5f * (ur + vr);
        g_khi[h0 * 2048 + f] = 0.5f * (ui + vi);
        g_khr[h1 * 2048 + f] = 0.5f * (ui - vi);
        g_khi[h1 * 2048 + f] = -0.5f * (ur - vr);
    }
}

// ---------------- main conv: fused pointwise + fused epilogue, fp16 output ----------------
__global__ void __launch_bounds__(256) k_conv(const float* __restrict__ Dp) {
    __shared__ float bAr[2048], bAi[2048], bBr[2048], bBi[2048];
    const float Cq = 0.70710678118654752440f;
    int tid = threadIdx.x;
    int h  = blockIdx.x;
    int pb = blockIdx.y;
    const float* za = g_z + ((size_t)(2 * pb) * Hh + h) * Ll;
    const float* zb = za + (size_t)Hh * Ll;
    float ra[4], rb[4];
    #pragma unroll
    for (int qq = 0; qq < 4; qq++) {
        int idx = tid + (qq << 8);
        ra[qq] = za[idx]; rb[qq] = zb[idx];
        bAr[idx] = ra[qq]; bAi[idx] = rb[qq];
    }
    __syncthreads();

    // ---- forward stage 1 (m=1): inputs s>=4 are the zero pad ----
    {
        float xr[4], xi[4];
        #pragma unroll
        for (int s = 0; s < 4; s++) { xr[s] = bAr[tid + (s << 8)]; xi[s] = bAi[tid + (s << 8)]; }
        float qr[4], qi[4];
        #pragma unroll
        for (int s = 0; s < 4; s++) { qr[s] = xr[s]; qi[s] = xi[s]; }
        { float a=qr[1], b=qi[1]; qr[1] = Cq*(a+b); qi[1] = Cq*(b-a); }
        { float a=qr[2], b=qi[2]; qr[2] = b;        qi[2] = -a;       }
        { float a=qr[3], b=qi[3]; qr[3] = Cq*(b-a); qi[3] = -Cq*(a+b); }
        float Xr[8], Xi[8];
        {
            float r0r=xr[0]+xr[2], r0i=xi[0]+xi[2];
            float r1r=xr[0]-xr[2], r1i=xi[0]-xi[2];
            float r2r=xr[1]+xr[3], r2i=xi[1]+xi[3];
            float t3r=xr[1]-xr[3], t3i=xi[1]-xi[3];
            float r3r=t3i, r3i=-t3r;
            Xr[0]=r0r+r2r; Xi[0]=r0i+r2i;
            Xr[2]=r1r+r3r; Xi[2]=r1i+r3i;
            Xr[4]=r0r-r2r; Xi[4]=r0i-r2i;
            Xr[6]=r1r-r3r; Xi[6]=r1i-r3i;
        }
        {
            float r0r=qr[0]+qr[2], r0i=qi[0]+qi[2];
            float r1r=qr[0]-qr[2], r1i=qi[0]-qi[2];
            float r2r=qr[1]+qr[3], r2i=qi[1]+qi[3];
            float t3r=qr[1]-qr[3], t3i=qi[1]-qi[3];
            float r3r=t3i, r3i=-t3r;
            Xr[1]=r0r+r2r; Xi[1]=r0i+r2i;
            Xr[3]=r1r+r3r; Xi[3]=r1i+r3i;
            Xr[5]=r0r-r2r; Xi[5]=r0i-r2i;
            Xr[7]=r1r-r3r; Xi[7]=r1i-r3i;
        }
        float2 w = g_tw[tid];
        float wjr = 1.f, wji = 0.f;
        int o = tid << 3;
        bBr[o] = Xr[0]; bBi[o] = Xi[0];
        #pragma unroll
        for (int j = 1; j < 8; j++) {
            float nr = wjr * w.x - wji * w.y;
            wji = wji * w.x + wjr * w.y;
            wjr = nr;
            bBr[o + j] = Xr[j] * wjr - Xi[j] * wji;
            bBi[o + j] = Xi[j] * wjr + Xr[j] * wji;
        }
    }
    __syncthreads();
    r8_stage(bBr, bBi, bAr, bAi, 3); __syncthreads();
    r8_stage(bAr, bAi, bBr, bBi, 6); __syncthreads();

    // ---- forward final r4 fused with spectrum multiply (+conj, +1/N) -> bA ----
    {
        const float* khr = g_khr + h * 2048;
        const float* khi = g_khi + h * 2048;
        const float inv = 1.0f / 2048.0f;
        #pragma unroll
        for (int q = 0; q < 2; q++) {
            int r = tid + (q << 8);
            float a0r=bBr[r],      a0i=bBi[r];
            float a1r=bBr[r+512],  a1i=bBi[r+512];
            float a2r=bBr[r+1024], a2i=bBi[r+1024];
            float a3r=bBr[r+1536], a3i=bBi[r+1536];
            float r0r=a0r+a2r, r0i=a0i+a2i;
            float r1r=a0r-a2r, r1i=a0i-a2i;
            float r2r=a1r+a3r, r2i=a1i+a3i;
            float t3r=a1r-a3r, t3i=a1i-a3i;
            float r3r=t3i, r3i=-t3r;
            float Xr4[4], Xi4[4];
            Xr4[0]=r0r+r2r; Xi4[0]=r0i+r2i;
            Xr4[1]=r1r+r3r; Xi4[1]=r1i+r3i;
            Xr4[2]=r0r-r2r; Xi4[2]=r0i-r2i;
            Xr4[3]=r1r-r3r; Xi4[3]=r1i-r3i;
            #pragma unroll
            for (int j = 0; j < 4; j++) {
                int f = r + j * 512;
                float kr = khr[f], ki = khi[f];
                float ar = Xr4[j], ai = Xi4[j];
                bAr[f] = (ar * kr - ai * ki) * inv;
                bAi[f] = -(ar * ki + ai * kr) * inv;
            }
        }
    }
    __syncthreads();

    // ---- inverse FFT ----
    r8_stage(bAr, bAi, bBr, bBi, 0); __syncthreads();
    r8_stage(bBr, bBi, bAr, bAi, 3); __syncthreads();
    r8_stage(bAr, bAi, bBr, bBi, 6); __syncthreads();

    // ---- inverse final r4 (outputs [0,1024) only) fused with epilogue, fp16 store ----
    float Dh = Dp[h];
    __half* ya = g_yg + ((size_t)(2 * pb) * Hh + h) * Ll;
    __half* yb = ya + (size_t)Hh * Ll;
    #pragma unroll
    for (int q = 0; q < 2; q++) {
        int r = tid + (q << 8);
        float a0r=bBr[r],      a0i=bBi[r];
        float a1r=bBr[r+512],  a1i=bBi[r+512];
        float a2r=bBr[r+1024], a2i=bBi[r+1024];
        float a3r=bBr[r+1536], a3i=bBi[r+1536];
        float r0r=a0r+a2r, r0i=a0i+a2i;
        float r1r=a0r-a2r, r1i=a0i-a2i;
        float r2r=a1r+a3r, r2i=a1i+a3i;
        float t3r=a1r-a3r, t3i=a1i-a3i;
        float r3r=t3i, r3i=-t3r;
        float o1r = r0r + r2r, o1i = r0i + r2i;
        float o2r = r1r + r3r, o2i = r1i + r3i;
        float v1 = o1r  + Dh * ra[q];
        float v2 = -o1i + Dh * rb[q];
        float v3 = o2r  + Dh * ra[q + 2];
        float v4 = -o2i + Dh * rb[q + 2];
        ya[r]       = __float2half_rn(geluf(v1));
        yb[r]       = __float2half_rn(geluf(v2));
        ya[r + 512] = __float2half_rn(geluf(v3));
        yb[r + 512] = __float2half_rn(geluf(v4));
    }
}

// ---------------- GEMM1: g = gate(out_w@yg + out_b + x1), fp16 out, ping-pong smem ----------------
__global__ void __launch_bounds__(256) k_gemm1(const float* __restrict__ bias,
                                               const __half* __restrict__ X,
                                               const float* __restrict__ resid,
                                               __half* __restrict__ Yout) {
    __shared__ __half Ws[2][128][24];
    __shared__ __half Xs[2][16][136];
    int l0 = blockIdx.x * 128;
    int o0 = blockIdx.y * 128;
    int b  = blockIdx.z;
    int tid = threadIdx.x;
    int lane = tid & 31, warp = tid >> 5;
    int wm = warp & 1, wn = warp >> 1;

    float acc[4][4][4];
    #pragma unroll
    for (int m = 0; m < 4; m++)
        #pragma unroll
        for (int n = 0; n < 4; n++)
            #pragma unroll
            for (int c = 0; c < 4; c++) acc[m][n][c] = 0.f;

    int wo = tid >> 1, wk = (tid & 1) * 8;
    const __half* whp = &g_wh[(size_t)(o0 + wo) * 256 + wk];
    int xk = tid >> 4, xl = (tid & 15) * 8;
    const __half* xpb = &X[((size_t)b * Hh + xk) * Ll + l0 + xl];

    uint4 wv = *(const uint4*)(whp);
    uint4 xv = *(const uint4*)(xpb);
    *(uint4*)&Ws[0][wo][wk] = wv;
    *(uint4*)&Xs[0][xk][xl] = xv;
    __syncthreads();

    #pragma unroll 1
    for (int it = 0; it < 16; it++) {
        int cur = it & 1;
        if (it < 15) {
            int kk = (it + 1) * 16;
            wv = *(const uint4*)(whp + kk);
            xv = *(const uint4*)(xpb + (size_t)kk * Ll);
        }
        int k0 = (lane & 3) * 2;
        int nb = wn * 32 + (lane >> 2);
        unsigned bf[4][2];
        #pragma unroll
        for (int nt = 0; nt < 4; nt++) {
            int n = nb + nt * 8;
            bf[nt][0] = pckh(Xs[cur][k0][n],     Xs[cur][k0 + 1][n]);
            bf[nt][1] = pckh(Xs[cur][k0 + 8][n], Xs[cur][k0 + 9][n]);
        }
        #pragma unroll
        for (int m = 0; m < 4; m++) {
            int r = wm * 64 + m * 16 + (lane >> 2);
            unsigned a0 = *(const unsigned*)&Ws[cur][r][k0];
            unsigned a1 = *(const unsigned*)&Ws[cur][r + 8][k0];
            unsigned a2 = *(const unsigned*)&Ws[cur][r][k0 + 8];
            unsigned a3 = *(const unsigned*)&Ws[cur][r + 8][k0 + 8];
            #pragma unroll
            for (int nt = 0; nt < 4; nt++)
                asm volatile(
                    "mma.sync.aligned.m16n8k16.row.col.f32.f16.f16.f32 "
                    "{%0,%1,%2,%3}, {%4,%5,%6,%7}, {%8,%9}, {%0,%1,%2,%3};"
                    : "+f"(acc[m][nt][0]), "+f"(acc[m][nt][1]),
                      "+f"(acc[m][nt][2]), "+f"(acc[m][nt][3])
                    : "r"(a0), "r"(a1), "r"(a2), "r"(a3),
                      "r"(bf[nt][0]), "r"(bf[nt][1]));
        }
        if (it < 15) {
            *(uint4*)&Ws[1 - cur][wo][wk] = wv;
            *(uint4*)&Xs[1 - cur][xk][xl] = xv;
        }
        __syncthreads();
    }

    #pragma unroll
    for (int m = 0; m < 4; m++) {
        int o = o0 + wm * 64 + m * 16 + (lane >> 2);
        float bo0 = bias[o], bo8 = bias[o + 8];
        #pragma unroll
        for (int nt = 0; nt < 4; nt++) {
            int lc = l0 + wn * 32 + nt * 8 + (lane & 3) * 2;
            size_t base0 = ((size_t)b * Hh + o) * Ll + lc;
            size_t base8 = base0 + 8 * (size_t)Ll;
            float2 r0 = *(const float2*)&resid[base0];
            float2 r8 = *(const float2*)&resid[base8];
            __half q0 = __float2half_rn(gatef(acc[m][nt][0] + bo0 + r0.x));
            __half q1 = __float2half_rn(gatef(acc[m][nt][1] + bo0 + r0.y));
            __half q2 = __float2half_rn(gatef(acc[m][nt][2] + bo8 + r8.x));
            __half q3 = __float2half_rn(gatef(acc[m][nt][3] + bo8 + r8.y));
            *(unsigned*)&Yout[base0] = pckh(q0, q1);
            *(unsigned*)&Yout[base8] = pckh(q2, q3);
        }
    }
}

// ---------------- GEMM2/3: out = lin@g + b (+x1 if addres), ping-pong smem ----------------
__global__ void __launch_bounds__(256) k_gemm2(int widx,
                                               const float* __restrict__ bias,
                                               const __half* __restrict__ X,
                                               const float* __restrict__ resid,
                                               float* __restrict__ out,
                                               int addres) {
    __shared__ __half Ws[2][128][24];
    __shared__ __half Xs[2][16][136];
    int l0 = blockIdx.x * 128;
    int o0 = blockIdx.y * 128;
    int b  = blockIdx.z;
    int tid = threadIdx.x;
    int lane = tid & 31, warp = tid >> 5;
    int wm = warp & 1, wn = warp >> 1;

    float acc[4][4][4];
    #pragma unroll
    for (int m = 0; m < 4; m++)
        #pragma unroll
        for (int n = 0; n < 4; n++)
            #pragma unroll
            for (int c = 0; c < 4; c++) acc[m][n][c] = 0.f;

    int wo = tid >> 1, wk = (tid & 1) * 8;
    const __half* whp = &g_wh[(size_t)widx * Hh * Hh + (size_t)(o0 + wo) * 256 + wk];
    int xk = tid >> 4, xl = (tid & 15) * 8;
    const __half* xpb = &X[((size_t)b * Hh + xk) * Ll + l0 + xl];

    uint4 wv = *(const uint4*)(whp);
    uint4 xv = *(const uint4*)(xpb);
    *(uint4*)&Ws[0][wo][wk] = wv;
    *(uint4*)&Xs[0][xk][xl] = xv;
    __syncthreads();

    #pragma unroll 1
    for (int it = 0; it < 16; it++) {
        int cur = it & 1;
        if (it < 15) {
            int kk = (it + 1) * 16;
            wv = *(const uint4*)(whp + kk);
            xv = *(const uint4*)(xpb + (size_t)kk * Ll);
        }
        int k0 = (lane & 3) * 2;
        int nb = wn * 32 + (lane >> 2);
        unsigned bf[4][2];
        #pragma unroll
        for (int nt = 0; nt < 4; nt++) {
            int n = nb + nt * 8;
            bf[nt][0] = pckh(Xs[cur][k0][n],     Xs[cur][k0 + 1][n]);
            bf[nt][1] = pckh(Xs[cur][k0 + 8][n], Xs[cur][k0 + 9][n]);
        }
        #pragma unroll
        for (int m = 0; m < 4; m++) {
            int r = wm * 64 + m * 16 + (lane >> 2);
            unsigned a0 = *(const unsigned*)&Ws[cur][r][k0];
            unsigned a1 = *(const unsigned*)&Ws[cur][r + 8][k0];
            unsigned a2 = *(const unsigned*)&Ws[cur][r][k0 + 8];
            unsigned a3 = *(const unsigned*)&Ws[cur][r + 8][k0 + 8];
            #pragma unroll
            for (int nt = 0; nt < 4; nt++)
                asm volatile(
                    "mma.sync.aligned.m16n8k16.row.col.f32.f16.f16.f32 "
                    "{%0,%1,%2,%3}, {%4,%5,%6,%7}, {%8,%9}, {%0,%1,%2,%3};"
                    : "+f"(acc[m][nt][0]), "+f"(acc[m][nt][1]),
                      "+f"(acc[m][nt][2]), "+f"(acc[m][nt][3])
                    : "r"(a0), "r"(a1), "r"(a2), "r"(a3),
                      "r"(bf[nt][0]), "r"(bf[nt][1]));
        }
        if (it < 15) {
            *(uint4*)&Ws[1 - cur][wo][wk] = wv;
            *(uint4*)&Xs[1 - cur][xk][xl] = xv;
        }
        __syncthreads();
    }

    #pragma unroll
    for (int m = 0; m < 4; m++) {
        int o = o0 + wm * 64 + m * 16 + (lane >> 2);
        float bo0 = bias[o], bo8 = bias[o + 8];
        #pragma unroll
        for (int nt = 0; nt < 4; nt++) {
            int lc = l0 + wn * 32 + nt * 8 + (lane & 3) * 2;
            size_t base0 = ((size_t)b * Hh + o) * Ll + lc;
            size_t base8 = base0 + 8 * (size_t)Ll;
            float v0 = acc[m][nt][0] + bo0;
            float v1 = acc[m][nt][1] + bo0;
            float v2 = acc[m][nt][2] + bo8;
            float v3 = acc[m][nt][3] + bo8;
            if (addres) {
                float2 r0 = *(const float2*)&resid[base0];
                float2 r8 = *(const float2*)&resid[base8];
                v0 += r0.x; v1 += r0.y; v2 += r8.x; v3 += r8.y;
            }
            *(float2*)&out[base0] = make_float2(v0, v1);
            *(float2*)&out[base8] = make_float2(v2, v3);
        }
    }
}

// ---------------- launch ----------------
extern "C" void kernel_launch(void* const* d_in, const int* in_sizes, int n_in,
                              void* d_out, int out_size) {
    const float* x      = (const float*)d_in[0];
    const int*   t      = (const int*)  d_in[1];
    const float* ada_w  = (const float*)d_in[2];
    const float* ada_b  = (const float*)d_in[3];
    const float* norm_w = (const float*)d_in[4];
    const float* norm_b = (const float*)d_in[5];
    const float* log_dt = (const float*)d_in[6];
    const float* A_re   = (const float*)d_in[7];
    const float* A_im   = (const float*)d_in[8];
    const float* C_re   = (const float*)d_in[9];
    const float* C_im   = (const float*)d_in[10];
    const float* Dp     = (const float*)d_in[11];
    const float* out_w  = (const float*)d_in[12];
    const float* out_b  = (const float*)d_in[13];
    const float* lin1_w = (const float*)d_in[14];
    const float* lin1_b = (const float*)d_in[15];
    const float* lin2_w = (const float*)d_in[16];
    const float* lin2_b = (const float*)d_in[17];
    float* out = (float*)d_out;
    (void)in_sizes; (void)n_in; (void)out_size;

    float *p_x1, *p_z;
    __half *p_yg;
    cudaGetSymbolAddress((void**)&p_x1, g_x1);
    cudaGetSymbolAddress((void**)&p_z,  g_z);
    cudaGetSymbolAddress((void**)&p_yg, g_yg);

    k_prep<<<836, 256>>>(t, out_w, lin1_w, lin2_w);
    k_ssm<<<256, 256>>>(log_dt, A_re, A_im, C_re, C_im);
    k_kfft<<<128, 256>>>();
    k_ada_gemm<<<dim3(64, 8), 256>>>(ada_w);
    k_ada_reduce<<<512, 256>>>(ada_b);
    k_adaln<<<Bb * Hh, 256>>>(x);
    k_chanln<<<dim3(64, 32), 256>>>(norm_w, norm_b);
    k_conv<<<dim3(256, 32), 256>>>(Dp);
    k_gemm1<<<dim3(8, 2, 64), 256>>>(out_b, p_yg, p_x1, (__half*)p_z);
    k_gemm2<<<dim3(8, 2, 64), 256>>>(1, lin1_b, (const __half*)p_z, p_x1, out, 1);
    k_gemm2<<<dim3(8, 2, 64), 256>>>(2, lin2_b, (const __half*)p_z, p_x1, out + BHL, 0);
}

// round 14
// speedup vs baseline: 1.5128x; 1.0618x over previous
#include <cuda_runtime.h>
#include <cuda_fp16.h>
#include <math.h>

#define Bb 64
#define Hh 256
#define Ll 1024
#define Nn 64
#define BHL (Bb*Hh*Ll)

// ---------------- scratch (device globals; no allocs allowed) ----------------
__device__ float g_x1[BHL];        // post-AdaLN x (residual source)
__device__ float g_z[BHL];         // z (pre-norm out); low half reused as fp16 gate g
__device__ __half g_yg[BHL];       // gelu(conv out + D*z), fp16
__device__ float g_ss[Bb*2048];    // scale(0:1024) / shift(1024:2048) per batch
__device__ float g_semb[Bb*1024];  // silu(sin/cos emb)
__device__ float g_ktime[Hh*2048]; // time-domain bidirectional kernel
__device__ float g_khr[Hh*2048];   // full complex spectrum of k (re)
__device__ float g_khi[Hh*2048];   // (im)
__device__ float g_part[8*Bb*2048];// ada split-K partials
__device__ float2 g_tw[1024];      // FFT twiddles exp(-i*pi*k/1024)
__device__ __half g_wh[3*Hh*Hh];   // fp16 weights (out_w, lin1_w, lin2_w)

// ---------------- helpers ----------------
__device__ __forceinline__ float geluf(float x) {
    return 0.5f * x * (1.0f + erff(x * 0.70710678118654752440f));
}
__device__ __forceinline__ float gatef(float x) {
    float t  = __expf(-fmaxf(x, -30.0f));
    float t2 = t * t;
    return ((1.0f - t2) / (1.0f + t2)) * (1.0f / (1.0f + t));
}
__device__ __forceinline__ unsigned pckh(__half a, __half b) {
    __half2 t; t.x = a; t.y = b;
    return *reinterpret_cast<unsigned*>(&t);
}

// ---------------- fused prep: twiddles + sinusoidal emb + weight fp16 ----------------
__global__ void __launch_bounds__(256) k_prep(const int* __restrict__ t,
                                              const float* __restrict__ w0,
                                              const float* __restrict__ w1,
                                              const float* __restrict__ w2) {
    int bid = blockIdx.x;
    int tid = threadIdx.x;
    if (bid < 4) {                       // twiddle table
        int i = bid * 256 + tid;
        float ang = -3.14159265358979323846f * (float)i * (1.0f / 1024.0f);
        float sn, cs; sincosf(ang, &sn, &cs);
        g_tw[i] = make_float2(cs, sn);
    } else if (bid < 68) {               // sinusoidal embedding + silu
        int b = bid - 4;
        float tf = (float)t[b];
        const float cfr = (float)(-9.210340371976184 / 511.0);
        #pragma unroll
        for (int r = 0; r < 4; r++) {
            int i = tid + (r << 8);
            float v;
            if (i < 512) v = sinf(tf * expf((float)i * cfr));
            else         v = cosf(tf * expf((float)(i - 512) * cfr));
            float sg = 1.0f / (1.0f + expf(-v));
            g_semb[b * 1024 + i] = v * sg;
        }
    } else {                             // weight fp16 conversion
        int i = (bid - 68) * 256 + tid;  // 0 .. 3*65536-1
        int m = i >> 16, r = i & 65535;
        float v = (m == 0) ? w0[r] : (m == 1) ? w1[r] : w2[r];
        g_wh[i] = __float2half_rn(v);
    }
}

// ---------------- emb @ ada_w.T  (split-K partials) ----------------
__global__ void __launch_bounds__(256) k_ada_gemm(const float* __restrict__ W) {
    __shared__ float Ws[64][32];
    __shared__ float Eb[64][68];   // [k][b], padded: rows 16B-aligned, conflict-free
    int o0 = blockIdx.x * 32;
    int kc = blockIdx.y;
    int tid = threadIdx.x;
    int o  = tid & 31;
    int bg = tid >> 5;
    float acc[8];
    #pragma unroll
    for (int j = 0; j < 8; j++) acc[j] = 0.f;

    for (int kk = kc * 128; kk < kc * 128 + 128; kk += 64) {
        {
            int oo = tid >> 3;
            int kq = tid & 7;
            const float* src = &W[(size_t)(o0 + oo) * 1024 + kk + kq * 8];
            float4 a = *(const float4*)(src);
            float4 c = *(const float4*)(src + 4);
            int kb = kq * 8;
            Ws[kb+0][oo] = a.x; Ws[kb+1][oo] = a.y; Ws[kb+2][oo] = a.z; Ws[kb+3][oo] = a.w;
            Ws[kb+4][oo] = c.x; Ws[kb+5][oo] = c.y; Ws[kb+6][oo] = c.z; Ws[kb+7][oo] = c.w;
        }
        #pragma unroll
        for (int r = 0; r < 16; r++) {
            int e = tid + (r << 8);
            int bq = e >> 6, k = e & 63;
            Eb[k][bq] = g_semb[bq * 1024 + kk + k];
        }
        __syncthreads();
        #pragma unroll 8
        for (int k = 0; k < 64; k++) {
            float wv = Ws[k][o];
            float4 e0 = *(const float4*)&Eb[k][bg * 8];
            float4 e1 = *(const float4*)&Eb[k][bg * 8 + 4];
            acc[0] += e0.x * wv; acc[1] += e0.y * wv;
            acc[2] += e0.z * wv; acc[3] += e0.w * wv;
            acc[4] += e1.x * wv; acc[5] += e1.y * wv;
            acc[6] += e1.z * wv; acc[7] += e1.w * wv;
        }
        __syncthreads();
    }
    #pragma unroll
    for (int j = 0; j < 8; j++)
        g_part[((size_t)kc * 64 + bg * 8 + j) * 2048 + o0 + o] = acc[j];
}

__global__ void __launch_bounds__(256) k_ada_reduce(const float* __restrict__ bias) {
    int idx = blockIdx.x * 256 + threadIdx.x;
    int b = idx >> 11, o = idx & 2047;
    float s = bias[o];
    #pragma unroll
    for (int kc = 0; kc < 8; kc++)
        s += g_part[((size_t)kc * 64 + b) * 2048 + o];
    g_ss[b * 2048 + o] = s;
}

// ---------------- AdaLayerNorm over L ----------------
__global__ void __launch_bounds__(256) k_adaln(const float* __restrict__ x) {
    int bh = blockIdx.x;
    int b = bh >> 8;
    int tid = threadIdx.x;
    const float4* xr = (const float4*)(x + (size_t)bh * 1024);
    float4 v = xr[tid];
    float s = v.x + v.y + v.z + v.w;
    float q = v.x*v.x + v.y*v.y + v.z*v.z + v.w*v.w;
    #pragma unroll
    for (int o = 16; o; o >>= 1) {
        s += __shfl_down_sync(0xffffffffu, s, o);
        q += __shfl_down_sync(0xffffffffu, q, o);
    }
    __shared__ float as_[8], aq_[8];
    if ((tid & 31) == 0) { as_[tid >> 5] = s; aq_[tid >> 5] = q; }
    __syncthreads();
    float S = 0.f, Q = 0.f;
    #pragma unroll
    for (int i = 0; i < 8; i++) { S += as_[i]; Q += aq_[i]; }
    float m  = S * (1.0f / 1024.0f);
    float va = Q * (1.0f / 1024.0f) - m * m;
    float rs = rsqrtf(va + 1e-5f);
    const float4* sc = (const float4*)(g_ss + b * 2048);
    const float4* sh = (const float4*)(g_ss + b * 2048 + 1024);
    float4 a = sc[tid], d = sh[tid];
    float4 o4;
    o4.x = (v.x - m) * rs * (1.0f + a.x) + d.x;
    o4.y = (v.y - m) * rs * (1.0f + a.y) + d.y;
    o4.z = (v.z - m) * rs * (1.0f + a.z) + d.z;
    o4.w = (v.w - m) * rs * (1.0f + a.w) + d.w;
    ((float4*)(g_x1 + (size_t)bh * 1024))[tid] = o4;
}

// ---------------- channel LayerNorm over H ----------------
__global__ void __launch_bounds__(256) k_chanln(const float* __restrict__ nw,
                                                const float* __restrict__ nb) {
    int b = blockIdx.x;
    int l0 = blockIdx.y * 32;
    int tid = threadIdx.x;
    int lx = tid & 31, hp = tid >> 5;
    float v[32];
    float s = 0.f, q = 0.f;
    const float* base = g_x1 + ((size_t)b * Hh) * Ll + l0 + lx;
    #pragma unroll 8
    for (int k = 0; k < 32; k++) {
        float xv = base[(size_t)(hp * 32 + k) * Ll];
        v[k] = xv; s += xv; q += xv * xv;
    }
    __shared__ float ps[8][32], pq[8][32];
    __shared__ float mean_[32], rstd_[32];
    ps[hp][lx] = s; pq[hp][lx] = q;
    __syncthreads();
    if (tid < 32) {
        float S = 0.f, Q = 0.f;
        #pragma unroll
        for (int p = 0; p < 8; p++) { S += ps[p][tid]; Q += pq[p][tid]; }
        float m  = S * (1.0f / 256.0f);
        float va = Q * (1.0f / 256.0f) - m * m;
        mean_[tid] = m; rstd_[tid] = rsqrtf(va + 1e-5f);
    }
    __syncthreads();
    float m = mean_[lx], r = rstd_[lx];
    float* zb = g_z + ((size_t)b * Hh) * Ll + l0 + lx;
    #pragma unroll 8
    for (int k = 0; k < 32; k++) {
        int h = hp * 32 + k;
        zb[(size_t)h * Ll] = (v[k] - m) * r * nw[h] + nb[h];
    }
}

// ---------------- SSM kernel: base sincos + 3-step complex recurrence ----------------
__global__ void __launch_bounds__(256) k_ssm(const float* __restrict__ log_dt,
                                             const float* __restrict__ A_re,
                                             const float* __restrict__ A_im,
                                             const float* __restrict__ C_re,
                                             const float* __restrict__ C_im) {
    __shared__ float pre[8][64]; // dre, dim, c0r, c0i, c1r, c1i, dAr, dAi
    int h = blockIdx.x, tid = threadIdx.x;
    if (tid < 64) {
        int n = tid;
        float dt  = expf(log_dt[h]);
        float are = -expf(A_re[h * 64 + n]);
        float aim = A_im[h * 64 + n];
        float dre = dt * are, dim = dt * aim;
        float er = expf(dre);
        float sn, cs; sincosf(dim, &sn, &cs);
        float dAr = er * cs, dAi = er * sn;
        float numr = dAr - 1.0f, numi = dAi;
        float den = are * are + aim * aim;
        float fr = (numr * are + numi * aim) / den;
        float fi = (numi * are - numr * aim) / den;
        float c0re = C_re[h * 64 + n],             c0im = C_im[h * 64 + n];
        float c1re = C_re[Hh * 64 + h * 64 + n],   c1im = C_im[Hh * 64 + h * 64 + n];
        pre[0][n] = dre; pre[1][n] = dim;
        pre[2][n] = c0re * fr - c0im * fi; pre[3][n] = c0re * fi + c0im * fr;
        pre[4][n] = c1re * fr - c1im * fi; pre[5][n] = c1re * fi + c1im * fr;
        pre[6][n] = dAr; pre[7][n] = dAi;
    }
    __syncthreads();
    int l0 = tid * 4;
    float lf = (float)l0;
    float k0[4] = {0.f, 0.f, 0.f, 0.f};
    float k1[4] = {0.f, 0.f, 0.f, 0.f};
    #pragma unroll 2
    for (int n = 0; n < 64; n++) {
        float pr = pre[0][n] * lf, pi = pre[1][n] * lf;
        float e = expf(pr);
        float sn, cs; sincosf(pi, &sn, &cs);
        float vr = e * cs, vi = e * sn;
        float sr_ = pre[6][n], si_ = pre[7][n];
        float c0r = pre[2][n], c0i = pre[3][n];
        float c1r = pre[4][n], c1i = pre[5][n];
        #pragma unroll
        for (int s = 0; s < 4; s++) {
            k0[s] += c0r * vr - c0i * vi;
            k1[s] += c1r * vr - c1i * vi;
            if (s < 3) {
                float nvr = vr * sr_ - vi * si_;
                vi = vi * sr_ + vr * si_;
                vr = nvr;
            }
        }
    }
    *(float4*)&g_ktime[h * 2048 + l0] =
        make_float4(2.f*k0[0], 2.f*k0[1], 2.f*k0[2], 2.f*k0[3]);
    *(float4*)&g_ktime[h * 2048 + 2044 - l0] =
        make_float4(2.f*k1[3], 2.f*k1[2], 2.f*k1[1], 2.f*k1[0]);
}

// ---------------- generic radix-8 Stockham stage (256 threads, N=2048) ----------------
__device__ __forceinline__ void r8_stage(const float* __restrict__ sr,
                                         const float* __restrict__ si,
                                         float* __restrict__ dr,
                                         float* __restrict__ di, int lm) {
    const float Cq = 0.70710678118654752440f;
    const int m = 1 << lm;
    int i = threadIdx.x;
    int p = i >> lm;
    int r = i & (m - 1);
    float xr[8], xi[8];
    #pragma unroll
    for (int s = 0; s < 8; s++) { xr[s] = sr[i + (s << 8)]; xi[s] = si[i + (s << 8)]; }
    float pr_[4], pi_[4], qr[4], qi[4];
    #pragma unroll
    for (int s = 0; s < 4; s++) {
        pr_[s] = xr[s] + xr[s+4]; pi_[s] = xi[s] + xi[s+4];
        qr[s]  = xr[s] - xr[s+4]; qi[s]  = xi[s] - xi[s+4];
    }
    { float a=qr[1], b=qi[1]; qr[1] = Cq*(a+b); qi[1] = Cq*(b-a); }
    { float a=qr[2], b=qi[2]; qr[2] = b;        qi[2] = -a;       }
    { float a=qr[3], b=qi[3]; qr[3] = Cq*(b-a); qi[3] = -Cq*(a+b); }
    float Xr[8], Xi[8];
    {
        float r0r=pr_[0]+pr_[2], r0i=pi_[0]+pi_[2];
        float r1r=pr_[0]-pr_[2], r1i=pi_[0]-pi_[2];
        float r2r=pr_[1]+pr_[3], r2i=pi_[1]+pi_[3];
        float t3r=pr_[1]-pr_[3], t3i=pi_[1]-pi_[3];
        float r3r=t3i, r3i=-t3r;
        Xr[0]=r0r+r2r; Xi[0]=r0i+r2i;
        Xr[2]=r1r+r3r; Xi[2]=r1i+r3i;
        Xr[4]=r0r-r2r; Xi[4]=r0i-r2i;
        Xr[6]=r1r-r3r; Xi[6]=r1i-r3i;
    }
    {
        float r0r=qr[0]+qr[2], r0i=qi[0]+qi[2];
        float r1r=qr[0]-qr[2], r1i=qi[0]-qi[2];
        float r2r=qr[1]+qr[3], r2i=qi[1]+qi[3];
        float t3r=qr[1]-qr[3], t3i=qi[1]-qi[3];
        float r3r=t3i, r3i=-t3r;
        Xr[1]=r0r+r2r; Xi[1]=r0i+r2i;
        Xr[3]=r1r+r3r; Xi[3]=r1i+r3i;
        Xr[5]=r0r-r2r; Xi[5]=r0i-r2i;
        Xr[7]=r1r-r3r; Xi[7]=r1i-r3i;
    }
    float2 w = g_tw[m * p];
    float wjr = 1.f, wji = 0.f;
    int o = ((m * p) << 3) + r;
    dr[o] = Xr[0]; di[o] = Xi[0];
    #pragma unroll
    for (int j = 1; j < 8; j++) {
        float nr = wjr * w.x - wji * w.y;
        wji = wji * w.x + wjr * w.y;
        wjr = nr;
        dr[o + j * m] = Xr[j] * wjr - Xi[j] * wji;
        di[o + j * m] = Xi[j] * wjr + Xr[j] * wji;
    }
}

// ---- radix-8 butterfly on register inputs (m=1, butterfly index i=tid) ----
__device__ __forceinline__ void r8_reg_m1(const float* xr, const float* xi,
                                          float* __restrict__ dr,
                                          float* __restrict__ di) {
    const float Cq = 0.70710678118654752440f;
    int i = threadIdx.x;
    float pr_[4], pi_[4], qr[4], qi[4];
    #pragma unroll
    for (int s = 0; s < 4; s++) {
        pr_[s] = xr[s] + xr[s+4]; pi_[s] = xi[s] + xi[s+4];
        qr[s]  = xr[s] - xr[s+4]; qi[s]  = xi[s] - xi[s+4];
    }
    { float a=qr[1], b=qi[1]; qr[1] = Cq*(a+b); qi[1] = Cq*(b-a); }
    { float a=qr[2], b=qi[2]; qr[2] = b;        qi[2] = -a;       }
    { float a=qr[3], b=qi[3]; qr[3] = Cq*(b-a); qi[3] = -Cq*(a+b); }
    float Xr[8], Xi[8];
    {
        float r0r=pr_[0]+pr_[2], r0i=pi_[0]+pi_[2];
        float r1r=pr_[0]-pr_[2], r1i=pi_[0]-pi_[2];
        float r2r=pr_[1]+pr_[3], r2i=pi_[1]+pi_[3];
        float t3r=pr_[1]-pr_[3], t3i=pi_[1]-pi_[3];
        float r3r=t3i, r3i=-t3r;
        Xr[0]=r0r+r2r; Xi[0]=r0i+r2i;
        Xr[2]=r1r+r3r; Xi[2]=r1i+r3i;
        Xr[4]=r0r-r2r; Xi[4]=r0i-r2i;
        Xr[6]=r1r-r3r; Xi[6]=r1i-r3i;
    }
    {
        float r0r=qr[0]+qr[2], r0i=qi[0]+qi[2];
        float r1r=qr[0]-qr[2], r1i=qi[0]-qi[2];
        float r2r=qr[1]+qr[3], r2i=qi[1]+qi[3];
        float t3r=qr[1]-qr[3], t3i=qi[1]-qi[3];
        float r3r=t3i, r3i=-t3r;
        Xr[1]=r0r+r2r; Xi[1]=r0i+r2i;
        Xr[3]=r1r+r3r; Xi[3]=r1i+r3i;
        Xr[5]=r0r-r2r; Xi[5]=r0i-r2i;
        Xr[7]=r1r-r3r; Xi[7]=r1i-r3i;
    }
    float2 w = g_tw[i];
    float wjr = 1.f, wji = 0.f;
    int o = i << 3;
    dr[o] = Xr[0]; di[o] = Xi[0];
    #pragma unroll
    for (int j = 1; j < 8; j++) {
        float nr = wjr * w.x - wji * w.y;
        wji = wji * w.x + wjr * w.y;
        wjr = nr;
        dr[o + j] = Xr[j] * wjr - Xi[j] * wji;
        di[o + j] = Xi[j] * wjr + Xr[j] * wji;
    }
}

// ---------------- full radix-8 FFT (generic; used by kfft) ----------------
__device__ __forceinline__ void fft2048_r8(float*& sr, float*& si, float*& dr, float*& di) {
    #pragma unroll
    for (int lm = 0; lm < 9; lm += 3) {
        r8_stage(sr, si, dr, di, lm);
        __syncthreads();
        float* tp; tp=sr;sr=dr;dr=tp; tp=si;si=di;di=tp;
    }
    #pragma unroll
    for (int q = 0; q < 2; q++) {
        int r = threadIdx.x + (q << 8);
        float a0r=sr[r],      a0i=si[r];
        float a1r=sr[r+512],  a1i=si[r+512];
        float a2r=sr[r+1024], a2i=si[r+1024];
        float a3r=sr[r+1536], a3i=si[r+1536];
        float r0r=a0r+a2r, r0i=a0i+a2i;
        float r1r=a0r-a2r, r1i=a0i-a2i;
        float r2r=a1r+a3r, r2i=a1i+a3i;
        float t3r=a1r-a3r, t3i=a1i-a3i;
        float r3r=t3i, r3i=-t3r;
        dr[r]      = r0r+r2r; di[r]      = r0i+r2i;
        dr[r+512]  = r1r+r3r; di[r+512]  = r1i+r3i;
        dr[r+1024] = r0r-r2r; di[r+1024] = r0i-r2i;
        dr[r+1536] = r1r-r3r; di[r+1536] = r1i-r3i;
    }
    __syncthreads();
    float* tp; tp=sr;sr=dr;dr=tp; tp=si;si=di;di=tp;
}

// ---------------- FFT of kernel rows ----------------
__global__ void __launch_bounds__(256) k_kfft() {
    __shared__ float bAr[2048], bAi[2048], bBr[2048], bBi[2048];
    int tid = threadIdx.x;
    int h0 = blockIdx.x * 2, h1 = h0 + 1;
    #pragma unroll
    for (int qq = 0; qq < 8; qq++) {
        int idx = tid + (qq << 8);
        bAr[idx] = g_ktime[h0 * 2048 + idx];
        bAi[idx] = g_ktime[h1 * 2048 + idx];
    }
    __syncthreads();
    float *sr = bAr, *si = bAi, *dr = bBr, *di = bBi;
    fft2048_r8(sr, si, dr, di);
    #pragma unroll
    for (int qq = 0; qq < 8; qq++) {
        int f = tid + (qq << 8);
        int fr2 = (2048 - f) & 2047;
        float ur = sr[f],  ui = si[f];
        float vr = sr[fr2], vi = -si[fr2];
        g_khr[h0 * 2048 + f] = 0.5f * (ur + vr);
        g_khi[h0 * 2048 + f] = 0.5f * (ui + vi);
        g_khr[h1 * 2048 + f] = 0.5f * (ui - vi);
        g_khi[h1 * 2048 + f] = -0.5f * (ur - vr);
    }
}

// ---------------- main conv: fused pointwise+inv-stage1, fused epilogue, fp16 out ----------------
__global__ void __launch_bounds__(256) k_conv(const float* __restrict__ Dp) {
    __shared__ float bAr[2048], bAi[2048], bBr[2048], bBi[2048];
    const float Cq = 0.70710678118654752440f;
    int tid = threadIdx.x;
    int h  = blockIdx.x;
    int pb = blockIdx.y;
    const float* za = g_z + ((size_t)(2 * pb) * Hh + h) * Ll;
    const float* zb = za + (size_t)Hh * Ll;
    float ra[4], rb[4];
    #pragma unroll
    for (int qq = 0; qq < 4; qq++) {
        int idx = tid + (qq << 8);
        ra[qq] = za[idx]; rb[qq] = zb[idx];
        bAr[idx] = ra[qq]; bAi[idx] = rb[qq];
    }
    __syncthreads();

    // ---- forward stage 1 (m=1): inputs s>=4 are the zero pad ----
    {
        float xr[4], xi[4];
        #pragma unroll
        for (int s = 0; s < 4; s++) { xr[s] = bAr[tid + (s << 8)]; xi[s] = bAi[tid + (s << 8)]; }
        float qr[4], qi[4];
        #pragma unroll
        for (int s = 0; s < 4; s++) { qr[s] = xr[s]; qi[s] = xi[s]; }
        { float a=qr[1], b=qi[1]; qr[1] = Cq*(a+b); qi[1] = Cq*(b-a); }
        { float a=qr[2], b=qi[2]; qr[2] = b;        qi[2] = -a;       }
        { float a=qr[3], b=qi[3]; qr[3] = Cq*(b-a); qi[3] = -Cq*(a+b); }
        float Xr[8], Xi[8];
        {
            float r0r=xr[0]+xr[2], r0i=xi[0]+xi[2];
            float r1r=xr[0]-xr[2], r1i=xi[0]-xi[2];
            float r2r=xr[1]+xr[3], r2i=xi[1]+xi[3];
            float t3r=xr[1]-xr[3], t3i=xi[1]-xi[3];
            float r3r=t3i, r3i=-t3r;
            Xr[0]=r0r+r2r; Xi[0]=r0i+r2i;
            Xr[2]=r1r+r3r; Xi[2]=r1i+r3i;
            Xr[4]=r0r-r2r; Xi[4]=r0i-r2i;
            Xr[6]=r1r-r3r; Xi[6]=r1i-r3i;
        }
        {
            float r0r=qr[0]+qr[2], r0i=qi[0]+qi[2];
            float r1r=qr[0]-qr[2], r1i=qi[0]-qi[2];
            float r2r=qr[1]+qr[3], r2i=qi[1]+qi[3];
            float t3r=qr[1]-qr[3], t3i=qi[1]-qi[3];
            float r3r=t3i, r3i=-t3r;
            Xr[1]=r0r+r2r; Xi[1]=r0i+r2i;
            Xr[3]=r1r+r3r; Xi[3]=r1i+r3i;
            Xr[5]=r0r-r2r; Xi[5]=r0i-r2i;
            Xr[7]=r1r-r3r; Xi[7]=r1i-r3i;
        }
        float2 w = g_tw[tid];
        float wjr = 1.f, wji = 0.f;
        int o = tid << 3;
        bBr[o] = Xr[0]; bBi[o] = Xi[0];
        #pragma unroll
        for (int j = 1; j < 8; j++) {
            float nr = wjr * w.x - wji * w.y;
            wji = wji * w.x + wjr * w.y;
            wjr = nr;
            bBr[o + j] = Xr[j] * wjr - Xi[j] * wji;
            bBi[o + j] = Xi[j] * wjr + Xr[j] * wji;
        }
    }
    __syncthreads();
    r8_stage(bBr, bBi, bAr, bAi, 3); __syncthreads();
    r8_stage(bAr, bAi, bBr, bBi, 6); __syncthreads();

    // ---- fused: forward final r4 + spectrum multiply + inverse stage-1 -> bA ----
    {
        const float* khr = g_khr + h * 2048;
        const float* khi = g_khi + h * 2048;
        const float inv = 1.0f / 2048.0f;
        float xr[8], xi[8];   // positions tid + s*256
        #pragma unroll
        for (int q = 0; q < 2; q++) {
            int r = tid + (q << 8);
            float a0r=bBr[r],      a0i=bBi[r];
            float a1r=bBr[r+512],  a1i=bBi[r+512];
            float a2r=bBr[r+1024], a2i=bBi[r+1024];
            float a3r=bBr[r+1536], a3i=bBi[r+1536];
            float r0r=a0r+a2r, r0i=a0i+a2i;
            float r1r=a0r-a2r, r1i=a0i-a2i;
            float r2r=a1r+a3r, r2i=a1i+a3i;
            float t3r=a1r-a3r, t3i=a1i-a3i;
            float r3r=t3i, r3i=-t3r;
            float Xr4[4], Xi4[4];
            Xr4[0]=r0r+r2r; Xi4[0]=r0i+r2i;
            Xr4[1]=r1r+r3r; Xi4[1]=r1i+r3i;
            Xr4[2]=r0r-r2r; Xi4[2]=r0i-r2i;
            Xr4[3]=r1r-r3r; Xi4[3]=r1i-r3i;
            #pragma unroll
            for (int j = 0; j < 4; j++) {
                int f = r + j * 512;
                int s = 2 * j + q;
                float kr = khr[f], ki = khi[f];
                float ar = Xr4[j], ai = Xi4[j];
                xr[s] = (ar * kr - ai * ki) * inv;
                xi[s] = -(ar * ki + ai * kr) * inv;
            }
        }
        __syncthreads();           // bB reads done before bA overwrite? bA is dest, safe; sync for bB reuse below
        r8_reg_m1(xr, xi, bAr, bAi);
    }
    __syncthreads();

    // ---- inverse FFT remaining stages ----
    r8_stage(bAr, bAi, bBr, bBi, 3); __syncthreads();
    r8_stage(bBr, bBi, bAr, bAi, 6); __syncthreads();

    // ---- inverse final r4 (outputs [0,1024) only) fused with epilogue, fp16 store ----
    float Dh = Dp[h];
    __half* ya = g_yg + ((size_t)(2 * pb) * Hh + h) * Ll;
    __half* yb = ya + (size_t)Hh * Ll;
    #pragma unroll
    for (int q = 0; q < 2; q++) {
        int r = tid + (q << 8);
        float a0r=bAr[r],      a0i=bAi[r];
        float a1r=bAr[r+512],  a1i=bAi[r+512];
        float a2r=bAr[r+1024], a2i=bAi[r+1024];
        float a3r=bAr[r+1536], a3i=bAi[r+1536];
        float r0r=a0r+a2r, r0i=a0i+a2i;
        float r1r=a0r-a2r, r1i=a0i-a2i;
        float r2r=a1r+a3r, r2i=a1i+a3i;
        float t3r=a1r-a3r, t3i=a1i-a3i;
        float r3r=t3i, r3i=-t3r;
        float o1r = r0r + r2r, o1i = r0i + r2i;
        float o2r = r1r + r3r, o2i = r1i + r3i;
        float v1 = o1r  + Dh * ra[q];
        float v2 = -o1i + Dh * rb[q];
        float v3 = o2r  + Dh * ra[q + 2];
        float v4 = -o2i + Dh * rb[q + 2];
        ya[r]       = __float2half_rn(geluf(v1));
        yb[r]       = __float2half_rn(geluf(v2));
        ya[r + 512] = __float2half_rn(geluf(v3));
        yb[r + 512] = __float2half_rn(geluf(v4));
    }
}

// ---------------- GEMM1: g = gate(out_w@yg + out_b + x1), fp16 out, ping-pong smem ----------------
__global__ void __launch_bounds__(256) k_gemm1(const float* __restrict__ bias,
                                               const __half* __restrict__ X,
                                               const float* __restrict__ resid,
                                               __half* __restrict__ Yout) {
    __shared__ __half Ws[2][128][24];
    __shared__ __half Xs[2][16][136];
    int l0 = blockIdx.x * 128;
    int o0 = blockIdx.y * 128;
    int b  = blockIdx.z;
    int tid = threadIdx.x;
    int lane = tid & 31, warp = tid >> 5;
    int wm = warp & 1, wn = warp >> 1;

    float acc[4][4][4];
    #pragma unroll
    for (int m = 0; m < 4; m++)
        #pragma unroll
        for (int n = 0; n < 4; n++)
            #pragma unroll
            for (int c = 0; c < 4; c++) acc[m][n][c] = 0.f;

    int wo = tid >> 1, wk = (tid & 1) * 8;
    const __half* whp = &g_wh[(size_t)(o0 + wo) * 256 + wk];
    int xk = tid >> 4, xl = (tid & 15) * 8;
    const __half* xpb = &X[((size_t)b * Hh + xk) * Ll + l0 + xl];

    uint4 wv = *(const uint4*)(whp);
    uint4 xv = *(const uint4*)(xpb);
    *(uint4*)&Ws[0][wo][wk] = wv;
    *(uint4*)&Xs[0][xk][xl] = xv;
    __syncthreads();

    #pragma unroll 1
    for (int it = 0; it < 16; it++) {
        int cur = it & 1;
        if (it < 15) {
            int kk = (it + 1) * 16;
            wv = *(const uint4*)(whp + kk);
            xv = *(const uint4*)(xpb + (size_t)kk * Ll);
        }
        int k0 = (lane & 3) * 2;
        int nb = wn * 32 + (lane >> 2);
        unsigned bf[4][2];
        #pragma unroll
        for (int nt = 0; nt < 4; nt++) {
            int n = nb + nt * 8;
            bf[nt][0] = pckh(Xs[cur][k0][n],     Xs[cur][k0 + 1][n]);
            bf[nt][1] = pckh(Xs[cur][k0 + 8][n], Xs[cur][k0 + 9][n]);
        }
        #pragma unroll
        for (int m = 0; m < 4; m++) {
            int r = wm * 64 + m * 16 + (lane >> 2);
            unsigned a0 = *(const unsigned*)&Ws[cur][r][k0];
            unsigned a1 = *(const unsigned*)&Ws[cur][r + 8][k0];
            unsigned a2 = *(const unsigned*)&Ws[cur][r][k0 + 8];
            unsigned a3 = *(const unsigned*)&Ws[cur][r + 8][k0 + 8];
            #pragma unroll
            for (int nt = 0; nt < 4; nt++)
                asm volatile(
                    "mma.sync.aligned.m16n8k16.row.col.f32.f16.f16.f32 "
                    "{%0,%1,%2,%3}, {%4,%5,%6,%7}, {%8,%9}, {%0,%1,%2,%3};"
                    : "+f"(acc[m][nt][0]), "+f"(acc[m][nt][1]),
                      "+f"(acc[m][nt][2]), "+f"(acc[m][nt][3])
                    : "r"(a0), "r"(a1), "r"(a2), "r"(a3),
                      "r"(bf[nt][0]), "r"(bf[nt][1]));
        }
        if (it < 15) {
            *(uint4*)&Ws[1 - cur][wo][wk] = wv;
            *(uint4*)&Xs[1 - cur][xk][xl] = xv;
        }
        __syncthreads();
    }

    #pragma unroll
    for (int m = 0; m < 4; m++) {
        int o = o0 + wm * 64 + m * 16 + (lane >> 2);
        float bo0 = bias[o], bo8 = bias[o + 8];
        #pragma unroll
        for (int nt = 0; nt < 4; nt++) {
            int lc = l0 + wn * 32 + nt * 8 + (lane & 3) * 2;
            size_t base0 = ((size_t)b * Hh + o) * Ll + lc;
            size_t base8 = base0 + 8 * (size_t)Ll;
            float2 r0 = *(const float2*)&resid[base0];
            float2 r8 = *(const float2*)&resid[base8];
            __half q0 = __float2half_rn(gatef(acc[m][nt][0] + bo0 + r0.x));
            __half q1 = __float2half_rn(gatef(acc[m][nt][1] + bo0 + r0.y));
            __half q2 = __float2half_rn(gatef(acc[m][nt][2] + bo8 + r8.x));
            __half q3 = __float2half_rn(gatef(acc[m][nt][3] + bo8 + r8.y));
            *(unsigned*)&Yout[base0] = pckh(q0, q1);
            *(unsigned*)&Yout[base8] = pckh(q2, q3);
        }
    }
}

// ---------------- GEMM2/3: out = lin@g + b (+x1 if addres), ping-pong smem ----------------
__global__ void __launch_bounds__(256) k_gemm2(int widx,
                                               const float* __restrict__ bias,
                                               const __half* __restrict__ X,
                                               const float* __restrict__ resid,
                                               float* __restrict__ out,
                                               int addres) {
    __shared__ __half Ws[2][128][24];
    __shared__ __half Xs[2][16][136];
    int l0 = blockIdx.x * 128;
    int o0 = blockIdx.y * 128;
    int b  = blockIdx.z;
    int tid = threadIdx.x;
    int lane = tid & 31, warp = tid >> 5;
    int wm = warp & 1, wn = warp >> 1;

    float acc[4][4][4];
    #pragma unroll
    for (int m = 0; m < 4; m++)
        #pragma unroll
        for (int n = 0; n < 4; n++)
            #pragma unroll
            for (int c = 0; c < 4; c++) acc[m][n][c] = 0.f;

    int wo = tid >> 1, wk = (tid & 1) * 8;
    const __half* whp = &g_wh[(size_t)widx * Hh * Hh + (size_t)(o0 + wo) * 256 + wk];
    int xk = tid >> 4, xl = (tid & 15) * 8;
    const __half* xpb = &X[((size_t)b * Hh + xk) * Ll + l0 + xl];

    uint4 wv = *(const uint4*)(whp);
    uint4 xv = *(const uint4*)(xpb);
    *(uint4*)&Ws[0][wo][wk] = wv;
    *(uint4*)&Xs[0][xk][xl] = xv;
    __syncthreads();

    #pragma unroll 1
    for (int it = 0; it < 16; it++) {
        int cur = it & 1;
        if (it < 15) {
            int kk = (it + 1) * 16;
            wv = *(const uint4*)(whp + kk);
            xv = *(const uint4*)(xpb + (size_t)kk * Ll);
        }
        int k0 = (lane & 3) * 2;
        int nb = wn * 32 + (lane >> 2);
        unsigned bf[4][2];
        #pragma unroll
        for (int nt = 0; nt < 4; nt++) {
            int n = nb + nt * 8;
            bf[nt][0] = pckh(Xs[cur][k0][n],     Xs[cur][k0 + 1][n]);
            bf[nt][1] = pckh(Xs[cur][k0 + 8][n], Xs[cur][k0 + 9][n]);
        }
        #pragma unroll
        for (int m = 0; m < 4; m++) {
            int r = wm * 64 + m * 16 + (lane >> 2);
            unsigned a0 = *(const unsigned*)&Ws[cur][r][k0];
            unsigned a1 = *(const unsigned*)&Ws[cur][r + 8][k0];
            unsigned a2 = *(const unsigned*)&Ws[cur][r][k0 + 8];
            unsigned a3 = *(const unsigned*)&Ws[cur][r + 8][k0 + 8];
            #pragma unroll
            for (int nt = 0; nt < 4; nt++)
                asm volatile(
                    "mma.sync.aligned.m16n8k16.row.col.f32.f16.f16.f32 "
                    "{%0,%1,%2,%3}, {%4,%5,%6,%7}, {%8,%9}, {%0,%1,%2,%3};"
                    : "+f"(acc[m][nt][0]), "+f"(acc[m][nt][1]),
                      "+f"(acc[m][nt][2]), "+f"(acc[m][nt][3])
                    : "r"(a0), "r"(a1), "r"(a2), "r"(a3),
                      "r"(bf[nt][0]), "r"(bf[nt][1]));
        }
        if (it < 15) {
            *(uint4*)&Ws[1 - cur][wo][wk] = wv;
            *(uint4*)&Xs[1 - cur][xk][xl] = xv;
        }
        __syncthreads();
    }

    #pragma unroll
    for (int m = 0; m < 4; m++) {
        int o = o0 + wm * 64 + m * 16 + (lane >> 2);
        float bo0 = bias[o], bo8 = bias[o + 8];
        #pragma unroll
        for (int nt = 0; nt < 4; nt++) {
            int lc = l0 + wn * 32 + nt * 8 + (lane & 3) * 2;
            size_t base0 = ((size_t)b * Hh + o) * Ll + lc;
            size_t base8 = base0 + 8 * (size_t)Ll;
            float v0 = acc[m][nt][0] + bo0;
            float v1 = acc[m][nt][1] + bo0;
            float v2 = acc[m][nt][2] + bo8;
            float v3 = acc[m][nt][3] + bo8;
            if (addres) {
                float2 r0 = *(const float2*)&resid[base0];
                float2 r8 = *(const float2*)&resid[base8];
                v0 += r0.x; v1 += r0.y; v2 += r8.x; v3 += r8.y;
            }
            *(float2*)&out[base0] = make_float2(v0, v1);
            *(float2*)&out[base8] = make_float2(v2, v3);
        }
    }
}

// ---------------- launch ----------------
extern "C" void kernel_launch(void* const* d_in, const int* in_sizes, int n_in,
                              void* d_out, int out_size) {
    const float* x      = (const float*)d_in[0];
    const int*   t      = (const int*)  d_in[1];
    const float* ada_w  = (const float*)d_in[2];
    const float* ada_b  = (const float*)d_in[3];
    const float* norm_w = (const float*)d_in[4];
    const float* norm_b = (const float*)d_in[5];
    const float* log_dt = (const float*)d_in[6];
    const float* A_re   = (const float*)d_in[7];
    const float* A_im   = (const float*)d_in[8];
    const float* C_re   = (const float*)d_in[9];
    const float* C_im   = (const float*)d_in[10];
    const float* Dp     = (const float*)d_in[11];
    const float* out_w  = (const float*)d_in[12];
    const float* out_b  = (const float*)d_in[13];
    const float* lin1_w = (const float*)d_in[14];
    const float* lin1_b = (const float*)d_in[15];
    const float* lin2_w = (const float*)d_in[16];
    const float* lin2_b = (const float*)d_in[17];
    float* out = (float*)d_out;
    (void)in_sizes; (void)n_in; (void)out_size;

    float *p_x1, *p_z;
    __half *p_yg;
    cudaGetSymbolAddress((void**)&p_x1, g_x1);
    cudaGetSymbolAddress((void**)&p_z,  g_z);
    cudaGetSymbolAddress((void**)&p_yg, g_yg);

    k_prep<<<836, 256>>>(t, out_w, lin1_w, lin2_w);
    k_ssm<<<256, 256>>>(log_dt, A_re, A_im, C_re, C_im);
    k_kfft<<<128, 256>>>();
    k_ada_gemm<<<dim3(64, 8), 256>>>(ada_w);
    k_ada_reduce<<<512, 256>>>(ada_b);
    k_adaln<<<Bb * Hh, 256>>>(x);
    k_chanln<<<dim3(64, 32), 256>>>(norm_w, norm_b);
    k_conv<<<dim3(256, 32), 256>>>(Dp);
    k_gemm1<<<dim3(8, 2, 64), 256>>>(out_b, p_yg, p_x1, (__half*)p_z);
    k_gemm2<<<dim3(8, 2, 64), 256>>>(1, lin1_b, (const __half*)p_z, p_x1, out, 1);
    k_gemm2<<<dim3(8, 2, 64), 256>>>(2, lin2_b, (const __half*)p_z, p_x1, out + BHL, 0);
}

// round 15
// speedup vs baseline: 1.5309x; 1.0120x over previous
#include <cuda_runtime.h>
#include <cuda_fp16.h>
#include <math.h>

#define Bb 64
#define Hh 256
#define Ll 1024
#define Nn 64
#define BHL (Bb*Hh*Ll)

// ---------------- scratch (device globals; no allocs allowed) ----------------
__device__ float g_x1[BHL];        // post-AdaLN x (residual source)
__device__ float g_z[BHL];         // z (pre-norm out); low half reused as fp16 gate g
__device__ __half g_yg[BHL];       // gelu(conv out + D*z), fp16
__device__ float g_ss[Bb*2048];    // scale(0:1024) / shift(1024:2048) per batch
__device__ float g_semb[Bb*1024];  // silu(sin/cos emb)
__device__ float g_ktime[Hh*2048]; // time-domain bidirectional kernel
__device__ float g_khr[Hh*2048];   // full complex spectrum of k (re)
__device__ float g_khi[Hh*2048];   // (im)
__device__ float g_part[8*Bb*2048];// ada split-K partials
__device__ float2 g_tw[1024];      // FFT twiddles exp(-i*pi*k/1024)
__device__ __half g_wh[3*Hh*Hh];   // fp16 weights (out_w, lin1_w, lin2_w)

// ---------------- helpers ----------------
__device__ __forceinline__ float geluf(float x) {
    return 0.5f * x * (1.0f + erff(x * 0.70710678118654752440f));
}
__device__ __forceinline__ float gatef(float x) {
    float t  = __expf(-fmaxf(x, -30.0f));
    float t2 = t * t;
    return ((1.0f - t2) / (1.0f + t2)) * (1.0f / (1.0f + t));
}
__device__ __forceinline__ unsigned pckh(__half a, __half b) {
    __half2 t; t.x = a; t.y = b;
    return *reinterpret_cast<unsigned*>(&t);
}

// ---------------- fused prep: twiddles + sinusoidal emb + weight fp16 ----------------
__global__ void __launch_bounds__(256) k_prep(const int* __restrict__ t,
                                              const float* __restrict__ w0,
                                              const float* __restrict__ w1,
                                              const float* __restrict__ w2) {
    int bid = blockIdx.x;
    int tid = threadIdx.x;
    if (bid < 4) {                       // twiddle table
        int i = bid * 256 + tid;
        float ang = -3.14159265358979323846f * (float)i * (1.0f / 1024.0f);
        float sn, cs; sincosf(ang, &sn, &cs);
        g_tw[i] = make_float2(cs, sn);
    } else if (bid < 68) {               // sinusoidal embedding + silu
        int b = bid - 4;
        float tf = (float)t[b];
        const float cfr = (float)(-9.210340371976184 / 511.0);
        #pragma unroll
        for (int r = 0; r < 4; r++) {
            int i = tid + (r << 8);
            float v;
            if (i < 512) v = sinf(tf * expf((float)i * cfr));
            else         v = cosf(tf * expf((float)(i - 512) * cfr));
            float sg = 1.0f / (1.0f + expf(-v));
            g_semb[b * 1024 + i] = v * sg;
        }
    } else {                             // weight fp16 conversion
        int i = (bid - 68) * 256 + tid;  // 0 .. 3*65536-1
        int m = i >> 16, r = i & 65535;
        float v = (m == 0) ? w0[r] : (m == 1) ? w1[r] : w2[r];
        g_wh[i] = __float2half_rn(v);
    }
}

// ---------------- emb @ ada_w.T  (split-K partials) ----------------
__global__ void __launch_bounds__(256) k_ada_gemm(const float* __restrict__ W) {
    __shared__ float Ws[64][32];
    __shared__ float Eb[64][68];   // [k][b], padded
    int o0 = blockIdx.x * 32;
    int kc = blockIdx.y;
    int tid = threadIdx.x;
    int o  = tid & 31;
    int bg = tid >> 5;
    float acc[8];
    #pragma unroll
    for (int j = 0; j < 8; j++) acc[j] = 0.f;

    for (int kk = kc * 128; kk < kc * 128 + 128; kk += 64) {
        {
            int oo = tid >> 3;
            int kq = tid & 7;
            const float* src = &W[(size_t)(o0 + oo) * 1024 + kk + kq * 8];
            float4 a = *(const float4*)(src);
            float4 c = *(const float4*)(src + 4);
            int kb = kq * 8;
            Ws[kb+0][oo] = a.x; Ws[kb+1][oo] = a.y; Ws[kb+2][oo] = a.z; Ws[kb+3][oo] = a.w;
            Ws[kb+4][oo] = c.x; Ws[kb+5][oo] = c.y; Ws[kb+6][oo] = c.z; Ws[kb+7][oo] = c.w;
        }
        #pragma unroll
        for (int r = 0; r < 16; r++) {
            int e = tid + (r << 8);
            int bq = e >> 6, k = e & 63;
            Eb[k][bq] = g_semb[bq * 1024 + kk + k];
        }
        __syncthreads();
        #pragma unroll 8
        for (int k = 0; k < 64; k++) {
            float wv = Ws[k][o];
            float4 e0 = *(const float4*)&Eb[k][bg * 8];
            float4 e1 = *(const float4*)&Eb[k][bg * 8 + 4];
            acc[0] += e0.x * wv; acc[1] += e0.y * wv;
            acc[2] += e0.z * wv; acc[3] += e0.w * wv;
            acc[4] += e1.x * wv; acc[5] += e1.y * wv;
            acc[6] += e1.z * wv; acc[7] += e1.w * wv;
        }
        __syncthreads();
    }
    #pragma unroll
    for (int j = 0; j < 8; j++)
        g_part[((size_t)kc * 64 + bg * 8 + j) * 2048 + o0 + o] = acc[j];
}

__global__ void __launch_bounds__(256) k_ada_reduce(const float* __restrict__ bias) {
    int idx = blockIdx.x * 256 + threadIdx.x;
    int b = idx >> 11, o = idx & 2047;
    float s = bias[o];
    #pragma unroll
    for (int kc = 0; kc < 8; kc++)
        s += g_part[((size_t)kc * 64 + b) * 2048 + o];
    g_ss[b * 2048 + o] = s;
}

// ---------------- AdaLayerNorm over L ----------------
__global__ void __launch_bounds__(256) k_adaln(const float* __restrict__ x) {
    int bh = blockIdx.x;
    int b = bh >> 8;
    int tid = threadIdx.x;
    const float4* xr = (const float4*)(x + (size_t)bh * 1024);
    float4 v = xr[tid];
    float s = v.x + v.y + v.z + v.w;
    float q = v.x*v.x + v.y*v.y + v.z*v.z + v.w*v.w;
    #pragma unroll
    for (int o = 16; o; o >>= 1) {
        s += __shfl_down_sync(0xffffffffu, s, o);
        q += __shfl_down_sync(0xffffffffu, q, o);
    }
    __shared__ float as_[8], aq_[8];
    if ((tid & 31) == 0) { as_[tid >> 5] = s; aq_[tid >> 5] = q; }
    __syncthreads();
    float S = 0.f, Q = 0.f;
    #pragma unroll
    for (int i = 0; i < 8; i++) { S += as_[i]; Q += aq_[i]; }
    float m  = S * (1.0f / 1024.0f);
    float va = Q * (1.0f / 1024.0f) - m * m;
    float rs = rsqrtf(va + 1e-5f);
    const float4* sc = (const float4*)(g_ss + b * 2048);
    const float4* sh = (const float4*)(g_ss + b * 2048 + 1024);
    float4 a = sc[tid], d = sh[tid];
    float4 o4;
    o4.x = (v.x - m) * rs * (1.0f + a.x) + d.x;
    o4.y = (v.y - m) * rs * (1.0f + a.y) + d.y;
    o4.z = (v.z - m) * rs * (1.0f + a.z) + d.z;
    o4.w = (v.w - m) * rs * (1.0f + a.w) + d.w;
    ((float4*)(g_x1 + (size_t)bh * 1024))[tid] = o4;
}

// ---------------- channel LayerNorm over H ----------------
__global__ void __launch_bounds__(256) k_chanln(const float* __restrict__ nw,
                                                const float* __restrict__ nb) {
    int b = blockIdx.x;
    int l0 = blockIdx.y * 32;
    int tid = threadIdx.x;
    int lx = tid & 31, hp = tid >> 5;
    float v[32];
    float s = 0.f, q = 0.f;
    const float* base = g_x1 + ((size_t)b * Hh) * Ll + l0 + lx;
    #pragma unroll 8
    for (int k = 0; k < 32; k++) {
        float xv = base[(size_t)(hp * 32 + k) * Ll];
        v[k] = xv; s += xv; q += xv * xv;
    }
    __shared__ float ps[8][32], pq[8][32];
    __shared__ float mean_[32], rstd_[32];
    ps[hp][lx] = s; pq[hp][lx] = q;
    __syncthreads();
    if (tid < 32) {
        float S = 0.f, Q = 0.f;
        #pragma unroll
        for (int p = 0; p < 8; p++) { S += ps[p][tid]; Q += pq[p][tid]; }
        float m  = S * (1.0f / 256.0f);
        float va = Q * (1.0f / 256.0f) - m * m;
        mean_[tid] = m; rstd_[tid] = rsqrtf(va + 1e-5f);
    }
    __syncthreads();
    float m = mean_[lx], r = rstd_[lx];
    float* zb = g_z + ((size_t)b * Hh) * Ll + l0 + lx;
    #pragma unroll 8
    for (int k = 0; k < 32; k++) {
        int h = hp * 32 + k;
        zb[(size_t)h * Ll] = (v[k] - m) * r * nw[h] + nb[h];
    }
}

// ---------------- SSM kernel: base sincos + 3-step complex recurrence ----------------
__global__ void __launch_bounds__(256) k_ssm(const float* __restrict__ log_dt,
                                             const float* __restrict__ A_re,
                                             const float* __restrict__ A_im,
                                             const float* __restrict__ C_re,
                                             const float* __restrict__ C_im) {
    __shared__ float pre[8][64]; // dre, dim, c0r, c0i, c1r, c1i, dAr, dAi
    int h = blockIdx.x, tid = threadIdx.x;
    if (tid < 64) {
        int n = tid;
        float dt  = expf(log_dt[h]);
        float are = -expf(A_re[h * 64 + n]);
        float aim = A_im[h * 64 + n];
        float dre = dt * are, dim = dt * aim;
        float er = expf(dre);
        float sn, cs; sincosf(dim, &sn, &cs);
        float dAr = er * cs, dAi = er * sn;
        float numr = dAr - 1.0f, numi = dAi;
        float den = are * are + aim * aim;
        float fr = (numr * are + numi * aim) / den;
        float fi = (numi * are - numr * aim) / den;
        float c0re = C_re[h * 64 + n],             c0im = C_im[h * 64 + n];
        float c1re = C_re[Hh * 64 + h * 64 + n],   c1im = C_im[Hh * 64 + h * 64 + n];
        pre[0][n] = dre; pre[1][n] = dim;
        pre[2][n] = c0re * fr - c0im * fi; pre[3][n] = c0re * fi + c0im * fr;
        pre[4][n] = c1re * fr - c1im * fi; pre[5][n] = c1re * fi + c1im * fr;
        pre[6][n] = dAr; pre[7][n] = dAi;
    }
    __syncthreads();
    int l0 = tid * 4;
    float lf = (float)l0;
    float k0[4] = {0.f, 0.f, 0.f, 0.f};
    float k1[4] = {0.f, 0.f, 0.f, 0.f};
    #pragma unroll 2
    for (int n = 0; n < 64; n++) {
        float pr = pre[0][n] * lf, pi = pre[1][n] * lf;
        float e = expf(pr);
        float sn, cs; sincosf(pi, &sn, &cs);
        float vr = e * cs, vi = e * sn;
        float sr_ = pre[6][n], si_ = pre[7][n];
        float c0r = pre[2][n], c0i = pre[3][n];
        float c1r = pre[4][n], c1i = pre[5][n];
        #pragma unroll
        for (int s = 0; s < 4; s++) {
            k0[s] += c0r * vr - c0i * vi;
            k1[s] += c1r * vr - c1i * vi;
            if (s < 3) {
                float nvr = vr * sr_ - vi * si_;
                vi = vi * sr_ + vr * si_;
                vr = nvr;
            }
        }
    }
    *(float4*)&g_ktime[h * 2048 + l0] =
        make_float4(2.f*k0[0], 2.f*k0[1], 2.f*k0[2], 2.f*k0[3]);
    *(float4*)&g_ktime[h * 2048 + 2044 - l0] =
        make_float4(2.f*k1[3], 2.f*k1[2], 2.f*k1[1], 2.f*k1[0]);
}

// ---------------- generic radix-8 Stockham stage (256 threads, N=2048) ----------------
__device__ __forceinline__ void r8_stage(const float* __restrict__ sr,
                                         const float* __restrict__ si,
                                         float* __restrict__ dr,
                                         float* __restrict__ di, int lm) {
    const float Cq = 0.70710678118654752440f;
    const int m = 1 << lm;
    int i = threadIdx.x;
    int p = i >> lm;
    int r = i & (m - 1);
    float xr[8], xi[8];
    #pragma unroll
    for (int s = 0; s < 8; s++) { xr[s] = sr[i + (s << 8)]; xi[s] = si[i + (s << 8)]; }
    float pr_[4], pi_[4], qr[4], qi[4];
    #pragma unroll
    for (int s = 0; s < 4; s++) {
        pr_[s] = xr[s] + xr[s+4]; pi_[s] = xi[s] + xi[s+4];
        qr[s]  = xr[s] - xr[s+4]; qi[s]  = xi[s] - xi[s+4];
    }
    { float a=qr[1], b=qi[1]; qr[1] = Cq*(a+b); qi[1] = Cq*(b-a); }
    { float a=qr[2], b=qi[2]; qr[2] = b;        qi[2] = -a;       }
    { float a=qr[3], b=qi[3]; qr[3] = Cq*(b-a); qi[3] = -Cq*(a+b); }
    float Xr[8], Xi[8];
    {
        float r0r=pr_[0]+pr_[2], r0i=pi_[0]+pi_[2];
        float r1r=pr_[0]-pr_[2], r1i=pi_[0]-pi_[2];
        float r2r=pr_[1]+pr_[3], r2i=pi_[1]+pi_[3];
        float t3r=pr_[1]-pr_[3], t3i=pi_[1]-pi_[3];
        float r3r=t3i, r3i=-t3r;
        Xr[0]=r0r+r2r; Xi[0]=r0i+r2i;
        Xr[2]=r1r+r3r; Xi[2]=r1i+r3i;
        Xr[4]=r0r-r2r; Xi[4]=r0i-r2i;
        Xr[6]=r1r-r3r; Xi[6]=r1i-r3i;
    }
    {
        float r0r=qr[0]+qr[2], r0i=qi[0]+qi[2];
        float r1r=qr[0]-qr[2], r1i=qi[0]-qi[2];
        float r2r=qr[1]+qr[3], r2i=qi[1]+qi[3];
        float t3r=qr[1]-qr[3], t3i=qi[1]-qi[3];
        float r3r=t3i, r3i=-t3r;
        Xr[1]=r0r+r2r; Xi[1]=r0i+r2i;
        Xr[3]=r1r+r3r; Xi[3]=r1i+r3i;
        Xr[5]=r0r-r2r; Xi[5]=r0i-r2i;
        Xr[7]=r1r-r3r; Xi[7]=r1i-r3i;
    }
    float2 w = g_tw[m * p];
    float wjr = 1.f, wji = 0.f;
    int o = ((m * p) << 3) + r;
    dr[o] = Xr[0]; di[o] = Xi[0];
    #pragma unroll
    for (int j = 1; j < 8; j++) {
        float nr = wjr * w.x - wji * w.y;
        wji = wji * w.x + wjr * w.y;
        wjr = nr;
        dr[o + j * m] = Xr[j] * wjr - Xi[j] * wji;
        di[o + j * m] = Xi[j] * wjr + Xr[j] * wji;
    }
}

// ---- radix-8 butterfly on register inputs (m=1, butterfly index i=tid) ----
__device__ __forceinline__ void r8_reg_m1(const float* xr, const float* xi,
                                          float* __restrict__ dr,
                                          float* __restrict__ di) {
    const float Cq = 0.70710678118654752440f;
    int i = threadIdx.x;
    float pr_[4], pi_[4], qr[4], qi[4];
    #pragma unroll
    for (int s = 0; s < 4; s++) {
        pr_[s] = xr[s] + xr[s+4]; pi_[s] = xi[s] + xi[s+4];
        qr[s]  = xr[s] - xr[s+4]; qi[s]  = xi[s] - xi[s+4];
    }
    { float a=qr[1], b=qi[1]; qr[1] = Cq*(a+b); qi[1] = Cq*(b-a); }
    { float a=qr[2], b=qi[2]; qr[2] = b;        qi[2] = -a;       }
    { float a=qr[3], b=qi[3]; qr[3] = Cq*(b-a); qi[3] = -Cq*(a+b); }
    float Xr[8], Xi[8];
    {
        float r0r=pr_[0]+pr_[2], r0i=pi_[0]+pi_[2];
        float r1r=pr_[0]-pr_[2], r1i=pi_[0]-pi_[2];
        float r2r=pr_[1]+pr_[3], r2i=pi_[1]+pi_[3];
        float t3r=pr_[1]-pr_[3], t3i=pi_[1]-pi_[3];
        float r3r=t3i, r3i=-t3r;
        Xr[0]=r0r+r2r; Xi[0]=r0i+r2i;
        Xr[2]=r1r+r3r; Xi[2]=r1i+r3i;
        Xr[4]=r0r-r2r; Xi[4]=r0i-r2i;
        Xr[6]=r1r-r3r; Xi[6]=r1i-r3i;
    }
    {
        float r0r=qr[0]+qr[2], r0i=qi[0]+qi[2];
        float r1r=qr[0]-qr[2], r1i=qi[0]-qi[2];
        float r2r=qr[1]+qr[3], r2i=qi[1]+qi[3];
        float t3r=qr[1]-qr[3], t3i=qi[1]-qi[3];
        float r3r=t3i, r3i=-t3r;
        Xr[1]=r0r+r2r; Xi[1]=r0i+r2i;
        Xr[3]=r1r+r3r; Xi[3]=r1i+r3i;
        Xr[5]=r0r-r2r; Xi[5]=r0i-r2i;
        Xr[7]=r1r-r3r; Xi[7]=r1i-r3i;
    }
    float2 w = g_tw[i];
    float wjr = 1.f, wji = 0.f;
    int o = i << 3;
    dr[o] = Xr[0]; di[o] = Xi[0];
    #pragma unroll
    for (int j = 1; j < 8; j++) {
        float nr = wjr * w.x - wji * w.y;
        wji = wji * w.x + wjr * w.y;
        wjr = nr;
        dr[o + j] = Xr[j] * wjr - Xi[j] * wji;
        di[o + j] = Xi[j] * wjr + Xr[j] * wji;
    }
}

// ---------------- full radix-8 FFT (generic; used by kfft) ----------------
__device__ __forceinline__ void fft2048_r8(float*& sr, float*& si, float*& dr, float*& di) {
    #pragma unroll
    for (int lm = 0; lm < 9; lm += 3) {
        r8_stage(sr, si, dr, di, lm);
        __syncthreads();
        float* tp; tp=sr;sr=dr;dr=tp; tp=si;si=di;di=tp;
    }
    #pragma unroll
    for (int q = 0; q < 2; q++) {
        int r = threadIdx.x + (q << 8);
        float a0r=sr[r],      a0i=si[r];
        float a1r=sr[r+512],  a1i=si[r+512];
        float a2r=sr[r+1024], a2i=si[r+1024];
        float a3r=sr[r+1536], a3i=si[r+1536];
        float r0r=a0r+a2r, r0i=a0i+a2i;
        float r1r=a0r-a2r, r1i=a0i-a2i;
        float r2r=a1r+a3r, r2i=a1i+a3i;
        float t3r=a1r-a3r, t3i=a1i-a3i;
        float r3r=t3i, r3i=-t3r;
        dr[r]      = r0r+r2r; di[r]      = r0i+r2i;
        dr[r+512]  = r1r+r3r; di[r+512]  = r1i+r3i;
        dr[r+1024] = r0r-r2r; di[r+1024] = r0i-r2i;
        dr[r+1536] = r1r-r3r; di[r+1536] = r1i-r3i;
    }
    __syncthreads();
    float* tp; tp=sr;sr=dr;dr=tp; tp=si;si=di;di=tp;
}

// ---------------- FFT of kernel rows ----------------
__global__ void __launch_bounds__(256) k_kfft() {
    __shared__ float bAr[2048], bAi[2048], bBr[2048], bBi[2048];
    int tid = threadIdx.x;
    int h0 = blockIdx.x * 2, h1 = h0 + 1;
    #pragma unroll
    for (int qq = 0; qq < 8; qq++) {
        int idx = tid + (qq << 8);
        bAr[idx] = g_ktime[h0 * 2048 + idx];
        bAi[idx] = g_ktime[h1 * 2048 + idx];
    }
    __syncthreads();
    float *sr = bAr, *si = bAi, *dr = bBr, *di = bBi;
    fft2048_r8(sr, si, dr, di);
    #pragma unroll
    for (int qq = 0; qq < 8; qq++) {
        int f = tid + (qq << 8);
        int fr2 = (2048 - f) & 2047;
        float ur = sr[f],  ui = si[f];
        float vr = sr[fr2], vi = -si[fr2];
        g_khr[h0 * 2048 + f] = 0.5f * (ur + vr);
        g_khi[h0 * 2048 + f] = 0.5f * (ui + vi);
        g_khr[h1 * 2048 + f] = 0.5f * (ui - vi);
        g_khi[h1 * 2048 + f] = -0.5f * (ur - vr);
    }
}

// ---------------- main conv: fused pointwise+inv-stage1, fused epilogue, fp16 out ----------------
__global__ void __launch_bounds__(256) k_conv(const float* __restrict__ Dp) {
    __shared__ float bAr[2048], bAi[2048], bBr[2048], bBi[2048];
    const float Cq = 0.70710678118654752440f;
    int tid = threadIdx.x;
    int h  = blockIdx.x;
    int pb = blockIdx.y;
    const float* za = g_z + ((size_t)(2 * pb) * Hh + h) * Ll;
    const float* zb = za + (size_t)Hh * Ll;
    float ra[4], rb[4];
    #pragma unroll
    for (int qq = 0; qq < 4; qq++) {
        int idx = tid + (qq << 8);
        ra[qq] = za[idx]; rb[qq] = zb[idx];
        bAr[idx] = ra[qq]; bAi[idx] = rb[qq];
    }
    __syncthreads();

    // ---- forward stage 1 (m=1): inputs s>=4 are the zero pad ----
    {
        float xr[4], xi[4];
        #pragma unroll
        for (int s = 0; s < 4; s++) { xr[s] = bAr[tid + (s << 8)]; xi[s] = bAi[tid + (s << 8)]; }
        float qr[4], qi[4];
        #pragma unroll
        for (int s = 0; s < 4; s++) { qr[s] = xr[s]; qi[s] = xi[s]; }
        { float a=qr[1], b=qi[1]; qr[1] = Cq*(a+b); qi[1] = Cq*(b-a); }
        { float a=qr[2], b=qi[2]; qr[2] = b;        qi[2] = -a;       }
        { float a=qr[3], b=qi[3]; qr[3] = Cq*(b-a); qi[3] = -Cq*(a+b); }
        float Xr[8], Xi[8];
        {
            float r0r=xr[0]+xr[2], r0i=xi[0]+xi[2];
            float r1r=xr[0]-xr[2], r1i=xi[0]-xi[2];
            float r2r=xr[1]+xr[3], r2i=xi[1]+xi[3];
            float t3r=xr[1]-xr[3], t3i=xi[1]-xi[3];
            float r3r=t3i, r3i=-t3r;
            Xr[0]=r0r+r2r; Xi[0]=r0i+r2i;
            Xr[2]=r1r+r3r; Xi[2]=r1i+r3i;
            Xr[4]=r0r-r2r; Xi[4]=r0i-r2i;
            Xr[6]=r1r-r3r; Xi[6]=r1i-r3i;
        }
        {
            float r0r=qr[0]+qr[2], r0i=qi[0]+qi[2];
            float r1r=qr[0]-qr[2], r1i=qi[0]-qi[2];
            float r2r=qr[1]+qr[3], r2i=qi[1]+qi[3];
            float t3r=qr[1]-qr[3], t3i=qi[1]-qi[3];
            float r3r=t3i, r3i=-t3r;
            Xr[1]=r0r+r2r; Xi[1]=r0i+r2i;
            Xr[3]=r1r+r3r; Xi[3]=r1i+r3i;
            Xr[5]=r0r-r2r; Xi[5]=r0i-r2i;
            Xr[7]=r1r-r3r; Xi[7]=r1i-r3i;
        }
        float2 w = g_tw[tid];
        float wjr = 1.f, wji = 0.f;
        int o = tid << 3;
        bBr[o] = Xr[0]; bBi[o] = Xi[0];
        #pragma unroll
        for (int j = 1; j < 8; j++) {
            float nr = wjr * w.x - wji * w.y;
            wji = wji * w.x + wjr * w.y;
            wjr = nr;
            bBr[o + j] = Xr[j] * wjr - Xi[j] * wji;
            bBi[o + j] = Xi[j] * wjr + Xr[j] * wji;
        }
    }
    __syncthreads();
    r8_stage(bBr, bBi, bAr, bAi, 3); __syncthreads();
    r8_stage(bAr, bAi, bBr, bBi, 6); __syncthreads();

    // ---- fused: forward final r4 + spectrum multiply + inverse stage-1 -> bA ----
    {
        const float* khr = g_khr + h * 2048;
        const float* khi = g_khi + h * 2048;
        const float inv = 1.0f / 2048.0f;
        float xr[8], xi[8];   // positions tid + s*256
        #pragma unroll
        for (int q = 0; q < 2; q++) {
            int r = tid + (q << 8);
            float a0r=bBr[r],      a0i=bBi[r];
            float a1r=bBr[r+512],  a1i=bBi[r+512];
            float a2r=bBr[r+1024], a2i=bBi[r+1024];
            float a3r=bBr[r+1536], a3i=bBi[r+1536];
            float r0r=a0r+a2r, r0i=a0i+a2i;
            float r1r=a0r-a2r, r1i=a0i-a2i;
            float r2r=a1r+a3r, r2i=a1i+a3i;
            float t3r=a1r-a3r, t3i=a1i-a3i;
            float r3r=t3i, r3i=-t3r;
            float Xr4[4], Xi4[4];
            Xr4[0]=r0r+r2r; Xi4[0]=r0i+r2i;
            Xr4[1]=r1r+r3r; Xi4[1]=r1i+r3i;
            Xr4[2]=r0r-r2r; Xi4[2]=r0i-r2i;
            Xr4[3]=r1r-r3r; Xi4[3]=r1i-r3i;
            #pragma unroll
            for (int j = 0; j < 4; j++) {
                int f = r + j * 512;
                int s = 2 * j + q;
                float kr = khr[f], ki = khi[f];
                float ar = Xr4[j], ai = Xi4[j];
                xr[s] = (ar * kr - ai * ki) * inv;
                xi[s] = -(ar * ki + ai * kr) * inv;
            }
        }
        __syncthreads();
        r8_reg_m1(xr, xi, bAr, bAi);
    }
    __syncthreads();

    // ---- inverse FFT remaining stages ----
    r8_stage(bAr, bAi, bBr, bBi, 3); __syncthreads();
    r8_stage(bBr, bBi, bAr, bAi, 6); __syncthreads();

    // ---- inverse final r4 (outputs [0,1024) only) fused with epilogue, fp16 store ----
    float Dh = Dp[h];
    __half* ya = g_yg + ((size_t)(2 * pb) * Hh + h) * Ll;
    __half* yb = ya + (size_t)Hh * Ll;
    #pragma unroll
    for (int q = 0; q < 2; q++) {
        int r = tid + (q << 8);
        float a0r=bAr[r],      a0i=bAi[r];
        float a1r=bAr[r+512],  a1i=bAi[r+512];
        float a2r=bAr[r+1024], a2i=bAi[r+1024];
        float a3r=bAr[r+1536], a3i=bAi[r+1536];
        float r0r=a0r+a2r, r0i=a0i+a2i;
        float r1r=a0r-a2r, r1i=a0i-a2i;
        float r2r=a1r+a3r, r2i=a1i+a3i;
        float t3r=a1r-a3r, t3i=a1i-a3i;
        float r3r=t3i, r3i=-t3r;
        float o1r = r0r + r2r, o1i = r0i + r2i;
        float o2r = r1r + r3r, o2i = r1i + r3i;
        float v1 = o1r  + Dh * ra[q];
        float v2 = -o1i + Dh * rb[q];
        float v3 = o2r  + Dh * ra[q + 2];
        float v4 = -o2i + Dh * rb[q + 2];
        ya[r]       = __float2half_rn(geluf(v1));
        yb[r]       = __float2half_rn(geluf(v2));
        ya[r + 512] = __float2half_rn(geluf(v3));
        yb[r + 512] = __float2half_rn(geluf(v4));
    }
}

// ---- ldmatrix wrappers ----
__device__ __forceinline__ void ldsm_x4(unsigned &r0, unsigned &r1, unsigned &r2, unsigned &r3,
                                        const void* p) {
    unsigned addr = (unsigned)__cvta_generic_to_shared(p);
    asm volatile("ldmatrix.sync.aligned.m8n8.x4.shared.b16 {%0,%1,%2,%3}, [%4];"
                 : "=r"(r0), "=r"(r1), "=r"(r2), "=r"(r3) : "r"(addr));
}
__device__ __forceinline__ void ldsm_x2t(unsigned &r0, unsigned &r1, const void* p) {
    unsigned addr = (unsigned)__cvta_generic_to_shared(p);
    asm volatile("ldmatrix.sync.aligned.m8n8.x2.trans.shared.b16 {%0,%1}, [%2];"
                 : "=r"(r0), "=r"(r1) : "r"(addr));
}

// ---------------- GEMM1: g = gate(out_w@yg + out_b + x1), fp16 out, ping-pong + LDSM ----------------
__global__ void __launch_bounds__(256) k_gemm1(const float* __restrict__ bias,
                                               const __half* __restrict__ X,
                                               const float* __restrict__ resid,
                                               __half* __restrict__ Yout) {
    __shared__ __half Ws[2][128][24];
    __shared__ __half Xs[2][16][136];
    int l0 = blockIdx.x * 128;
    int o0 = blockIdx.y * 128;
    int b  = blockIdx.z;
    int tid = threadIdx.x;
    int lane = tid & 31, warp = tid >> 5;
    int wm = warp & 1, wn = warp >> 1;

    float acc[4][4][4];
    #pragma unroll
    for (int m = 0; m < 4; m++)
        #pragma unroll
        for (int n = 0; n < 4; n++)
            #pragma unroll
            for (int c = 0; c < 4; c++) acc[m][n][c] = 0.f;

    int wo = tid >> 1, wk = (tid & 1) * 8;
    const __half* whp = &g_wh[(size_t)(o0 + wo) * 256 + wk];
    int xk = tid >> 4, xl = (tid & 15) * 8;
    const __half* xpb = &X[((size_t)b * Hh + xk) * Ll + l0 + xl];

    // ldmatrix lane addressing (constant across iterations except buffer)
    int arow = wm * 64 + (lane & 15);        // + m*16 added per m
    int acol = (lane & 16) ? 8 : 0;
    int brow = lane & 15;

    uint4 wv = *(const uint4*)(whp);
    uint4 xv = *(const uint4*)(xpb);
    *(uint4*)&Ws[0][wo][wk] = wv;
    *(uint4*)&Xs[0][xk][xl] = xv;
    __syncthreads();

    #pragma unroll 1
    for (int it = 0; it < 16; it++) {
        int cur = it & 1;
        if (it < 15) {
            int kk = (it + 1) * 16;
            wv = *(const uint4*)(whp + kk);
            xv = *(const uint4*)(xpb + (size_t)kk * Ll);
        }
        unsigned bf[4][2];
        #pragma unroll
        for (int nt = 0; nt < 4; nt++) {
            int n0 = wn * 32 + nt * 8;
            ldsm_x2t(bf[nt][0], bf[nt][1], &Xs[cur][brow][n0]);
        }
        #pragma unroll
        for (int m = 0; m < 4; m++) {
            unsigned a0, a1, a2, a3;
            ldsm_x4(a0, a1, a2, a3, &Ws[cur][arow + m * 16][acol]);
            #pragma unroll
            for (int nt = 0; nt < 4; nt++)
                asm volatile(
                    "mma.sync.aligned.m16n8k16.row.col.f32.f16.f16.f32 "
                    "{%0,%1,%2,%3}, {%4,%5,%6,%7}, {%8,%9}, {%0,%1,%2,%3};"
                    : "+f"(acc[m][nt][0]), "+f"(acc[m][nt][1]),
                      "+f"(acc[m][nt][2]), "+f"(acc[m][nt][3])
                    : "r"(a0), "r"(a1), "r"(a2), "r"(a3),
                      "r"(bf[nt][0]), "r"(bf[nt][1]));
        }
        if (it < 15) {
            *(uint4*)&Ws[1 - cur][wo][wk] = wv;
            *(uint4*)&Xs[1 - cur][xk][xl] = xv;
        }
        __syncthreads();
    }

    #pragma unroll
    for (int m = 0; m < 4; m++) {
        int o = o0 + wm * 64 + m * 16 + (lane >> 2);
        float bo0 = bias[o], bo8 = bias[o + 8];
        #pragma unroll
        for (int nt = 0; nt < 4; nt++) {
            int lc = l0 + wn * 32 + nt * 8 + (lane & 3) * 2;
            size_t base0 = ((size_t)b * Hh + o) * Ll + lc;
            size_t base8 = base0 + 8 * (size_t)Ll;
            float2 r0 = *(const float2*)&resid[base0];
            float2 r8 = *(const float2*)&resid[base8];
            __half q0 = __float2half_rn(gatef(acc[m][nt][0] + bo0 + r0.x));
            __half q1 = __float2half_rn(gatef(acc[m][nt][1] + bo0 + r0.y));
            __half q2 = __float2half_rn(gatef(acc[m][nt][2] + bo8 + r8.x));
            __half q3 = __float2half_rn(gatef(acc[m][nt][3] + bo8 + r8.y));
            *(unsigned*)&Yout[base0] = pckh(q0, q1);
            *(unsigned*)&Yout[base8] = pckh(q2, q3);
        }
    }
}

// ---------------- GEMM2/3: out = lin@g + b (+x1 if addres), ping-pong + LDSM ----------------
__global__ void __launch_bounds__(256) k_gemm2(int widx,
                                               const float* __restrict__ bias,
                                               const __half* __restrict__ X,
                                               const float* __restrict__ resid,
                                               float* __restrict__ out,
                                               int addres) {
    __shared__ __half Ws[2][128][24];
    __shared__ __half Xs[2][16][136];
    int l0 = blockIdx.x * 128;
    int o0 = blockIdx.y * 128;
    int b  = blockIdx.z;
    int tid = threadIdx.x;
    int lane = tid & 31, warp = tid >> 5;
    int wm = warp & 1, wn = warp >> 1;

    float acc[4][4][4];
    #pragma unroll
    for (int m = 0; m < 4; m++)
        #pragma unroll
        for (int n = 0; n < 4; n++)
            #pragma unroll
            for (int c = 0; c < 4; c++) acc[m][n][c] = 0.f;

    int wo = tid >> 1, wk = (tid & 1) * 8;
    const __half* whp = &g_wh[(size_t)widx * Hh * Hh + (size_t)(o0 + wo) * 256 + wk];
    int xk = tid >> 4, xl = (tid & 15) * 8;
    const __half* xpb = &X[((size_t)b * Hh + xk) * Ll + l0 + xl];

    int arow = wm * 64 + (lane & 15);
    int acol = (lane & 16) ? 8 : 0;
    int brow = lane & 15;

    uint4 wv = *(const uint4*)(whp);
    uint4 xv = *(const uint4*)(xpb);
    *(uint4*)&Ws[0][wo][wk] = wv;
    *(uint4*)&Xs[0][xk][xl] = xv;
    __syncthreads();

    #pragma unroll 1
    for (int it = 0; it < 16; it++) {
        int cur = it & 1;
        if (it < 15) {
            int kk = (it + 1) * 16;
            wv = *(const uint4*)(whp + kk);
            xv = *(const uint4*)(xpb + (size_t)kk * Ll);
        }
        unsigned bf[4][2];
        #pragma unroll
        for (int nt = 0; nt < 4; nt++) {
            int n0 = wn * 32 + nt * 8;
            ldsm_x2t(bf[nt][0], bf[nt][1], &Xs[cur][brow][n0]);
        }
        #pragma unroll
        for (int m = 0; m < 4; m++) {
            unsigned a0, a1, a2, a3;
            ldsm_x4(a0, a1, a2, a3, &Ws[cur][arow + m * 16][acol]);
            #pragma unroll
            for (int nt = 0; nt < 4; nt++)
                asm volatile(
                    "mma.sync.aligned.m16n8k16.row.col.f32.f16.f16.f32 "
                    "{%0,%1,%2,%3}, {%4,%5,%6,%7}, {%8,%9}, {%0,%1,%2,%3};"
                    : "+f"(acc[m][nt][0]), "+f"(acc[m][nt][1]),
                      "+f"(acc[m][nt][2]), "+f"(acc[m][nt][3])
                    : "r"(a0), "r"(a1), "r"(a2), "r"(a3),
                      "r"(bf[nt][0]), "r"(bf[nt][1]));
        }
        if (it < 15) {
            *(uint4*)&Ws[1 - cur][wo][wk] = wv;
            *(uint4*)&Xs[1 - cur][xk][xl] = xv;
        }
        __syncthreads();
    }

    #pragma unroll
    for (int m = 0; m < 4; m++) {
        int o = o0 + wm * 64 + m * 16 + (lane >> 2);
        float bo0 = bias[o], bo8 = bias[o + 8];
        #pragma unroll
        for (int nt = 0; nt < 4; nt++) {
            int lc = l0 + wn * 32 + nt * 8 + (lane & 3) * 2;
            size_t base0 = ((size_t)b * Hh + o) * Ll + lc;
            size_t base8 = base0 + 8 * (size_t)Ll;
            float v0 = acc[m][nt][0] + bo0;
            float v1 = acc[m][nt][1] + bo0;
            float v2 = acc[m][nt][2] + bo8;
            float v3 = acc[m][nt][3] + bo8;
            if (addres) {
                float2 r0 = *(const float2*)&resid[base0];
                float2 r8 = *(const float2*)&resid[base8];
                v0 += r0.x; v1 += r0.y; v2 += r8.x; v3 += r8.y;
            }
            *(float2*)&out[base0] = make_float2(v0, v1);
            *(float2*)&out[base8] = make_float2(v2, v3);
        }
    }
}

// ---------------- launch ----------------
extern "C" void kernel_launch(void* const* d_in, const int* in_sizes, int n_in,
                              void* d_out, int out_size) {
    const float* x      = (const float*)d_in[0];
    const int*   t      = (const int*)  d_in[1];
    const float* ada_w  = (const float*)d_in[2];
    const float* ada_b  = (const float*)d_in[3];
    const float* norm_w = (const float*)d_in[4];
    const float* norm_b = (const float*)d_in[5];
    const float* log_dt = (const float*)d_in[6];
    const float* A_re   = (const float*)d_in[7];
    const float* A_im   = (const float*)d_in[8];
    const float* C_re   = (const float*)d_in[9];
    const float* C_im   = (const float*)d_in[10];
    const float* Dp     = (const float*)d_in[11];
    const float* out_w  = (const float*)d_in[12];
    const float* out_b  = (const float*)d_in[13];
    const float* lin1_w = (const float*)d_in[14];
    const float* lin1_b = (const float*)d_in[15];
    const float* lin2_w = (const float*)d_in[16];
    const float* lin2_b = (const float*)d_in[17];
    float* out = (float*)d_out;
    (void)in_sizes; (void)n_in; (void)out_size;

    float *p_x1, *p_z;
    __half *p_yg;
    cudaGetSymbolAddress((void**)&p_x1, g_x1);
    cudaGetSymbolAddress((void**)&p_z,  g_z);
    cudaGetSymbolAddress((void**)&p_yg, g_yg);

    k_prep<<<836, 256>>>(t, out_w, lin1_w, lin2_w);
    k_ssm<<<256, 256>>>(log_dt, A_re, A_im, C_re, C_im);
    k_kfft<<<128, 256>>>();
    k_ada_gemm<<<dim3(64, 8), 256>>>(ada_w);
    k_ada_reduce<<<512, 256>>>(ada_b);
    k_adaln<<<Bb * Hh, 256>>>(x);
    k_chanln<<<dim3(64, 32), 256>>>(norm_w, norm_b);
    k_conv<<<dim3(256, 32), 256>>>(Dp);
    k_gemm1<<<dim3(8, 2, 64), 256>>>(out_b, p_yg, p_x1, (__half*)p_z);
    k_gemm2<<<dim3(8, 2, 64), 256>>>(1, lin1_b, (const __half*)p_z, p_x1, out, 1);
    k_gemm2<<<dim3(8, 2, 64), 256>>>(2, lin2_b, (const __half*)p_z, p_x1, out + BHL, 0);
}